// round 11
// baseline (speedup 1.0000x reference)
#include <cuda_runtime.h>
#include <cuda_fp16.h>
#include <cstdint>

static constexpr int NB  = 64;     // batch
static constexpr int PP  = 196;    // spatial positions
static constexpr int EE  = 2048;   // feature dim
static constexpr int DD  = 256;    // hidden
static constexpr int HH  = 256;    // attention hidden
static constexpr int EMB = 256;    // embedding
static constexpr int VV  = 10000;  // vocab
static constexpr int LL  = 32;     // caption length
static constexpr int TT  = 31;     // timesteps
static constexpr int XK  = EMB + EE + DD;  // 2560
static constexpr int G4  = 4 * DD;         // 1024
static constexpr int KC  = 10;             // split-K chunks for gates gemm
static constexpr int NBLK = 256;           // persistent grid size

__device__ int    g_order[NB];
__device__ int    g_target[NB];
__device__ int    g_nact[TT + 1];           // active rows (target > t) per step
__device__ __half g_feat16[NB * PP * EE];   // 51.4 MB fp16 feat, order-permuted
__device__ __half g_fe16[NB * PP * HH];     // 6.4 MB fp16 attention features
__device__ float  g_mean[NB * EE];          // prologue: mean; loop: he (NB*256)
__device__ float  g_h[NB * DD];
__device__ float  g_c[NB * DD];
__device__ float  g_score[NB * PP];
__device__ float  g_x[NB * XK];
__device__ float  g_gp[KC * NB * G4];       // split-K partials (gates / init)
__device__ float  g_gatep[2 * NB * EE];     // split-K partials for gate pre-act
__device__ __half g_Wg16[DD * EE];          // W_gate fp16
__device__ __half g_Wih16[XK * G4];         // [W_ih ; W_hh] fp16 concat
__device__ __half g_Whead16[DD * VV];       // W_head fp16
__device__ __half g_Wf16[EE * HH];          // Wf fp16 (same [K,N] layout)

// two-level grid barrier state (16 groups x 16 blocks); counters padded
__device__ int          g_cnt_grp[16 * 32];
__device__ int          g_cnt_root;
__device__ volatile int g_gen_grp[16 * 32];
__device__ volatile int g_gen_root;

__device__ __forceinline__ float sigf(float x) { return 1.0f / (1.0f + expf(-x)); }

// ---------------------------------------------------------------------------
// K0: stable descending counting sort + per-step active counts
// ---------------------------------------------------------------------------
__global__ void k_order(const int* __restrict__ caplen) {
    if (threadIdx.x == 0) {
        int idx = 0;
        for (int v = LL; v >= 1; --v) {
            for (int i = 0; i < NB; ++i) {
                if (caplen[i] == v) {
                    g_order[idx]  = i;
                    g_target[idx] = v - 1;
                    ++idx;
                }
            }
        }
        for (int t = 0; t <= TT; ++t) {
            int n = 0;
            for (int i = 0; i < NB; ++i) n += (g_target[i] > t) ? 1 : 0;
            g_nact[t] = n;
        }
    }
}

// ---------------------------------------------------------------------------
// K_cvt: one-time fp32 -> fp16 conversion of weights (incl. Wf)
// ---------------------------------------------------------------------------
__global__ void k_cvt(const float* __restrict__ Wg, const float* __restrict__ Wih,
                      const float* __restrict__ Whh, const float* __restrict__ Whead,
                      const float* __restrict__ Wf) {
    const int NQ_G  = (DD * EE) / 4;
    const int NQ_IH = (2304 * G4) / 4;
    const int NQ_HH = (DD * G4) / 4;
    const int NQ_HD = (DD * VV) / 4;
    const int NQ_WF = (EE * HH) / 4;
    const int total = NQ_G + NQ_IH + NQ_HH + NQ_HD + NQ_WF;
    for (int i = blockIdx.x * blockDim.x + threadIdx.x; i < total;
         i += gridDim.x * blockDim.x) {
        const float* src; __half* dst; int q;
        if (i < NQ_G)                          { src = Wg;    dst = g_Wg16;              q = i; }
        else if (i < NQ_G + NQ_IH)             { src = Wih;   dst = g_Wih16;             q = i - NQ_G; }
        else if (i < NQ_G + NQ_IH + NQ_HH)     { src = Whh;  dst = g_Wih16 + 2304 * G4;  q = i - NQ_G - NQ_IH; }
        else if (i < NQ_G + NQ_IH + NQ_HH + NQ_HD) { src = Whead; dst = g_Whead16;       q = i - NQ_G - NQ_IH - NQ_HH; }
        else                                   { src = Wf;    dst = g_Wf16;              q = i - NQ_G - NQ_IH - NQ_HH - NQ_HD; }
        float4 v = *(const float4*)(src + (size_t)q * 4);
        *(__half2*)(dst + (size_t)q * 4)     = __floats2half2_rn(v.x, v.y);
        *(__half2*)(dst + (size_t)q * 4 + 2) = __floats2half2_rn(v.z, v.w);
    }
}

// ---------------------------------------------------------------------------
// K_cvtf: one-time feat -> fp16 with the order permutation baked in.
// ---------------------------------------------------------------------------
__global__ void __launch_bounds__(256) k_cvtf(const float* __restrict__ feat) {
    int row = blockIdx.x;
    int b = row / PP, p = row % PP;
    const float* src = feat + ((size_t)g_order[b] * PP + p) * EE + threadIdx.x * 8;
    __half* dst = g_feat16 + (size_t)row * EE + threadIdx.x * 8;
    float4 v0 = *(const float4*)(src);
    float4 v1 = *(const float4*)(src + 4);
    *(__half2*)(dst + 0) = __floats2half2_rn(v0.x, v0.y);
    *(__half2*)(dst + 2) = __floats2half2_rn(v0.z, v0.w);
    *(__half2*)(dst + 4) = __floats2half2_rn(v1.x, v1.y);
    *(__half2*)(dst + 6) = __floats2half2_rn(v1.z, v1.w);
}

// ---------------------------------------------------------------------------
// K3: grid (98, 5).  y<4: fe = feat16 @ Wf16 + bf via mma.sync (tensor cores).
//     y==4: mean over positions from fp32 feat (blocks 0..63).
// ---------------------------------------------------------------------------
__global__ void __launch_bounds__(256) k_fe(const float* __restrict__ feat,
                                            const float* __restrict__ bf) {
    int tid = threadIdx.x;
    int mb = blockIdx.x, nb = blockIdx.y;

    if (nb == 4) {
        if (mb >= NB) return;
        int b = mb;
        const float4* base = (const float4*)(feat + (size_t)g_order[b] * PP * EE);
        float4 sA = make_float4(0.f, 0.f, 0.f, 0.f);
        float4 sB = make_float4(0.f, 0.f, 0.f, 0.f);
        #pragma unroll 2
        for (int p = 0; p < PP; ++p) {
            float4 v0 = __ldcs(base + (size_t)p * (EE / 4) + tid);
            float4 v1 = __ldcs(base + (size_t)p * (EE / 4) + tid + 256);
            sA.x += v0.x; sA.y += v0.y; sA.z += v0.z; sA.w += v0.w;
            sB.x += v1.x; sB.y += v1.y; sB.z += v1.z; sB.w += v1.w;
        }
        const float inv = 1.0f / PP;
        sA.x *= inv; sA.y *= inv; sA.z *= inv; sA.w *= inv;
        sB.x *= inv; sB.y *= inv; sB.z *= inv; sB.w *= inv;
        *(float4*)(g_mean + b * EE + tid * 4)        = sA;
        *(float4*)(g_mean + b * EE + 1024 + tid * 4) = sB;
        return;
    }

    __shared__ __half As[128][72];
    __shared__ __half Bs[64][72];

    int warp = tid >> 5, lane = tid & 31;
    int wm = warp & 3, wn = warp >> 2;

    float acc[2][4][4] = {};

    for (int k0 = 0; k0 < EE; k0 += 64) {
        #pragma unroll
        for (int i = 0; i < 4; ++i) {
            int idx = tid + i * 256;
            int r = idx >> 3, c = (idx & 7) * 8;
            *(uint4*)&As[r][c] =
                *(const uint4*)(g_feat16 + (size_t)(mb * 128 + r) * EE + k0 + c);
        }
        #pragma unroll
        for (int i = 0; i < 2; ++i) {
            int idx = tid + i * 256;
            int r = idx >> 3, c = (idx & 7) * 8;
            *(uint4*)&Bs[r][c] =
                *(const uint4*)(g_Wf16 + (size_t)(k0 + r) * HH + nb * 64 + c);
        }
        __syncthreads();

        #pragma unroll
        for (int kk = 0; kk < 64; kk += 16) {
            unsigned a[2][4], b[4][2];
            #pragma unroll
            for (int mi = 0; mi < 2; ++mi) {
                unsigned addr = (unsigned)__cvta_generic_to_shared(
                    &As[wm * 32 + mi * 16 + (lane & 15)][kk + (lane >> 4) * 8]);
                asm volatile("ldmatrix.sync.aligned.m8n8.x4.shared.b16 {%0,%1,%2,%3}, [%4];"
                    : "=r"(a[mi][0]), "=r"(a[mi][1]), "=r"(a[mi][2]), "=r"(a[mi][3])
                    : "r"(addr));
            }
            #pragma unroll
            for (int ni = 0; ni < 4; ++ni) {
                unsigned addr = (unsigned)__cvta_generic_to_shared(
                    &Bs[kk + (lane & 15)][wn * 32 + ni * 8]);
                asm volatile("ldmatrix.sync.aligned.m8n8.x2.trans.shared.b16 {%0,%1}, [%2];"
                    : "=r"(b[ni][0]), "=r"(b[ni][1]) : "r"(addr));
            }
            #pragma unroll
            for (int mi = 0; mi < 2; ++mi)
                #pragma unroll
                for (int ni = 0; ni < 4; ++ni)
                    asm volatile(
                        "mma.sync.aligned.m16n8k16.row.col.f32.f16.f16.f32 "
                        "{%0,%1,%2,%3}, {%4,%5,%6,%7}, {%8,%9}, {%0,%1,%2,%3};"
                        : "+f"(acc[mi][ni][0]), "+f"(acc[mi][ni][1]),
                          "+f"(acc[mi][ni][2]), "+f"(acc[mi][ni][3])
                        : "r"(a[mi][0]), "r"(a[mi][1]), "r"(a[mi][2]), "r"(a[mi][3]),
                          "r"(b[ni][0]), "r"(b[ni][1]));
        }
        __syncthreads();
    }

    int gr = lane >> 2;
    int gc = (lane & 3) * 2;
    #pragma unroll
    for (int mi = 0; mi < 2; ++mi)
        #pragma unroll
        for (int ni = 0; ni < 4; ++ni) {
            int gn = nb * 64 + wn * 32 + ni * 8 + gc;
            float b0 = bf[gn], b1 = bf[gn + 1];
            int m0 = mb * 128 + wm * 32 + mi * 16 + gr;
            *(__half2*)(g_fe16 + (size_t)m0 * HH + gn) =
                __floats2half2_rn(acc[mi][ni][0] + b0, acc[mi][ni][1] + b1);
            int m1 = m0 + 8;
            *(__half2*)(g_fe16 + (size_t)m1 * HH + gn) =
                __floats2half2_rn(acc[mi][ni][2] + b0, acc[mi][ni][3] + b1);
        }
}

// ---------------------------------------------------------------------------
// K2a: init GEMM  mean(64x2048) @ [W_hid | W_cell](2048x512), split-K=8.
// ---------------------------------------------------------------------------
__global__ void __launch_bounds__(256) k_initA(const float* __restrict__ W_hid,
                                               const float* __restrict__ W_cell) {
    __shared__ float As[16][68];
    __shared__ float Bs[16][64];
    int tid = threadIdx.x;
    int nb = blockIdx.x, kc = blockIdx.y;
    const float* wsrc = (nb < 4) ? W_hid : W_cell;
    int ncol0 = (nb & 3) * 64;
    int k0g = kc * 256;
    float acc[4][4] = {};
    int rb = (tid >> 4) * 4, cb = (tid & 15) * 4;

    for (int kt = 0; kt < 256; kt += 16) {
        {
            int r = tid >> 2, kk = (tid & 3) * 4;
            float4 av = *(const float4*)(g_mean + r * EE + k0g + kt + kk);
            As[kk + 0][r] = av.x; As[kk + 1][r] = av.y;
            As[kk + 2][r] = av.z; As[kk + 3][r] = av.w;
        }
        {
            int kk = tid >> 4, n = (tid & 15) * 4;
            *(float4*)&Bs[kk][n] =
                *(const float4*)(wsrc + (size_t)(k0g + kt + kk) * DD + ncol0 + n);
        }
        __syncthreads();
        #pragma unroll
        for (int kk = 0; kk < 16; ++kk) {
            float a[4], bv[4];
            *(float4*)a  = *(float4*)&As[kk][rb];
            *(float4*)bv = *(float4*)&Bs[kk][cb];
            #pragma unroll
            for (int i = 0; i < 4; ++i)
                #pragma unroll
                for (int j = 0; j < 4; ++j) acc[i][j] += a[i] * bv[j];
        }
        __syncthreads();
    }
    #pragma unroll
    for (int i = 0; i < 4; ++i)
        #pragma unroll
        for (int j = 0; j < 4; ++j)
            g_gp[((size_t)kc * NB + rb + i) * 512 + nb * 64 + cb + j] = acc[i][j];
}

__global__ void k_init2(const float* __restrict__ b_hid, const float* __restrict__ b_cell) {
    int b = blockIdx.x, j = threadIdx.x;
    float h = b_hid[j], c = b_cell[j];
    #pragma unroll
    for (int kc = 0; kc < 8; ++kc) {
        const float* p = g_gp + ((size_t)kc * NB + b) * 512;
        h += p[j];
        c += p[256 + j];
    }
    g_h[b * DD + j] = h;
    g_c[b * DD + j] = c;
}

// ===========================================================================
// Persistent step-loop kernel
// ===========================================================================
struct SMu {
    union {
        struct { float As[16][68]; float Bs[16][64]; } g;
        struct { float she[256]; float swe[256]; } a;
        struct { float sw[256]; float red[8]; } c;
    } u;
};

// two-level grid barrier: 16 groups of 16 blocks
__device__ __forceinline__ void gridbar() {
    __syncthreads();
    __threadfence();
    if (threadIdx.x == 0) {
        int g = blockIdx.x & 15;
        int* cnt = &g_cnt_grp[g * 32];
        volatile int* gen = &g_gen_grp[g * 32];
        int my = *gen;
        if (atomicAdd(cnt, 1) == 15) {
            *cnt = 0;
            int rmy = g_gen_root;
            if (atomicAdd(&g_cnt_root, 1) == 15) {
                g_cnt_root = 0;
                __threadfence();
                g_gen_root = rmy + 1;
            } else {
                while (g_gen_root == rmy) __nanosleep(32);
            }
            __threadfence();
            *gen = my + 1;
        } else {
            while (*gen == my) __nanosleep(32);
        }
    }
    __syncthreads();
    __threadfence();
}

// P1 unit: he = h @ Wh + bh  (64 x 256 x 256), 4 column tiles of 64.
// Result into g_mean[b*256 + j] (g_mean is free after the prologue).
__device__ __forceinline__ void dev_he(int nb, SMu& sm,
        const float* __restrict__ Wh, const float* __restrict__ bh) {
    int tid = threadIdx.x;
    float acc[4][4] = {};
    int rb = (tid >> 4) * 4, cb = (tid & 15) * 4;

    for (int kt = 0; kt < 256; kt += 16) {
        {
            int r = tid >> 2, kk = (tid & 3) * 4;
            float4 av = *(const float4*)(g_h + r * DD + kt + kk);
            sm.u.g.As[kk + 0][r] = av.x; sm.u.g.As[kk + 1][r] = av.y;
            sm.u.g.As[kk + 2][r] = av.z; sm.u.g.As[kk + 3][r] = av.w;
        }
        {
            int kk = tid >> 4, n = (tid & 15) * 4;
            *(float4*)&sm.u.g.Bs[kk][n] =
                *(const float4*)(Wh + (size_t)(kt + kk) * HH + nb * 64 + n);
        }
        __syncthreads();
        #pragma unroll
        for (int kk = 0; kk < 16; ++kk) {
            float a[4], bv[4];
            *(float4*)a  = *(float4*)&sm.u.g.As[kk][rb];
            *(float4*)bv = *(float4*)&sm.u.g.Bs[kk][cb];
            #pragma unroll
            for (int i = 0; i < 4; ++i)
                #pragma unroll
                for (int j = 0; j < 4; ++j) acc[i][j] += a[i] * bv[j];
        }
        __syncthreads();
    }
    #pragma unroll
    for (int i = 0; i < 4; ++i)
        #pragma unroll
        for (int j = 0; j < 4; ++j) {
            int gj = nb * 64 + cb + j;
            g_mean[(size_t)(rb + i) * 256 + gj] = acc[i][j] + bh[gj];
        }
}

__device__ __forceinline__ void dev_gpre(int bid, SMu& sm) {
    int tid = threadIdx.x;
    int nb = bid & 31, kc = bid >> 5;
    int kbase = kc * 128;
    float acc[4][4] = {};
    int rb = (tid >> 4) * 4, cb = (tid & 15) * 4;

    for (int kt = 0; kt < 128; kt += 16) {
        {
            int r = tid >> 2, kk = (tid & 3) * 4;
            float4 av = *(const float4*)(g_h + r * DD + kbase + kt + kk);
            sm.u.g.As[kk + 0][r] = av.x; sm.u.g.As[kk + 1][r] = av.y;
            sm.u.g.As[kk + 2][r] = av.z; sm.u.g.As[kk + 3][r] = av.w;
        }
        {
            int kk = tid >> 4, n = (tid & 15) * 4;
            const __half* src = g_Wg16 + (size_t)(kbase + kt + kk) * EE + nb * 64 + n;
            float2 f0 = __half22float2(*(const __half2*)(src));
            float2 f1 = __half22float2(*(const __half2*)(src + 2));
            sm.u.g.Bs[kk][n + 0] = f0.x; sm.u.g.Bs[kk][n + 1] = f0.y;
            sm.u.g.Bs[kk][n + 2] = f1.x; sm.u.g.Bs[kk][n + 3] = f1.y;
        }
        __syncthreads();
        #pragma unroll
        for (int kk = 0; kk < 16; ++kk) {
            float a[4], bv[4];
            *(float4*)a  = *(float4*)&sm.u.g.As[kk][rb];
            *(float4*)bv = *(float4*)&sm.u.g.Bs[kk][cb];
            #pragma unroll
            for (int i = 0; i < 4; ++i)
                #pragma unroll
                for (int j = 0; j < 4; ++j) acc[i][j] += a[i] * bv[j];
        }
        __syncthreads();
    }
    #pragma unroll
    for (int i = 0; i < 4; ++i)
        #pragma unroll
        for (int j = 0; j < 4; ++j)
            g_gatep[((size_t)kc * NB + rb + i) * EE + nb * 64 + cb + j] = acc[i][j];
}

__device__ __forceinline__ void dev_head(int nb, int tprev, SMu& sm,
        const float* __restrict__ b_head, float* __restrict__ out) {
    int tid = threadIdx.x;
    int n0 = nb * 64;
    float acc[4][4] = {};
    int rb = (tid >> 4) * 4, cb = (tid & 15) * 4;

    for (int k0 = 0; k0 < DD; k0 += 16) {
        {
            int r = tid >> 2, kk = (tid & 3) * 4;
            float4 av = *(const float4*)(g_h + r * DD + k0 + kk);
            sm.u.g.As[kk + 0][r] = av.x; sm.u.g.As[kk + 1][r] = av.y;
            sm.u.g.As[kk + 2][r] = av.z; sm.u.g.As[kk + 3][r] = av.w;
        }
        {
            int kk = tid >> 4, n = (tid & 15) * 4;
            int gn = n0 + n;
            const __half* src = g_Whead16 + (size_t)(k0 + kk) * VV + gn;
            float b0, b1, b2, b3;
            if (gn + 3 < VV) {
                float2 f0 = __half22float2(*(const __half2*)(src));
                float2 f1 = __half22float2(*(const __half2*)(src + 2));
                b0 = f0.x; b1 = f0.y; b2 = f1.x; b3 = f1.y;
            } else {
                b0 = (gn + 0 < VV) ? __half2float(src[0]) : 0.f;
                b1 = (gn + 1 < VV) ? __half2float(src[1]) : 0.f;
                b2 = (gn + 2 < VV) ? __half2float(src[2]) : 0.f;
                b3 = (gn + 3 < VV) ? __half2float(src[3]) : 0.f;
            }
            sm.u.g.Bs[kk][n + 0] = b0; sm.u.g.Bs[kk][n + 1] = b1;
            sm.u.g.Bs[kk][n + 2] = b2; sm.u.g.Bs[kk][n + 3] = b3;
        }
        __syncthreads();
        #pragma unroll
        for (int kk = 0; kk < 16; ++kk) {
            float a[4], bv[4];
            *(float4*)a  = *(float4*)&sm.u.g.As[kk][rb];
            *(float4*)bv = *(float4*)&sm.u.g.Bs[kk][cb];
            #pragma unroll
            for (int i = 0; i < 4; ++i)
                #pragma unroll
                for (int j = 0; j < 4; ++j) acc[i][j] += a[i] * bv[j];
        }
        __syncthreads();
    }
    #pragma unroll
    for (int i = 0; i < 4; ++i) {
        int b = rb + i;
        bool msk = (g_target[b] > tprev);
        size_t rowbase = ((size_t)b * TT + tprev) * VV;
        #pragma unroll
        for (int j = 0; j < 4; ++j) {
            int gn = n0 + cb + j;
            if (gn < VV) out[rowbase + gn] = msk ? (acc[i][j] + b_head[gn]) : 0.f;
        }
    }
}

// P2 unit: scores for (b, quarter q: 49 rows). he precomputed in g_mean.
__device__ __forceinline__ void dev_score(int b, int q, SMu& sm,
        const float* __restrict__ We, const float* __restrict__ be) {
    int tid = threadIdx.x, lane = tid & 31, wid = tid >> 5;
    sm.u.a.she[tid] = g_mean[(size_t)b * 256 + tid];
    sm.u.a.swe[tid] = We[tid];
    __syncthreads();
    float be0 = be[0];
    int p0 = q * 49, p1 = p0 + 49;
    const __half* febase = g_fe16 + (size_t)b * PP * HH;
    for (int p = p0 + wid; p < p1; p += 8) {
        const __half* fr = febase + (size_t)p * HH;
        float s = 0.f;
        #pragma unroll
        for (int it = 0; it < 4; ++it) {
            int j = it * 64 + lane * 2;
            float2 fv = __half22float2(*(const __half2*)(fr + j));
            float v0 = fv.x + sm.u.a.she[j], v1 = fv.y + sm.u.a.she[j + 1];
            s += fmaxf(v0, 0.f) * sm.u.a.swe[j] + fmaxf(v1, 0.f) * sm.u.a.swe[j + 1];
        }
        #pragma unroll
        for (int o = 16; o; o >>= 1) s += __shfl_xor_sync(0xffffffffu, s, o);
        if (lane == 0) g_score[b * PP + p] = s + be0;
    }
}

// P3 unit: softmax + ctx for (b, quarter q: 512 e-columns).
__device__ __forceinline__ void dev_ctx(int b, int q, int t, int nact, SMu& sm,
        const float* __restrict__ b_gate, const float* __restrict__ emb,
        const int* __restrict__ tok, float* __restrict__ out_att) {
    int tid = threadIdx.x, lane = tid & 31, wid = tid >> 5;

    if (b >= nact) {
        if (q == 0 && tid < PP)
            out_att[((size_t)b * TT + t) * PP + tid] = 0.f;
        return;
    }

    float v = (tid < PP) ? g_score[b * PP + tid] : -3.4e38f;
    float m = v;
    #pragma unroll
    for (int o = 16; o; o >>= 1) m = fmaxf(m, __shfl_xor_sync(0xffffffffu, m, o));
    if (lane == 0) sm.u.c.red[wid] = m;
    __syncthreads();
    if (tid == 0) {
        float mm = sm.u.c.red[0];
        #pragma unroll
        for (int i = 1; i < 8; ++i) mm = fmaxf(mm, sm.u.c.red[i]);
        sm.u.c.red[0] = mm;
    }
    __syncthreads();
    float mx = sm.u.c.red[0];
    __syncthreads();

    float e = (tid < PP) ? expf(v - mx) : 0.f;
    float s = e;
    #pragma unroll
    for (int o = 16; o; o >>= 1) s += __shfl_xor_sync(0xffffffffu, s, o);
    if (lane == 0) sm.u.c.red[wid] = s;
    __syncthreads();
    if (tid == 0) {
        float ss = 0.f;
        #pragma unroll
        for (int i = 0; i < 8; ++i) ss += sm.u.c.red[i];
        sm.u.c.red[0] = ss;
    }
    __syncthreads();
    float inv = 1.0f / sm.u.c.red[0];
    if (tid < PP) sm.u.c.sw[tid] = e * inv;
    __syncthreads();

    if (q == 0) {
        if (tid < PP)
            out_att[((size_t)b * TT + t) * PP + tid] = sm.u.c.sw[tid];
        int token = tok[g_order[b] * LL + t];
        g_x[b * XK + tid] = emb[(size_t)token * EMB + tid];
        g_x[b * XK + EMB + EE + tid] = g_h[b * DD + tid];
    }

    int e0i = q * 512 + tid * 2;
    const __half* fb = g_feat16 + (size_t)b * PP * EE + e0i;

    float2 a0 = make_float2(0.f, 0.f), a1 = make_float2(0.f, 0.f);
    float2 a2 = make_float2(0.f, 0.f), a3 = make_float2(0.f, 0.f);
    #pragma unroll 2
    for (int p = 0; p < PP; p += 4) {
        float w0 = sm.u.c.sw[p], w1 = sm.u.c.sw[p + 1];
        float w2 = sm.u.c.sw[p + 2], w3 = sm.u.c.sw[p + 3];
        unsigned r0 = __ldcs((const unsigned*)(fb + (size_t)(p + 0) * EE));
        unsigned r1 = __ldcs((const unsigned*)(fb + (size_t)(p + 1) * EE));
        unsigned r2 = __ldcs((const unsigned*)(fb + (size_t)(p + 2) * EE));
        unsigned r3 = __ldcs((const unsigned*)(fb + (size_t)(p + 3) * EE));
        float2 f0 = __half22float2(*reinterpret_cast<__half2*>(&r0));
        float2 f1 = __half22float2(*reinterpret_cast<__half2*>(&r1));
        float2 f2 = __half22float2(*reinterpret_cast<__half2*>(&r2));
        float2 f3 = __half22float2(*reinterpret_cast<__half2*>(&r3));
        a0.x += w0 * f0.x; a0.y += w0 * f0.y;
        a1.x += w1 * f1.x; a1.y += w1 * f1.y;
        a2.x += w2 * f2.x; a2.y += w2 * f2.y;
        a3.x += w3 * f3.x; a3.y += w3 * f3.y;
    }
    float2 sum;
    sum.x = (a0.x + a1.x) + (a2.x + a3.x);
    sum.y = (a0.y + a1.y) + (a2.y + a3.y);

    float2 gp0 = *(const float2*)(g_gatep + (size_t)b * EE + e0i);
    float2 gp1 = *(const float2*)(g_gatep + ((size_t)NB + b) * EE + e0i);
    float2 bg  = *(const float2*)(b_gate + e0i);
    float2 ctx;
    ctx.x = sum.x * sigf(bg.x + gp0.x + gp1.x);
    ctx.y = sum.y * sigf(bg.y + gp0.y + gp1.y);
    *(float2*)(g_x + (size_t)b * XK + EMB + e0i) = ctx;
}

__device__ __forceinline__ void dev_gates(int nb, int kc, SMu& sm) {
    int tid = threadIdx.x;
    int k0g = kc * 256;
    const __half* wbase = g_Wih16 + (size_t)k0g * G4;
    float acc[4][4] = {};
    int rb = (tid >> 4) * 4, cb = (tid & 15) * 4;

    for (int kt = 0; kt < 256; kt += 16) {
        {
            int r = tid >> 2, kk = (tid & 3) * 4;
            float4 av = *(const float4*)(g_x + r * XK + k0g + kt + kk);
            sm.u.g.As[kk + 0][r] = av.x; sm.u.g.As[kk + 1][r] = av.y;
            sm.u.g.As[kk + 2][r] = av.z; sm.u.g.As[kk + 3][r] = av.w;
        }
        {
            int kk = tid >> 4, n = (tid & 15) * 4;
            const __half* src = wbase + (size_t)(kt + kk) * G4 + nb * 64 + n;
            float2 f0 = __half22float2(*(const __half2*)(src));
            float2 f1 = __half22float2(*(const __half2*)(src + 2));
            sm.u.g.Bs[kk][n + 0] = f0.x; sm.u.g.Bs[kk][n + 1] = f0.y;
            sm.u.g.Bs[kk][n + 2] = f1.x; sm.u.g.Bs[kk][n + 3] = f1.y;
        }
        __syncthreads();
        #pragma unroll
        for (int kk = 0; kk < 16; ++kk) {
            float a[4], bv[4];
            *(float4*)a  = *(float4*)&sm.u.g.As[kk][rb];
            *(float4*)bv = *(float4*)&sm.u.g.Bs[kk][cb];
            #pragma unroll
            for (int i = 0; i < 4; ++i)
                #pragma unroll
                for (int j = 0; j < 4; ++j) acc[i][j] += a[i] * bv[j];
        }
        __syncthreads();
    }
    #pragma unroll
    for (int i = 0; i < 4; ++i)
        #pragma unroll
        for (int j = 0; j < 4; ++j)
            g_gp[((size_t)kc * NB + rb + i) * G4 + nb * 64 + cb + j] = acc[i][j];
}

__device__ __forceinline__ void dev_lstm(int b, int t,
        const float* __restrict__ b_ih, const float* __restrict__ b_hh) {
    int j = threadIdx.x;
    float gi = b_ih[j] + b_hh[j];
    float gf = b_ih[DD + j] + b_hh[DD + j];
    float gg = b_ih[2 * DD + j] + b_hh[2 * DD + j];
    float go = b_ih[3 * DD + j] + b_hh[3 * DD + j];
    #pragma unroll
    for (int kc = 0; kc < KC; ++kc) {
        const float* p = g_gp + ((size_t)kc * NB + b) * G4;
        gi += p[j];
        gf += p[DD + j];
        gg += p[2 * DD + j];
        go += p[3 * DD + j];
    }
    float c = g_c[b * DD + j];
    float cn = sigf(gf) * c + sigf(gi) * tanhf(gg);
    float hn = sigf(go) * tanhf(cn);
    if (g_target[b] > t) {
        g_h[b * DD + j] = hn;
        g_c[b * DD + j] = cn;
    }
}

__global__ void __launch_bounds__(256, 2) k_loop(
        const float* __restrict__ Wh, const float* __restrict__ bh,
        const float* __restrict__ We, const float* __restrict__ be,
        const float* __restrict__ b_gate, const float* __restrict__ emb,
        const int* __restrict__ tok,
        const float* __restrict__ b_ih, const float* __restrict__ b_hh,
        const float* __restrict__ b_head,
        float* __restrict__ out, float* __restrict__ out_att) {
    __shared__ SMu sm;
    int bid = blockIdx.x;
    for (int t = 0; t < TT; ++t) {
        int nact = g_nact[t];
        // P1: he(4) + gpre(64) + head(t-1)(157) = 225 units, one round
        int nP1 = 68 + (t >= 1 ? 157 : 0);
        for (int u = bid; u < nP1; u += NBLK) {
            __syncthreads();
            if (u < 4)       dev_he(u, sm, Wh, bh);
            else if (u < 68) dev_gpre(u - 4, sm);
            else             dev_head(u - 68, t - 1, sm, b_head, out);
        }
        gridbar();
        // P2: scores, 256 quarter-units (one per block)
        if ((bid >> 2) < nact) dev_score(bid >> 2, bid & 3, sm, We, be);
        gridbar();
        // P3: softmax + ctx, 256 quarter-units (one per block)
        dev_ctx(bid >> 2, bid & 3, t, nact, sm, b_gate, emb, tok, out_att);
        gridbar();
        // P4: gates split-K GEMM (160 units)
        if (bid < 160) { __syncthreads(); dev_gates(bid & 15, bid >> 4, sm); }
        gridbar();
        // P5: LSTM pointwise (64 units)
        if (bid < NB) dev_lstm(bid, t, b_ih, b_hh);
        gridbar();
    }
    // Tail: head for the final step (t = TT-1)
    for (int u = bid; u < 157; u += NBLK) {
        __syncthreads();
        dev_head(u, TT - 1, sm, b_head, out);
    }
}

// ---------------------------------------------------------------------------
extern "C" void kernel_launch(void* const* d_in, const int* in_sizes, int n_in,
                              void* d_out, int out_size) {
    const float* feat   = (const float*)d_in[0];
    const int*   tok    = (const int*)d_in[1];
    const int*   caplen = (const int*)d_in[2];
    const float* Wf     = (const float*)d_in[3];
    const float* bf     = (const float*)d_in[4];
    const float* Wh     = (const float*)d_in[5];
    const float* bh     = (const float*)d_in[6];
    const float* We     = (const float*)d_in[7];
    const float* be     = (const float*)d_in[8];
    const float* emb    = (const float*)d_in[9];
    const float* W_ih   = (const float*)d_in[10];
    const float* b_ih   = (const float*)d_in[11];
    const float* W_hh   = (const float*)d_in[12];
    const float* b_hh   = (const float*)d_in[13];
    const float* W_hid  = (const float*)d_in[14];
    const float* b_hid  = (const float*)d_in[15];
    const float* W_cell = (const float*)d_in[16];
    const float* b_cell = (const float*)d_in[17];
    const float* W_gate = (const float*)d_in[18];
    const float* b_gate = (const float*)d_in[19];
    const float* W_head = (const float*)d_in[20];
    const float* b_head = (const float*)d_in[21];

    float* out = (float*)d_out;
    float* out_att = out + (size_t)NB * TT * VV;

    k_order<<<1, 32>>>(caplen);
    k_cvt<<<512, 256>>>(W_gate, W_ih, W_hh, W_head, Wf);
    k_cvtf<<<NB * PP, 256>>>(feat);
    k_fe<<<dim3(98, 5), 256>>>(feat, bf);         // fe HGEMM (tensor cores) + mean
    k_initA<<<dim3(8, 8), 256>>>(W_hid, W_cell);  // init GEMM, split-K
    k_init2<<<NB, 256>>>(b_hid, b_cell);

    // entire 31-step decoder loop in ONE persistent kernel
    k_loop<<<NBLK, 256>>>(Wh, bh, We, be, b_gate, emb, tok,
                          b_ih, b_hh, b_head, out, out_att);
}

// round 12
// speedup vs baseline: 1.0952x; 1.0952x over previous
#include <cuda_runtime.h>
#include <cuda_fp16.h>
#include <cstdint>

static constexpr int NB  = 64;     // batch
static constexpr int PP  = 196;    // spatial positions
static constexpr int EE  = 2048;   // feature dim
static constexpr int DD  = 256;    // hidden
static constexpr int HH  = 256;    // attention hidden
static constexpr int EMB = 256;    // embedding
static constexpr int VV  = 10000;  // vocab
static constexpr int LL  = 32;     // caption length
static constexpr int TT  = 31;     // timesteps
static constexpr int XK  = EMB + EE + DD;  // 2560
static constexpr int G4  = 4 * DD;         // 1024
static constexpr int KC  = 10;             // split-K chunks for gates gemm
static constexpr int NBLK = 256;           // persistent grid size

__device__ int    g_order[NB];
__device__ int    g_target[NB];
__device__ int    g_nact[TT + 1];           // active rows (target > t) per step
__device__ __half g_feat16[NB * PP * EE];   // 51.4 MB fp16 feat, order-permuted
__device__ __half g_fe16[NB * PP * HH];     // 6.4 MB fp16 attention features
__device__ float  g_mean[NB * EE];
__device__ float  g_h[NB * DD];
__device__ float  g_c[NB * DD];
__device__ float  g_score[NB * PP];
__device__ float  g_x[NB * XK];
__device__ float  g_gp[KC * NB * G4];       // split-K partials (gates / init)
__device__ float  g_gatep[2 * NB * EE];     // split-K partials for gate pre-act
__device__ __half g_Wg16[DD * EE];          // W_gate fp16
__device__ __half g_Wih16[XK * G4];         // [W_ih ; W_hh] fp16 concat
__device__ __half g_Whead16[DD * VV];       // W_head fp16
__device__ __half g_Wf16[EE * HH];          // Wf fp16 (same [K,N] layout)

// two-level grid barrier state (16 groups x 16 blocks); padded counters
__device__ int          g_cnt_grp[16 * 32];
__device__ int          g_cnt_root;
__device__ volatile int g_gen_grp[16 * 32];
__device__ volatile int g_gen_root;

__device__ __forceinline__ float sigf(float x) { return 1.0f / (1.0f + expf(-x)); }

// ---------------------------------------------------------------------------
// K0: stable descending counting sort + per-step active counts
// ---------------------------------------------------------------------------
__global__ void k_order(const int* __restrict__ caplen) {
    if (threadIdx.x == 0) {
        int idx = 0;
        for (int v = LL; v >= 1; --v) {
            for (int i = 0; i < NB; ++i) {
                if (caplen[i] == v) {
                    g_order[idx]  = i;
                    g_target[idx] = v - 1;
                    ++idx;
                }
            }
        }
        for (int t = 0; t <= TT; ++t) {
            int n = 0;
            for (int i = 0; i < NB; ++i) n += (g_target[i] > t) ? 1 : 0;
            g_nact[t] = n;
        }
    }
}

// ---------------------------------------------------------------------------
// K_cvt: one-time fp32 -> fp16 conversion of weights (incl. Wf)
// ---------------------------------------------------------------------------
__global__ void k_cvt(const float* __restrict__ Wg, const float* __restrict__ Wih,
                      const float* __restrict__ Whh, const float* __restrict__ Whead,
                      const float* __restrict__ Wf) {
    const int NQ_G  = (DD * EE) / 4;
    const int NQ_IH = (2304 * G4) / 4;
    const int NQ_HH = (DD * G4) / 4;
    const int NQ_HD = (DD * VV) / 4;
    const int NQ_WF = (EE * HH) / 4;
    const int total = NQ_G + NQ_IH + NQ_HH + NQ_HD + NQ_WF;
    for (int i = blockIdx.x * blockDim.x + threadIdx.x; i < total;
         i += gridDim.x * blockDim.x) {
        const float* src; __half* dst; int q;
        if (i < NQ_G)                          { src = Wg;    dst = g_Wg16;              q = i; }
        else if (i < NQ_G + NQ_IH)             { src = Wih;   dst = g_Wih16;             q = i - NQ_G; }
        else if (i < NQ_G + NQ_IH + NQ_HH)     { src = Whh;  dst = g_Wih16 + 2304 * G4;  q = i - NQ_G - NQ_IH; }
        else if (i < NQ_G + NQ_IH + NQ_HH + NQ_HD) { src = Whead; dst = g_Whead16;       q = i - NQ_G - NQ_IH - NQ_HH; }
        else                                   { src = Wf;    dst = g_Wf16;              q = i - NQ_G - NQ_IH - NQ_HH - NQ_HD; }
        float4 v = *(const float4*)(src + (size_t)q * 4);
        *(__half2*)(dst + (size_t)q * 4)     = __floats2half2_rn(v.x, v.y);
        *(__half2*)(dst + (size_t)q * 4 + 2) = __floats2half2_rn(v.z, v.w);
    }
}

// ---------------------------------------------------------------------------
// K_cvtf: one-time feat -> fp16 with the order permutation baked in.
// ---------------------------------------------------------------------------
__global__ void __launch_bounds__(256) k_cvtf(const float* __restrict__ feat) {
    int row = blockIdx.x;
    int b = row / PP, p = row % PP;
    const float* src = feat + ((size_t)g_order[b] * PP + p) * EE + threadIdx.x * 8;
    __half* dst = g_feat16 + (size_t)row * EE + threadIdx.x * 8;
    float4 v0 = *(const float4*)(src);
    float4 v1 = *(const float4*)(src + 4);
    *(__half2*)(dst + 0) = __floats2half2_rn(v0.x, v0.y);
    *(__half2*)(dst + 2) = __floats2half2_rn(v0.z, v0.w);
    *(__half2*)(dst + 4) = __floats2half2_rn(v1.x, v1.y);
    *(__half2*)(dst + 6) = __floats2half2_rn(v1.z, v1.w);
}

// ---------------------------------------------------------------------------
// K3: grid (98, 5).  y<4: fe = feat16 @ Wf16 + bf via mma.sync (tensor cores).
//     y==4: mean over positions from fp32 feat (blocks 0..63).
// ---------------------------------------------------------------------------
__global__ void __launch_bounds__(256) k_fe(const float* __restrict__ feat,
                                            const float* __restrict__ bf) {
    int tid = threadIdx.x;
    int mb = blockIdx.x, nb = blockIdx.y;

    if (nb == 4) {
        if (mb >= NB) return;
        int b = mb;
        const float4* base = (const float4*)(feat + (size_t)g_order[b] * PP * EE);
        float4 sA = make_float4(0.f, 0.f, 0.f, 0.f);
        float4 sB = make_float4(0.f, 0.f, 0.f, 0.f);
        #pragma unroll 2
        for (int p = 0; p < PP; ++p) {
            float4 v0 = __ldcs(base + (size_t)p * (EE / 4) + tid);
            float4 v1 = __ldcs(base + (size_t)p * (EE / 4) + tid + 256);
            sA.x += v0.x; sA.y += v0.y; sA.z += v0.z; sA.w += v0.w;
            sB.x += v1.x; sB.y += v1.y; sB.z += v1.z; sB.w += v1.w;
        }
        const float inv = 1.0f / PP;
        sA.x *= inv; sA.y *= inv; sA.z *= inv; sA.w *= inv;
        sB.x *= inv; sB.y *= inv; sB.z *= inv; sB.w *= inv;
        *(float4*)(g_mean + b * EE + tid * 4)        = sA;
        *(float4*)(g_mean + b * EE + 1024 + tid * 4) = sB;
        return;
    }

    __shared__ __half As[128][72];
    __shared__ __half Bs[64][72];

    int warp = tid >> 5, lane = tid & 31;
    int wm = warp & 3, wn = warp >> 2;

    float acc[2][4][4] = {};

    for (int k0 = 0; k0 < EE; k0 += 64) {
        #pragma unroll
        for (int i = 0; i < 4; ++i) {
            int idx = tid + i * 256;
            int r = idx >> 3, c = (idx & 7) * 8;
            *(uint4*)&As[r][c] =
                *(const uint4*)(g_feat16 + (size_t)(mb * 128 + r) * EE + k0 + c);
        }
        #pragma unroll
        for (int i = 0; i < 2; ++i) {
            int idx = tid + i * 256;
            int r = idx >> 3, c = (idx & 7) * 8;
            *(uint4*)&Bs[r][c] =
                *(const uint4*)(g_Wf16 + (size_t)(k0 + r) * HH + nb * 64 + c);
        }
        __syncthreads();

        #pragma unroll
        for (int kk = 0; kk < 64; kk += 16) {
            unsigned a[2][4], b[4][2];
            #pragma unroll
            for (int mi = 0; mi < 2; ++mi) {
                unsigned addr = (unsigned)__cvta_generic_to_shared(
                    &As[wm * 32 + mi * 16 + (lane & 15)][kk + (lane >> 4) * 8]);
                asm volatile("ldmatrix.sync.aligned.m8n8.x4.shared.b16 {%0,%1,%2,%3}, [%4];"
                    : "=r"(a[mi][0]), "=r"(a[mi][1]), "=r"(a[mi][2]), "=r"(a[mi][3])
                    : "r"(addr));
            }
            #pragma unroll
            for (int ni = 0; ni < 4; ++ni) {
                unsigned addr = (unsigned)__cvta_generic_to_shared(
                    &Bs[kk + (lane & 15)][wn * 32 + ni * 8]);
                asm volatile("ldmatrix.sync.aligned.m8n8.x2.trans.shared.b16 {%0,%1}, [%2];"
                    : "=r"(b[ni][0]), "=r"(b[ni][1]) : "r"(addr));
            }
            #pragma unroll
            for (int mi = 0; mi < 2; ++mi)
                #pragma unroll
                for (int ni = 0; ni < 4; ++ni)
                    asm volatile(
                        "mma.sync.aligned.m16n8k16.row.col.f32.f16.f16.f32 "
                        "{%0,%1,%2,%3}, {%4,%5,%6,%7}, {%8,%9}, {%0,%1,%2,%3};"
                        : "+f"(acc[mi][ni][0]), "+f"(acc[mi][ni][1]),
                          "+f"(acc[mi][ni][2]), "+f"(acc[mi][ni][3])
                        : "r"(a[mi][0]), "r"(a[mi][1]), "r"(a[mi][2]), "r"(a[mi][3]),
                          "r"(b[ni][0]), "r"(b[ni][1]));
        }
        __syncthreads();
    }

    int gr = lane >> 2;
    int gc = (lane & 3) * 2;
    #pragma unroll
    for (int mi = 0; mi < 2; ++mi)
        #pragma unroll
        for (int ni = 0; ni < 4; ++ni) {
            int gn = nb * 64 + wn * 32 + ni * 8 + gc;
            float b0 = bf[gn], b1 = bf[gn + 1];
            int m0 = mb * 128 + wm * 32 + mi * 16 + gr;
            *(__half2*)(g_fe16 + (size_t)m0 * HH + gn) =
                __floats2half2_rn(acc[mi][ni][0] + b0, acc[mi][ni][1] + b1);
            int m1 = m0 + 8;
            *(__half2*)(g_fe16 + (size_t)m1 * HH + gn) =
                __floats2half2_rn(acc[mi][ni][2] + b0, acc[mi][ni][3] + b1);
        }
}

// ---------------------------------------------------------------------------
// K2a: init GEMM  mean(64x2048) @ [W_hid | W_cell](2048x512), split-K=8.
// ---------------------------------------------------------------------------
__global__ void __launch_bounds__(256) k_initA(const float* __restrict__ W_hid,
                                               const float* __restrict__ W_cell) {
    __shared__ float As[16][68];
    __shared__ float Bs[16][64];
    int tid = threadIdx.x;
    int nb = blockIdx.x, kc = blockIdx.y;
    const float* wsrc = (nb < 4) ? W_hid : W_cell;
    int ncol0 = (nb & 3) * 64;
    int k0g = kc * 256;
    float acc[4][4] = {};
    int rb = (tid >> 4) * 4, cb = (tid & 15) * 4;

    for (int kt = 0; kt < 256; kt += 16) {
        {
            int r = tid >> 2, kk = (tid & 3) * 4;
            float4 av = *(const float4*)(g_mean + r * EE + k0g + kt + kk);
            As[kk + 0][r] = av.x; As[kk + 1][r] = av.y;
            As[kk + 2][r] = av.z; As[kk + 3][r] = av.w;
        }
        {
            int kk = tid >> 4, n = (tid & 15) * 4;
            *(float4*)&Bs[kk][n] =
                *(const float4*)(wsrc + (size_t)(k0g + kt + kk) * DD + ncol0 + n);
        }
        __syncthreads();
        #pragma unroll
        for (int kk = 0; kk < 16; ++kk) {
            float a[4], bv[4];
            *(float4*)a  = *(float4*)&As[kk][rb];
            *(float4*)bv = *(float4*)&Bs[kk][cb];
            #pragma unroll
            for (int i = 0; i < 4; ++i)
                #pragma unroll
                for (int j = 0; j < 4; ++j) acc[i][j] += a[i] * bv[j];
        }
        __syncthreads();
    }
    #pragma unroll
    for (int i = 0; i < 4; ++i)
        #pragma unroll
        for (int j = 0; j < 4; ++j)
            g_gp[((size_t)kc * NB + rb + i) * 512 + nb * 64 + cb + j] = acc[i][j];
}

__global__ void k_init2(const float* __restrict__ b_hid, const float* __restrict__ b_cell) {
    int b = blockIdx.x, j = threadIdx.x;
    float h = b_hid[j], c = b_cell[j];
    #pragma unroll
    for (int kc = 0; kc < 8; ++kc) {
        const float* p = g_gp + ((size_t)kc * NB + b) * 512;
        h += p[j];
        c += p[256 + j];
    }
    g_h[b * DD + j] = h;
    g_c[b * DD + j] = c;
}

// ===========================================================================
// Persistent step-loop kernel (Round-10 structure; two-level barrier only)
// ===========================================================================
struct SMu {
    union {
        struct { float As[16][68]; float Bs[16][64]; } g;
        struct { float sh[256]; float she[256]; float swe[256]; } a;
        struct { float sw[256]; float red[8]; } c;
    } u;
};

// two-level grid barrier: 16 groups of 16 blocks, padded counters
__device__ __forceinline__ void gridbar() {
    __syncthreads();
    __threadfence();
    if (threadIdx.x == 0) {
        int g = blockIdx.x & 15;
        int* cnt = &g_cnt_grp[g * 32];
        volatile int* gen = &g_gen_grp[g * 32];
        int my = *gen;
        if (atomicAdd(cnt, 1) == 15) {
            *cnt = 0;
            int rmy = g_gen_root;
            if (atomicAdd(&g_cnt_root, 1) == 15) {
                g_cnt_root = 0;
                __threadfence();
                g_gen_root = rmy + 1;
            } else {
                while (g_gen_root == rmy) __nanosleep(32);
            }
            __threadfence();
            *gen = my + 1;
        } else {
            while (*gen == my) __nanosleep(32);
        }
    }
    __syncthreads();
    __threadfence();
}

__device__ __forceinline__ void dev_score(int b, int half, SMu& sm,
        const float* __restrict__ Wh, const float* __restrict__ bh,
        const float* __restrict__ We, const float* __restrict__ be) {
    int tid = threadIdx.x, lane = tid & 31, wid = tid >> 5;
    sm.u.a.sh[tid]  = g_h[b * DD + tid];
    sm.u.a.swe[tid] = We[tid];
    __syncthreads();
    float acc = bh[tid];
    #pragma unroll 8
    for (int k = 0; k < DD; ++k) acc += sm.u.a.sh[k] * Wh[k * HH + tid];
    sm.u.a.she[tid] = acc;
    __syncthreads();
    float be0 = be[0];
    int p0 = half * 98, p1 = p0 + 98;
    const __half* febase = g_fe16 + (size_t)b * PP * HH;
    for (int p = p0 + wid; p < p1; p += 8) {
        const __half* fr = febase + (size_t)p * HH;
        float s = 0.f;
        #pragma unroll
        for (int it = 0; it < 4; ++it) {
            int j = it * 64 + lane * 2;
            float2 fv = __half22float2(*(const __half2*)(fr + j));
            float v0 = fv.x + sm.u.a.she[j], v1 = fv.y + sm.u.a.she[j + 1];
            s += fmaxf(v0, 0.f) * sm.u.a.swe[j] + fmaxf(v1, 0.f) * sm.u.a.swe[j + 1];
        }
        #pragma unroll
        for (int o = 16; o; o >>= 1) s += __shfl_xor_sync(0xffffffffu, s, o);
        if (lane == 0) g_score[b * PP + p] = s + be0;
    }
}

__device__ __forceinline__ void dev_gpre(int bid, SMu& sm) {
    int tid = threadIdx.x;
    int nb = bid & 31, kc = bid >> 5;
    int kbase = kc * 128;
    float acc[4][4] = {};
    int rb = (tid >> 4) * 4, cb = (tid & 15) * 4;

    for (int kt = 0; kt < 128; kt += 16) {
        {
            int r = tid >> 2, kk = (tid & 3) * 4;
            float4 av = *(const float4*)(g_h + r * DD + kbase + kt + kk);
            sm.u.g.As[kk + 0][r] = av.x; sm.u.g.As[kk + 1][r] = av.y;
            sm.u.g.As[kk + 2][r] = av.z; sm.u.g.As[kk + 3][r] = av.w;
        }
        {
            int kk = tid >> 4, n = (tid & 15) * 4;
            const __half* src = g_Wg16 + (size_t)(kbase + kt + kk) * EE + nb * 64 + n;
            float2 f0 = __half22float2(*(const __half2*)(src));
            float2 f1 = __half22float2(*(const __half2*)(src + 2));
            sm.u.g.Bs[kk][n + 0] = f0.x; sm.u.g.Bs[kk][n + 1] = f0.y;
            sm.u.g.Bs[kk][n + 2] = f1.x; sm.u.g.Bs[kk][n + 3] = f1.y;
        }
        __syncthreads();
        #pragma unroll
        for (int kk = 0; kk < 16; ++kk) {
            float a[4], bv[4];
            *(float4*)a  = *(float4*)&sm.u.g.As[kk][rb];
            *(float4*)bv = *(float4*)&sm.u.g.Bs[kk][cb];
            #pragma unroll
            for (int i = 0; i < 4; ++i)
                #pragma unroll
                for (int j = 0; j < 4; ++j) acc[i][j] += a[i] * bv[j];
        }
        __syncthreads();
    }
    #pragma unroll
    for (int i = 0; i < 4; ++i)
        #pragma unroll
        for (int j = 0; j < 4; ++j)
            g_gatep[((size_t)kc * NB + rb + i) * EE + nb * 64 + cb + j] = acc[i][j];
}

__device__ __forceinline__ void dev_head(int nb, int tprev, SMu& sm,
        const float* __restrict__ b_head, float* __restrict__ out) {
    int tid = threadIdx.x;
    int n0 = nb * 64;
    float acc[4][4] = {};
    int rb = (tid >> 4) * 4, cb = (tid & 15) * 4;

    for (int k0 = 0; k0 < DD; k0 += 16) {
        {
            int r = tid >> 2, kk = (tid & 3) * 4;
            float4 av = *(const float4*)(g_h + r * DD + k0 + kk);
            sm.u.g.As[kk + 0][r] = av.x; sm.u.g.As[kk + 1][r] = av.y;
            sm.u.g.As[kk + 2][r] = av.z; sm.u.g.As[kk + 3][r] = av.w;
        }
        {
            int kk = tid >> 4, n = (tid & 15) * 4;
            int gn = n0 + n;
            const __half* src = g_Whead16 + (size_t)(k0 + kk) * VV + gn;
            float b0, b1, b2, b3;
            if (gn + 3 < VV) {
                float2 f0 = __half22float2(*(const __half2*)(src));
                float2 f1 = __half22float2(*(const __half2*)(src + 2));
                b0 = f0.x; b1 = f0.y; b2 = f1.x; b3 = f1.y;
            } else {
                b0 = (gn + 0 < VV) ? __half2float(src[0]) : 0.f;
                b1 = (gn + 1 < VV) ? __half2float(src[1]) : 0.f;
                b2 = (gn + 2 < VV) ? __half2float(src[2]) : 0.f;
                b3 = (gn + 3 < VV) ? __half2float(src[3]) : 0.f;
            }
            sm.u.g.Bs[kk][n + 0] = b0; sm.u.g.Bs[kk][n + 1] = b1;
            sm.u.g.Bs[kk][n + 2] = b2; sm.u.g.Bs[kk][n + 3] = b3;
        }
        __syncthreads();
        #pragma unroll
        for (int kk = 0; kk < 16; ++kk) {
            float a[4], bv[4];
            *(float4*)a  = *(float4*)&sm.u.g.As[kk][rb];
            *(float4*)bv = *(float4*)&sm.u.g.Bs[kk][cb];
            #pragma unroll
            for (int i = 0; i < 4; ++i)
                #pragma unroll
                for (int j = 0; j < 4; ++j) acc[i][j] += a[i] * bv[j];
        }
        __syncthreads();
    }
    #pragma unroll
    for (int i = 0; i < 4; ++i) {
        int b = rb + i;
        bool msk = (g_target[b] > tprev);
        size_t rowbase = ((size_t)b * TT + tprev) * VV;
        #pragma unroll
        for (int j = 0; j < 4; ++j) {
            int gn = n0 + cb + j;
            if (gn < VV) out[rowbase + gn] = msk ? (acc[i][j] + b_head[gn]) : 0.f;
        }
    }
}

__device__ __forceinline__ void dev_ctx(int b, int half, int t, int nact, SMu& sm,
        const float* __restrict__ b_gate, const float* __restrict__ emb,
        const int* __restrict__ tok, float* __restrict__ out_att) {
    int tid = threadIdx.x, lane = tid & 31, wid = tid >> 5;

    if (b >= nact) {
        if (half == 0 && tid < PP)
            out_att[((size_t)b * TT + t) * PP + tid] = 0.f;
        return;
    }

    float v = (tid < PP) ? g_score[b * PP + tid] : -3.4e38f;
    float m = v;
    #pragma unroll
    for (int o = 16; o; o >>= 1) m = fmaxf(m, __shfl_xor_sync(0xffffffffu, m, o));
    if (lane == 0) sm.u.c.red[wid] = m;
    __syncthreads();
    if (tid == 0) {
        float mm = sm.u.c.red[0];
        #pragma unroll
        for (int i = 1; i < 8; ++i) mm = fmaxf(mm, sm.u.c.red[i]);
        sm.u.c.red[0] = mm;
    }
    __syncthreads();
    float mx = sm.u.c.red[0];
    __syncthreads();

    float e = (tid < PP) ? expf(v - mx) : 0.f;
    float s = e;
    #pragma unroll
    for (int o = 16; o; o >>= 1) s += __shfl_xor_sync(0xffffffffu, s, o);
    if (lane == 0) sm.u.c.red[wid] = s;
    __syncthreads();
    if (tid == 0) {
        float ss = 0.f;
        #pragma unroll
        for (int i = 0; i < 8; ++i) ss += sm.u.c.red[i];
        sm.u.c.red[0] = ss;
    }
    __syncthreads();
    float inv = 1.0f / sm.u.c.red[0];
    if (tid < PP) sm.u.c.sw[tid] = e * inv;
    __syncthreads();

    if (half == 0) {
        if (tid < PP)
            out_att[((size_t)b * TT + t) * PP + tid] = sm.u.c.sw[tid];
        int token = tok[g_order[b] * LL + t];
        g_x[b * XK + tid] = emb[(size_t)token * EMB + tid];
        g_x[b * XK + EMB + EE + tid] = g_h[b * DD + tid];
    }

    int e0i = half * 1024 + tid * 4;
    const __half* fb = g_feat16 + (size_t)b * PP * EE + e0i;

    float4 s0 = make_float4(0.f, 0.f, 0.f, 0.f);
    float4 s1 = make_float4(0.f, 0.f, 0.f, 0.f);
    float4 s2 = make_float4(0.f, 0.f, 0.f, 0.f);
    float4 s3 = make_float4(0.f, 0.f, 0.f, 0.f);
    for (int p = 0; p < PP; p += 4) {
        float w0 = sm.u.c.sw[p], w1 = sm.u.c.sw[p + 1];
        float w2 = sm.u.c.sw[p + 2], w3 = sm.u.c.sw[p + 3];
        uint2 r0 = __ldcs((const uint2*)(fb + (size_t)(p + 0) * EE));
        uint2 r1 = __ldcs((const uint2*)(fb + (size_t)(p + 1) * EE));
        uint2 r2 = __ldcs((const uint2*)(fb + (size_t)(p + 2) * EE));
        uint2 r3 = __ldcs((const uint2*)(fb + (size_t)(p + 3) * EE));
        float2 a0 = __half22float2(*reinterpret_cast<__half2*>(&r0.x));
        float2 c0 = __half22float2(*reinterpret_cast<__half2*>(&r0.y));
        float2 a1 = __half22float2(*reinterpret_cast<__half2*>(&r1.x));
        float2 c1 = __half22float2(*reinterpret_cast<__half2*>(&r1.y));
        float2 a2 = __half22float2(*reinterpret_cast<__half2*>(&r2.x));
        float2 c2 = __half22float2(*reinterpret_cast<__half2*>(&r2.y));
        float2 a3 = __half22float2(*reinterpret_cast<__half2*>(&r3.x));
        float2 c3 = __half22float2(*reinterpret_cast<__half2*>(&r3.y));
        s0.x += w0 * a0.x; s0.y += w0 * a0.y; s0.z += w0 * c0.x; s0.w += w0 * c0.y;
        s1.x += w1 * a1.x; s1.y += w1 * a1.y; s1.z += w1 * c1.x; s1.w += w1 * c1.y;
        s2.x += w2 * a2.x; s2.y += w2 * a2.y; s2.z += w2 * c2.x; s2.w += w2 * c2.y;
        s3.x += w3 * a3.x; s3.y += w3 * a3.y; s3.z += w3 * c3.x; s3.w += w3 * c3.y;
    }
    float4 sum;
    sum.x = (s0.x + s1.x) + (s2.x + s3.x);
    sum.y = (s0.y + s1.y) + (s2.y + s3.y);
    sum.z = (s0.z + s1.z) + (s2.z + s3.z);
    sum.w = (s0.w + s1.w) + (s2.w + s3.w);

    float4 gp0 = *(const float4*)(g_gatep + (size_t)b * EE + e0i);
    float4 gp1 = *(const float4*)(g_gatep + ((size_t)NB + b) * EE + e0i);
    float4 bg  = *(const float4*)(b_gate + e0i);
    float4 ctx;
    ctx.x = sum.x * sigf(bg.x + gp0.x + gp1.x);
    ctx.y = sum.y * sigf(bg.y + gp0.y + gp1.y);
    ctx.z = sum.z * sigf(bg.z + gp0.z + gp1.z);
    ctx.w = sum.w * sigf(bg.w + gp0.w + gp1.w);
    *(float4*)(g_x + (size_t)b * XK + EMB + e0i) = ctx;
}

__device__ __forceinline__ void dev_gates(int nb, int kc, SMu& sm) {
    int tid = threadIdx.x;
    int k0g = kc * 256;
    const __half* wbase = g_Wih16 + (size_t)k0g * G4;
    float acc[4][4] = {};
    int rb = (tid >> 4) * 4, cb = (tid & 15) * 4;

    for (int kt = 0; kt < 256; kt += 16) {
        {
            int r = tid >> 2, kk = (tid & 3) * 4;
            float4 av = *(const float4*)(g_x + r * XK + k0g + kt + kk);
            sm.u.g.As[kk + 0][r] = av.x; sm.u.g.As[kk + 1][r] = av.y;
            sm.u.g.As[kk + 2][r] = av.z; sm.u.g.As[kk + 3][r] = av.w;
        }
        {
            int kk = tid >> 4, n = (tid & 15) * 4;
            const __half* src = wbase + (size_t)(kt + kk) * G4 + nb * 64 + n;
            float2 f0 = __half22float2(*(const __half2*)(src));
            float2 f1 = __half22float2(*(const __half2*)(src + 2));
            sm.u.g.Bs[kk][n + 0] = f0.x; sm.u.g.Bs[kk][n + 1] = f0.y;
            sm.u.g.Bs[kk][n + 2] = f1.x; sm.u.g.Bs[kk][n + 3] = f1.y;
        }
        __syncthreads();
        #pragma unroll
        for (int kk = 0; kk < 16; ++kk) {
            float a[4], bv[4];
            *(float4*)a  = *(float4*)&sm.u.g.As[kk][rb];
            *(float4*)bv = *(float4*)&sm.u.g.Bs[kk][cb];
            #pragma unroll
            for (int i = 0; i < 4; ++i)
                #pragma unroll
                for (int j = 0; j < 4; ++j) acc[i][j] += a[i] * bv[j];
        }
        __syncthreads();
    }
    #pragma unroll
    for (int i = 0; i < 4; ++i)
        #pragma unroll
        for (int j = 0; j < 4; ++j)
            g_gp[((size_t)kc * NB + rb + i) * G4 + nb * 64 + cb + j] = acc[i][j];
}

__device__ __forceinline__ void dev_lstm(int b, int t,
        const float* __restrict__ b_ih, const float* __restrict__ b_hh) {
    int j = threadIdx.x;
    float gi = b_ih[j] + b_hh[j];
    float gf = b_ih[DD + j] + b_hh[DD + j];
    float gg = b_ih[2 * DD + j] + b_hh[2 * DD + j];
    float go = b_ih[3 * DD + j] + b_hh[3 * DD + j];
    #pragma unroll
    for (int kc = 0; kc < KC; ++kc) {
        const float* p = g_gp + ((size_t)kc * NB + b) * G4;
        gi += p[j];
        gf += p[DD + j];
        gg += p[2 * DD + j];
        go += p[3 * DD + j];
    }
    float c = g_c[b * DD + j];
    float cn = sigf(gf) * c + sigf(gi) * tanhf(gg);
    float hn = sigf(go) * tanhf(cn);
    if (g_target[b] > t) {
        g_h[b * DD + j] = hn;
        g_c[b * DD + j] = cn;
    }
}

__global__ void __launch_bounds__(256, 2) k_loop(
        const float* __restrict__ Wh, const float* __restrict__ bh,
        const float* __restrict__ We, const float* __restrict__ be,
        const float* __restrict__ b_gate, const float* __restrict__ emb,
        const int* __restrict__ tok,
        const float* __restrict__ b_ih, const float* __restrict__ b_hh,
        const float* __restrict__ b_head,
        float* __restrict__ out, float* __restrict__ out_att) {
    __shared__ SMu sm;
    for (int t = 0; t < TT; ++t) {
        int nact = g_nact[t];
        // Phase A: scores(t) 128 + gpre(t) 64 + head(t-1) nb[0,64) = 256 units
        int nA = 192 + (t >= 1 ? 64 : 0);
        for (int u = blockIdx.x; u < nA; u += NBLK) {
            __syncthreads();
            if (u < 128) {
                if ((u >> 1) < nact) dev_score(u >> 1, u & 1, sm, Wh, bh, We, be);
            }
            else if (u < 192) dev_gpre(u - 128, sm);
            else              dev_head(u - 192, t - 1, sm, b_head, out);
        }
        gridbar();
        // Phase B: ctx 128 + head(t-1) nb[64,157) = 221 units
        int nB = 128 + (t >= 1 ? 93 : 0);
        for (int u = blockIdx.x; u < nB; u += NBLK) {
            __syncthreads();
            if (u < 128) dev_ctx(u >> 1, u & 1, t, nact, sm, b_gate, emb, tok, out_att);
            else         dev_head(64 + (u - 128), t - 1, sm, b_head, out);
        }
        gridbar();
        // Phase C: gates split-K GEMM (160 units)
        for (int u = blockIdx.x; u < 160; u += NBLK) {
            __syncthreads();
            dev_gates(u & 15, u >> 4, sm);
        }
        gridbar();
        // Phase D: LSTM pointwise (64 units)
        if (blockIdx.x < NB) dev_lstm(blockIdx.x, t, b_ih, b_hh);
        gridbar();
    }
    // Tail: head for the final step (t = TT-1)
    for (int u = blockIdx.x; u < 157; u += NBLK) {
        __syncthreads();
        dev_head(u, TT - 1, sm, b_head, out);
    }
}

// ---------------------------------------------------------------------------
extern "C" void kernel_launch(void* const* d_in, const int* in_sizes, int n_in,
                              void* d_out, int out_size) {
    const float* feat   = (const float*)d_in[0];
    const int*   tok    = (const int*)d_in[1];
    const int*   caplen = (const int*)d_in[2];
    const float* Wf     = (const float*)d_in[3];
    const float* bf     = (const float*)d_in[4];
    const float* Wh     = (const float*)d_in[5];
    const float* bh     = (const float*)d_in[6];
    const float* We     = (const float*)d_in[7];
    const float* be     = (const float*)d_in[8];
    const float* emb    = (const float*)d_in[9];
    const float* W_ih   = (const float*)d_in[10];
    const float* b_ih   = (const float*)d_in[11];
    const float* W_hh   = (const float*)d_in[12];
    const float* b_hh   = (const float*)d_in[13];
    const float* W_hid  = (const float*)d_in[14];
    const float* b_hid  = (const float*)d_in[15];
    const float* W_cell = (const float*)d_in[16];
    const float* b_cell = (const float*)d_in[17];
    const float* W_gate = (const float*)d_in[18];
    const float* b_gate = (const float*)d_in[19];
    const float* W_head = (const float*)d_in[20];
    const float* b_head = (const float*)d_in[21];

    float* out = (float*)d_out;
    float* out_att = out + (size_t)NB * TT * VV;

    k_order<<<1, 32>>>(caplen);
    k_cvt<<<512, 256>>>(W_gate, W_ih, W_hh, W_head, Wf);
    k_cvtf<<<NB * PP, 256>>>(feat);
    k_fe<<<dim3(98, 5), 256>>>(feat, bf);         // fe HGEMM (tensor cores) + mean
    k_initA<<<dim3(8, 8), 256>>>(W_hid, W_cell);  // init GEMM, split-K
    k_init2<<<NB, 256>>>(b_hid, b_cell);

    // entire 31-step decoder loop in ONE persistent kernel
    k_loop<<<NBLK, 256>>>(Wh, bh, We, be, b_gate, emb, tok,
                          b_ih, b_hh, b_head, out, out_att);
}

// round 13
// speedup vs baseline: 1.2537x; 1.1447x over previous
#include <cuda_runtime.h>
#include <cuda_fp16.h>
#include <cstdint>

static constexpr int NB  = 64;     // batch
static constexpr int PP  = 196;    // spatial positions
static constexpr int EE  = 2048;   // feature dim
static constexpr int DD  = 256;    // hidden
static constexpr int HH  = 256;    // attention hidden
static constexpr int EMB = 256;    // embedding
static constexpr int VV  = 10000;  // vocab
static constexpr int LL  = 32;     // caption length
static constexpr int TT  = 31;     // timesteps
static constexpr int XK  = EMB + EE + DD;  // 2560
static constexpr int G4  = 4 * DD;         // 1024
static constexpr int KC  = 10;             // split-K chunks for gates gemm
static constexpr int NBLK = 256;           // persistent grid size

__device__ int    g_order[NB];
__device__ int    g_target[NB];
__device__ int    g_nact[TT + 1];           // active rows (target > t) per step
__device__ __half g_feat16[NB * PP * EE];   // 51.4 MB fp16 feat, order-permuted
__device__ __half g_fe16[NB * PP * HH];     // 6.4 MB fp16 attention features
__device__ float  g_mean[NB * EE];
__device__ float  g_h[NB * DD];
__device__ float  g_c[NB * DD];
__device__ float  g_score[NB * PP];
__device__ float  g_x[NB * XK];
__device__ float  g_gp[KC * NB * G4];       // split-K partials (gates / init)
__device__ float  g_gatep[2 * NB * EE];     // split-K partials for gate pre-act
__device__ __half g_Wg16[DD * EE];          // W_gate fp16
__device__ __half g_Wih16[XK * G4];         // [W_ih ; W_hh] fp16 concat
__device__ __half g_Whead16[DD * VV];       // W_head fp16
__device__ __half g_Wf16[EE * HH];          // Wf fp16 (same [K,N] layout)

// single-level grid barrier (R10 variant — fastest measured)
__device__ int          g_bar_count;
__device__ volatile int g_bar_gen;

__device__ __forceinline__ float sigf(float x) { return 1.0f / (1.0f + expf(-x)); }

// ---------------------------------------------------------------------------
// K0: stable descending counting sort + per-step active counts
// ---------------------------------------------------------------------------
__global__ void k_order(const int* __restrict__ caplen) {
    if (threadIdx.x == 0) {
        int idx = 0;
        for (int v = LL; v >= 1; --v) {
            for (int i = 0; i < NB; ++i) {
                if (caplen[i] == v) {
                    g_order[idx]  = i;
                    g_target[idx] = v - 1;
                    ++idx;
                }
            }
        }
        for (int t = 0; t <= TT; ++t) {
            int n = 0;
            for (int i = 0; i < NB; ++i) n += (g_target[i] > t) ? 1 : 0;
            g_nact[t] = n;
        }
    }
}

// ---------------------------------------------------------------------------
// K_cvt: one-time fp32 -> fp16 conversion of weights (incl. Wf)
// ---------------------------------------------------------------------------
__global__ void k_cvt(const float* __restrict__ Wg, const float* __restrict__ Wih,
                      const float* __restrict__ Whh, const float* __restrict__ Whead,
                      const float* __restrict__ Wf) {
    const int NQ_G  = (DD * EE) / 4;
    const int NQ_IH = (2304 * G4) / 4;
    const int NQ_HH = (DD * G4) / 4;
    const int NQ_HD = (DD * VV) / 4;
    const int NQ_WF = (EE * HH) / 4;
    const int total = NQ_G + NQ_IH + NQ_HH + NQ_HD + NQ_WF;
    for (int i = blockIdx.x * blockDim.x + threadIdx.x; i < total;
         i += gridDim.x * blockDim.x) {
        const float* src; __half* dst; int q;
        if (i < NQ_G)                          { src = Wg;    dst = g_Wg16;              q = i; }
        else if (i < NQ_G + NQ_IH)             { src = Wih;   dst = g_Wih16;             q = i - NQ_G; }
        else if (i < NQ_G + NQ_IH + NQ_HH)     { src = Whh;  dst = g_Wih16 + 2304 * G4;  q = i - NQ_G - NQ_IH; }
        else if (i < NQ_G + NQ_IH + NQ_HH + NQ_HD) { src = Whead; dst = g_Whead16;       q = i - NQ_G - NQ_IH - NQ_HH; }
        else                                   { src = Wf;    dst = g_Wf16;              q = i - NQ_G - NQ_IH - NQ_HH - NQ_HD; }
        float4 v = *(const float4*)(src + (size_t)q * 4);
        *(__half2*)(dst + (size_t)q * 4)     = __floats2half2_rn(v.x, v.y);
        *(__half2*)(dst + (size_t)q * 4 + 2) = __floats2half2_rn(v.z, v.w);
    }
}

// ---------------------------------------------------------------------------
// K_cvtf: one-time feat -> fp16 with the order permutation baked in.
// ---------------------------------------------------------------------------
__global__ void __launch_bounds__(256) k_cvtf(const float* __restrict__ feat) {
    int row = blockIdx.x;
    int b = row / PP, p = row % PP;
    const float* src = feat + ((size_t)g_order[b] * PP + p) * EE + threadIdx.x * 8;
    __half* dst = g_feat16 + (size_t)row * EE + threadIdx.x * 8;
    float4 v0 = *(const float4*)(src);
    float4 v1 = *(const float4*)(src + 4);
    *(__half2*)(dst + 0) = __floats2half2_rn(v0.x, v0.y);
    *(__half2*)(dst + 2) = __floats2half2_rn(v0.z, v0.w);
    *(__half2*)(dst + 4) = __floats2half2_rn(v1.x, v1.y);
    *(__half2*)(dst + 6) = __floats2half2_rn(v1.z, v1.w);
}

// ---------------------------------------------------------------------------
// K3: grid (98, 5).  y<4: fe = feat16 @ Wf16 + bf via mma.sync (tensor cores).
//     y==4: mean over positions from fp32 feat (blocks 0..63).
// ---------------------------------------------------------------------------
__global__ void __launch_bounds__(256) k_fe(const float* __restrict__ feat,
                                            const float* __restrict__ bf) {
    int tid = threadIdx.x;
    int mb = blockIdx.x, nb = blockIdx.y;

    if (nb == 4) {
        if (mb >= NB) return;
        int b = mb;
        const float4* base = (const float4*)(feat + (size_t)g_order[b] * PP * EE);
        float4 sA = make_float4(0.f, 0.f, 0.f, 0.f);
        float4 sB = make_float4(0.f, 0.f, 0.f, 0.f);
        #pragma unroll 2
        for (int p = 0; p < PP; ++p) {
            float4 v0 = __ldcs(base + (size_t)p * (EE / 4) + tid);
            float4 v1 = __ldcs(base + (size_t)p * (EE / 4) + tid + 256);
            sA.x += v0.x; sA.y += v0.y; sA.z += v0.z; sA.w += v0.w;
            sB.x += v1.x; sB.y += v1.y; sB.z += v1.z; sB.w += v1.w;
        }
        const float inv = 1.0f / PP;
        sA.x *= inv; sA.y *= inv; sA.z *= inv; sA.w *= inv;
        sB.x *= inv; sB.y *= inv; sB.z *= inv; sB.w *= inv;
        *(float4*)(g_mean + b * EE + tid * 4)        = sA;
        *(float4*)(g_mean + b * EE + 1024 + tid * 4) = sB;
        return;
    }

    __shared__ __half As[128][72];
    __shared__ __half Bs[64][72];

    int warp = tid >> 5, lane = tid & 31;
    int wm = warp & 3, wn = warp >> 2;

    float acc[2][4][4] = {};

    for (int k0 = 0; k0 < EE; k0 += 64) {
        #pragma unroll
        for (int i = 0; i < 4; ++i) {
            int idx = tid + i * 256;
            int r = idx >> 3, c = (idx & 7) * 8;
            *(uint4*)&As[r][c] =
                *(const uint4*)(g_feat16 + (size_t)(mb * 128 + r) * EE + k0 + c);
        }
        #pragma unroll
        for (int i = 0; i < 2; ++i) {
            int idx = tid + i * 256;
            int r = idx >> 3, c = (idx & 7) * 8;
            *(uint4*)&Bs[r][c] =
                *(const uint4*)(g_Wf16 + (size_t)(k0 + r) * HH + nb * 64 + c);
        }
        __syncthreads();

        #pragma unroll
        for (int kk = 0; kk < 64; kk += 16) {
            unsigned a[2][4], b[4][2];
            #pragma unroll
            for (int mi = 0; mi < 2; ++mi) {
                unsigned addr = (unsigned)__cvta_generic_to_shared(
                    &As[wm * 32 + mi * 16 + (lane & 15)][kk + (lane >> 4) * 8]);
                asm volatile("ldmatrix.sync.aligned.m8n8.x4.shared.b16 {%0,%1,%2,%3}, [%4];"
                    : "=r"(a[mi][0]), "=r"(a[mi][1]), "=r"(a[mi][2]), "=r"(a[mi][3])
                    : "r"(addr));
            }
            #pragma unroll
            for (int ni = 0; ni < 4; ++ni) {
                unsigned addr = (unsigned)__cvta_generic_to_shared(
                    &Bs[kk + (lane & 15)][wn * 32 + ni * 8]);
                asm volatile("ldmatrix.sync.aligned.m8n8.x2.trans.shared.b16 {%0,%1}, [%2];"
                    : "=r"(b[ni][0]), "=r"(b[ni][1]) : "r"(addr));
            }
            #pragma unroll
            for (int mi = 0; mi < 2; ++mi)
                #pragma unroll
                for (int ni = 0; ni < 4; ++ni)
                    asm volatile(
                        "mma.sync.aligned.m16n8k16.row.col.f32.f16.f16.f32 "
                        "{%0,%1,%2,%3}, {%4,%5,%6,%7}, {%8,%9}, {%0,%1,%2,%3};"
                        : "+f"(acc[mi][ni][0]), "+f"(acc[mi][ni][1]),
                          "+f"(acc[mi][ni][2]), "+f"(acc[mi][ni][3])
                        : "r"(a[mi][0]), "r"(a[mi][1]), "r"(a[mi][2]), "r"(a[mi][3]),
                          "r"(b[ni][0]), "r"(b[ni][1]));
        }
        __syncthreads();
    }

    int gr = lane >> 2;
    int gc = (lane & 3) * 2;
    #pragma unroll
    for (int mi = 0; mi < 2; ++mi)
        #pragma unroll
        for (int ni = 0; ni < 4; ++ni) {
            int gn = nb * 64 + wn * 32 + ni * 8 + gc;
            float b0 = bf[gn], b1 = bf[gn + 1];
            int m0 = mb * 128 + wm * 32 + mi * 16 + gr;
            *(__half2*)(g_fe16 + (size_t)m0 * HH + gn) =
                __floats2half2_rn(acc[mi][ni][0] + b0, acc[mi][ni][1] + b1);
            int m1 = m0 + 8;
            *(__half2*)(g_fe16 + (size_t)m1 * HH + gn) =
                __floats2half2_rn(acc[mi][ni][2] + b0, acc[mi][ni][3] + b1);
        }
}

// ---------------------------------------------------------------------------
// K2a: init GEMM  mean(64x2048) @ [W_hid | W_cell](2048x512), split-K=8.
// ---------------------------------------------------------------------------
__global__ void __launch_bounds__(256) k_initA(const float* __restrict__ W_hid,
                                               const float* __restrict__ W_cell) {
    __shared__ float As[16][68];
    __shared__ float Bs[16][64];
    int tid = threadIdx.x;
    int nb = blockIdx.x, kc = blockIdx.y;
    const float* wsrc = (nb < 4) ? W_hid : W_cell;
    int ncol0 = (nb & 3) * 64;
    int k0g = kc * 256;
    float acc[4][4] = {};
    int rb = (tid >> 4) * 4, cb = (tid & 15) * 4;

    for (int kt = 0; kt < 256; kt += 16) {
        {
            int r = tid >> 2, kk = (tid & 3) * 4;
            float4 av = *(const float4*)(g_mean + r * EE + k0g + kt + kk);
            As[kk + 0][r] = av.x; As[kk + 1][r] = av.y;
            As[kk + 2][r] = av.z; As[kk + 3][r] = av.w;
        }
        {
            int kk = tid >> 4, n = (tid & 15) * 4;
            *(float4*)&Bs[kk][n] =
                *(const float4*)(wsrc + (size_t)(k0g + kt + kk) * DD + ncol0 + n);
        }
        __syncthreads();
        #pragma unroll
        for (int kk = 0; kk < 16; ++kk) {
            float a[4], bv[4];
            *(float4*)a  = *(float4*)&As[kk][rb];
            *(float4*)bv = *(float4*)&Bs[kk][cb];
            #pragma unroll
            for (int i = 0; i < 4; ++i)
                #pragma unroll
                for (int j = 0; j < 4; ++j) acc[i][j] += a[i] * bv[j];
        }
        __syncthreads();
    }
    #pragma unroll
    for (int i = 0; i < 4; ++i)
        #pragma unroll
        for (int j = 0; j < 4; ++j)
            g_gp[((size_t)kc * NB + rb + i) * 512 + nb * 64 + cb + j] = acc[i][j];
}

__global__ void k_init2(const float* __restrict__ b_hid, const float* __restrict__ b_cell) {
    int b = blockIdx.x, j = threadIdx.x;
    float h = b_hid[j], c = b_cell[j];
    #pragma unroll
    for (int kc = 0; kc < 8; ++kc) {
        const float* p = g_gp + ((size_t)kc * NB + b) * 512;
        h += p[j];
        c += p[256 + j];
    }
    g_h[b * DD + j] = h;
    g_c[b * DD + j] = c;
}

// ===========================================================================
// Persistent step-loop kernel (Round-10 structure exactly; ctx loads cached)
// ===========================================================================
struct SMu {
    union {
        struct { float As[16][68]; float Bs[16][64]; } g;
        struct { float sh[256]; float she[256]; float swe[256]; } a;
        struct { float sw[256]; float red[8]; } c;
    } u;
};

__device__ __forceinline__ void gridbar() {
    __syncthreads();
    __threadfence();
    if (threadIdx.x == 0) {
        int gen = g_bar_gen;
        if (atomicAdd(&g_bar_count, 1) == NBLK - 1) {
            g_bar_count = 0;
            __threadfence();
            g_bar_gen = gen + 1;
        } else {
            while (g_bar_gen == gen) __nanosleep(64);
        }
    }
    __syncthreads();
    __threadfence();
}

__device__ __forceinline__ void dev_score(int b, int half, SMu& sm,
        const float* __restrict__ Wh, const float* __restrict__ bh,
        const float* __restrict__ We, const float* __restrict__ be) {
    int tid = threadIdx.x, lane = tid & 31, wid = tid >> 5;
    sm.u.a.sh[tid]  = g_h[b * DD + tid];
    sm.u.a.swe[tid] = We[tid];
    __syncthreads();
    float acc = bh[tid];
    #pragma unroll 8
    for (int k = 0; k < DD; ++k) acc += sm.u.a.sh[k] * Wh[k * HH + tid];
    sm.u.a.she[tid] = acc;
    __syncthreads();
    float be0 = be[0];
    int p0 = half * 98, p1 = p0 + 98;
    const __half* febase = g_fe16 + (size_t)b * PP * HH;
    for (int p = p0 + wid; p < p1; p += 8) {
        const __half* fr = febase + (size_t)p * HH;
        float s = 0.f;
        #pragma unroll
        for (int it = 0; it < 4; ++it) {
            int j = it * 64 + lane * 2;
            float2 fv = __half22float2(*(const __half2*)(fr + j));
            float v0 = fv.x + sm.u.a.she[j], v1 = fv.y + sm.u.a.she[j + 1];
            s += fmaxf(v0, 0.f) * sm.u.a.swe[j] + fmaxf(v1, 0.f) * sm.u.a.swe[j + 1];
        }
        #pragma unroll
        for (int o = 16; o; o >>= 1) s += __shfl_xor_sync(0xffffffffu, s, o);
        if (lane == 0) g_score[b * PP + p] = s + be0;
    }
}

__device__ __forceinline__ void dev_gpre(int bid, SMu& sm) {
    int tid = threadIdx.x;
    int nb = bid & 31, kc = bid >> 5;
    int kbase = kc * 128;
    float acc[4][4] = {};
    int rb = (tid >> 4) * 4, cb = (tid & 15) * 4;

    for (int kt = 0; kt < 128; kt += 16) {
        {
            int r = tid >> 2, kk = (tid & 3) * 4;
            float4 av = *(const float4*)(g_h + r * DD + kbase + kt + kk);
            sm.u.g.As[kk + 0][r] = av.x; sm.u.g.As[kk + 1][r] = av.y;
            sm.u.g.As[kk + 2][r] = av.z; sm.u.g.As[kk + 3][r] = av.w;
        }
        {
            int kk = tid >> 4, n = (tid & 15) * 4;
            const __half* src = g_Wg16 + (size_t)(kbase + kt + kk) * EE + nb * 64 + n;
            float2 f0 = __half22float2(*(const __half2*)(src));
            float2 f1 = __half22float2(*(const __half2*)(src + 2));
            sm.u.g.Bs[kk][n + 0] = f0.x; sm.u.g.Bs[kk][n + 1] = f0.y;
            sm.u.g.Bs[kk][n + 2] = f1.x; sm.u.g.Bs[kk][n + 3] = f1.y;
        }
        __syncthreads();
        #pragma unroll
        for (int kk = 0; kk < 16; ++kk) {
            float a[4], bv[4];
            *(float4*)a  = *(float4*)&sm.u.g.As[kk][rb];
            *(float4*)bv = *(float4*)&sm.u.g.Bs[kk][cb];
            #pragma unroll
            for (int i = 0; i < 4; ++i)
                #pragma unroll
                for (int j = 0; j < 4; ++j) acc[i][j] += a[i] * bv[j];
        }
        __syncthreads();
    }
    #pragma unroll
    for (int i = 0; i < 4; ++i)
        #pragma unroll
        for (int j = 0; j < 4; ++j)
            g_gatep[((size_t)kc * NB + rb + i) * EE + nb * 64 + cb + j] = acc[i][j];
}

__device__ __forceinline__ void dev_head(int nb, int tprev, SMu& sm,
        const float* __restrict__ b_head, float* __restrict__ out) {
    int tid = threadIdx.x;
    int n0 = nb * 64;
    float acc[4][4] = {};
    int rb = (tid >> 4) * 4, cb = (tid & 15) * 4;

    for (int k0 = 0; k0 < DD; k0 += 16) {
        {
            int r = tid >> 2, kk = (tid & 3) * 4;
            float4 av = *(const float4*)(g_h + r * DD + k0 + kk);
            sm.u.g.As[kk + 0][r] = av.x; sm.u.g.As[kk + 1][r] = av.y;
            sm.u.g.As[kk + 2][r] = av.z; sm.u.g.As[kk + 3][r] = av.w;
        }
        {
            int kk = tid >> 4, n = (tid & 15) * 4;
            int gn = n0 + n;
            const __half* src = g_Whead16 + (size_t)(k0 + kk) * VV + gn;
            float b0, b1, b2, b3;
            if (gn + 3 < VV) {
                float2 f0 = __half22float2(*(const __half2*)(src));
                float2 f1 = __half22float2(*(const __half2*)(src + 2));
                b0 = f0.x; b1 = f0.y; b2 = f1.x; b3 = f1.y;
            } else {
                b0 = (gn + 0 < VV) ? __half2float(src[0]) : 0.f;
                b1 = (gn + 1 < VV) ? __half2float(src[1]) : 0.f;
                b2 = (gn + 2 < VV) ? __half2float(src[2]) : 0.f;
                b3 = (gn + 3 < VV) ? __half2float(src[3]) : 0.f;
            }
            sm.u.g.Bs[kk][n + 0] = b0; sm.u.g.Bs[kk][n + 1] = b1;
            sm.u.g.Bs[kk][n + 2] = b2; sm.u.g.Bs[kk][n + 3] = b3;
        }
        __syncthreads();
        #pragma unroll
        for (int kk = 0; kk < 16; ++kk) {
            float a[4], bv[4];
            *(float4*)a  = *(float4*)&sm.u.g.As[kk][rb];
            *(float4*)bv = *(float4*)&sm.u.g.Bs[kk][cb];
            #pragma unroll
            for (int i = 0; i < 4; ++i)
                #pragma unroll
                for (int j = 0; j < 4; ++j) acc[i][j] += a[i] * bv[j];
        }
        __syncthreads();
    }
    #pragma unroll
    for (int i = 0; i < 4; ++i) {
        int b = rb + i;
        bool msk = (g_target[b] > tprev);
        size_t rowbase = ((size_t)b * TT + tprev) * VV;
        #pragma unroll
        for (int j = 0; j < 4; ++j) {
            int gn = n0 + cb + j;
            if (gn < VV) out[rowbase + gn] = msk ? (acc[i][j] + b_head[gn]) : 0.f;
        }
    }
}

__device__ __forceinline__ void dev_ctx(int b, int half, int t, int nact, SMu& sm,
        const float* __restrict__ b_gate, const float* __restrict__ emb,
        const int* __restrict__ tok, float* __restrict__ out_att) {
    int tid = threadIdx.x, lane = tid & 31, wid = tid >> 5;

    if (b >= nact) {
        if (half == 0 && tid < PP)
            out_att[((size_t)b * TT + t) * PP + tid] = 0.f;
        return;
    }

    float v = (tid < PP) ? g_score[b * PP + tid] : -3.4e38f;
    float m = v;
    #pragma unroll
    for (int o = 16; o; o >>= 1) m = fmaxf(m, __shfl_xor_sync(0xffffffffu, m, o));
    if (lane == 0) sm.u.c.red[wid] = m;
    __syncthreads();
    if (tid == 0) {
        float mm = sm.u.c.red[0];
        #pragma unroll
        for (int i = 1; i < 8; ++i) mm = fmaxf(mm, sm.u.c.red[i]);
        sm.u.c.red[0] = mm;
    }
    __syncthreads();
    float mx = sm.u.c.red[0];
    __syncthreads();

    float e = (tid < PP) ? expf(v - mx) : 0.f;
    float s = e;
    #pragma unroll
    for (int o = 16; o; o >>= 1) s += __shfl_xor_sync(0xffffffffu, s, o);
    if (lane == 0) sm.u.c.red[wid] = s;
    __syncthreads();
    if (tid == 0) {
        float ss = 0.f;
        #pragma unroll
        for (int i = 0; i < 8; ++i) ss += sm.u.c.red[i];
        sm.u.c.red[0] = ss;
    }
    __syncthreads();
    float inv = 1.0f / sm.u.c.red[0];
    if (tid < PP) sm.u.c.sw[tid] = e * inv;
    __syncthreads();

    if (half == 0) {
        if (tid < PP)
            out_att[((size_t)b * TT + t) * PP + tid] = sm.u.c.sw[tid];
        int token = tok[g_order[b] * LL + t];
        g_x[b * XK + tid] = emb[(size_t)token * EMB + tid];
        g_x[b * XK + EMB + EE + tid] = g_h[b * DD + tid];
    }

    // feat16 fits in L2 alongside everything else -> use NORMAL cached loads
    int e0i = half * 1024 + tid * 4;
    const __half* fb = g_feat16 + (size_t)b * PP * EE + e0i;

    float4 s0 = make_float4(0.f, 0.f, 0.f, 0.f);
    float4 s1 = make_float4(0.f, 0.f, 0.f, 0.f);
    float4 s2 = make_float4(0.f, 0.f, 0.f, 0.f);
    float4 s3 = make_float4(0.f, 0.f, 0.f, 0.f);
    for (int p = 0; p < PP; p += 4) {
        float w0 = sm.u.c.sw[p], w1 = sm.u.c.sw[p + 1];
        float w2 = sm.u.c.sw[p + 2], w3 = sm.u.c.sw[p + 3];
        uint2 r0 = *(const uint2*)(fb + (size_t)(p + 0) * EE);
        uint2 r1 = *(const uint2*)(fb + (size_t)(p + 1) * EE);
        uint2 r2 = *(const uint2*)(fb + (size_t)(p + 2) * EE);
        uint2 r3 = *(const uint2*)(fb + (size_t)(p + 3) * EE);
        float2 a0 = __half22float2(*reinterpret_cast<__half2*>(&r0.x));
        float2 c0 = __half22float2(*reinterpret_cast<__half2*>(&r0.y));
        float2 a1 = __half22float2(*reinterpret_cast<__half2*>(&r1.x));
        float2 c1 = __half22float2(*reinterpret_cast<__half2*>(&r1.y));
        float2 a2 = __half22float2(*reinterpret_cast<__half2*>(&r2.x));
        float2 c2 = __half22float2(*reinterpret_cast<__half2*>(&r2.y));
        float2 a3 = __half22float2(*reinterpret_cast<__half2*>(&r3.x));
        float2 c3 = __half22float2(*reinterpret_cast<__half2*>(&r3.y));
        s0.x += w0 * a0.x; s0.y += w0 * a0.y; s0.z += w0 * c0.x; s0.w += w0 * c0.y;
        s1.x += w1 * a1.x; s1.y += w1 * a1.y; s1.z += w1 * c1.x; s1.w += w1 * c1.y;
        s2.x += w2 * a2.x; s2.y += w2 * a2.y; s2.z += w2 * c2.x; s2.w += w2 * c2.y;
        s3.x += w3 * a3.x; s3.y += w3 * a3.y; s3.z += w3 * c3.x; s3.w += w3 * c3.y;
    }
    float4 sum;
    sum.x = (s0.x + s1.x) + (s2.x + s3.x);
    sum.y = (s0.y + s1.y) + (s2.y + s3.y);
    sum.z = (s0.z + s1.z) + (s2.z + s3.z);
    sum.w = (s0.w + s1.w) + (s2.w + s3.w);

    float4 gp0 = *(const float4*)(g_gatep + (size_t)b * EE + e0i);
    float4 gp1 = *(const float4*)(g_gatep + ((size_t)NB + b) * EE + e0i);
    float4 bg  = *(const float4*)(b_gate + e0i);
    float4 ctx;
    ctx.x = sum.x * sigf(bg.x + gp0.x + gp1.x);
    ctx.y = sum.y * sigf(bg.y + gp0.y + gp1.y);
    ctx.z = sum.z * sigf(bg.z + gp0.z + gp1.z);
    ctx.w = sum.w * sigf(bg.w + gp0.w + gp1.w);
    *(float4*)(g_x + (size_t)b * XK + EMB + e0i) = ctx;
}

__device__ __forceinline__ void dev_gates(int nb, int kc, SMu& sm) {
    int tid = threadIdx.x;
    int k0g = kc * 256;
    const __half* wbase = g_Wih16 + (size_t)k0g * G4;
    float acc[4][4] = {};
    int rb = (tid >> 4) * 4, cb = (tid & 15) * 4;

    for (int kt = 0; kt < 256; kt += 16) {
        {
            int r = tid >> 2, kk = (tid & 3) * 4;
            float4 av = *(const float4*)(g_x + r * XK + k0g + kt + kk);
            sm.u.g.As[kk + 0][r] = av.x; sm.u.g.As[kk + 1][r] = av.y;
            sm.u.g.As[kk + 2][r] = av.z; sm.u.g.As[kk + 3][r] = av.w;
        }
        {
            int kk = tid >> 4, n = (tid & 15) * 4;
            const __half* src = wbase + (size_t)(kt + kk) * G4 + nb * 64 + n;
            float2 f0 = __half22float2(*(const __half2*)(src));
            float2 f1 = __half22float2(*(const __half2*)(src + 2));
            sm.u.g.Bs[kk][n + 0] = f0.x; sm.u.g.Bs[kk][n + 1] = f0.y;
            sm.u.g.Bs[kk][n + 2] = f1.x; sm.u.g.Bs[kk][n + 3] = f1.y;
        }
        __syncthreads();
        #pragma unroll
        for (int kk = 0; kk < 16; ++kk) {
            float a[4], bv[4];
            *(float4*)a  = *(float4*)&sm.u.g.As[kk][rb];
            *(float4*)bv = *(float4*)&sm.u.g.Bs[kk][cb];
            #pragma unroll
            for (int i = 0; i < 4; ++i)
                #pragma unroll
                for (int j = 0; j < 4; ++j) acc[i][j] += a[i] * bv[j];
        }
        __syncthreads();
    }
    #pragma unroll
    for (int i = 0; i < 4; ++i)
        #pragma unroll
        for (int j = 0; j < 4; ++j)
            g_gp[((size_t)kc * NB + rb + i) * G4 + nb * 64 + cb + j] = acc[i][j];
}

__device__ __forceinline__ void dev_lstm(int b, int t,
        const float* __restrict__ b_ih, const float* __restrict__ b_hh) {
    int j = threadIdx.x;
    float gi = b_ih[j] + b_hh[j];
    float gf = b_ih[DD + j] + b_hh[DD + j];
    float gg = b_ih[2 * DD + j] + b_hh[2 * DD + j];
    float go = b_ih[3 * DD + j] + b_hh[3 * DD + j];
    #pragma unroll
    for (int kc = 0; kc < KC; ++kc) {
        const float* p = g_gp + ((size_t)kc * NB + b) * G4;
        gi += p[j];
        gf += p[DD + j];
        gg += p[2 * DD + j];
        go += p[3 * DD + j];
    }
    float c = g_c[b * DD + j];
    float cn = sigf(gf) * c + sigf(gi) * tanhf(gg);
    float hn = sigf(go) * tanhf(cn);
    if (g_target[b] > t) {
        g_h[b * DD + j] = hn;
        g_c[b * DD + j] = cn;
    }
}

__global__ void __launch_bounds__(256, 2) k_loop(
        const float* __restrict__ Wh, const float* __restrict__ bh,
        const float* __restrict__ We, const float* __restrict__ be,
        const float* __restrict__ b_gate, const float* __restrict__ emb,
        const int* __restrict__ tok,
        const float* __restrict__ b_ih, const float* __restrict__ b_hh,
        const float* __restrict__ b_head,
        float* __restrict__ out, float* __restrict__ out_att) {
    __shared__ SMu sm;
    for (int t = 0; t < TT; ++t) {
        int nact = g_nact[t];
        // Phase A: scores(t) 128 + gpre(t) 64 + head(t-1) nb[0,64) = 256 units
        int nA = 192 + (t >= 1 ? 64 : 0);
        for (int u = blockIdx.x; u < nA; u += NBLK) {
            __syncthreads();
            if (u < 128) {
                if ((u >> 1) < nact) dev_score(u >> 1, u & 1, sm, Wh, bh, We, be);
            }
            else if (u < 192) dev_gpre(u - 128, sm);
            else              dev_head(u - 192, t - 1, sm, b_head, out);
        }
        gridbar();
        // Phase B: ctx 128 + head(t-1) nb[64,157) = 221 units
        int nB = 128 + (t >= 1 ? 93 : 0);
        for (int u = blockIdx.x; u < nB; u += NBLK) {
            __syncthreads();
            if (u < 128) dev_ctx(u >> 1, u & 1, t, nact, sm, b_gate, emb, tok, out_att);
            else         dev_head(64 + (u - 128), t - 1, sm, b_head, out);
        }
        gridbar();
        // Phase C: gates split-K GEMM (160 units)
        for (int u = blockIdx.x; u < 160; u += NBLK) {
            __syncthreads();
            dev_gates(u & 15, u >> 4, sm);
        }
        gridbar();
        // Phase D: LSTM pointwise (64 units)
        if (blockIdx.x < NB) dev_lstm(blockIdx.x, t, b_ih, b_hh);
        gridbar();
    }
    // Tail: head for the final step (t = TT-1)
    for (int u = blockIdx.x; u < 157; u += NBLK) {
        __syncthreads();
        dev_head(u, TT - 1, sm, b_head, out);
    }
}

// ---------------------------------------------------------------------------
extern "C" void kernel_launch(void* const* d_in, const int* in_sizes, int n_in,
                              void* d_out, int out_size) {
    const float* feat   = (const float*)d_in[0];
    const int*   tok    = (const int*)d_in[1];
    const int*   caplen = (const int*)d_in[2];
    const float* Wf     = (const float*)d_in[3];
    const float* bf     = (const float*)d_in[4];
    const float* Wh     = (const float*)d_in[5];
    const float* bh     = (const float*)d_in[6];
    const float* We     = (const float*)d_in[7];
    const float* be     = (const float*)d_in[8];
    const float* emb    = (const float*)d_in[9];
    const float* W_ih   = (const float*)d_in[10];
    const float* b_ih   = (const float*)d_in[11];
    const float* W_hh   = (const float*)d_in[12];
    const float* b_hh   = (const float*)d_in[13];
    const float* W_hid  = (const float*)d_in[14];
    const float* b_hid  = (const float*)d_in[15];
    const float* W_cell = (const float*)d_in[16];
    const float* b_cell = (const float*)d_in[17];
    const float* W_gate = (const float*)d_in[18];
    const float* b_gate = (const float*)d_in[19];
    const float* W_head = (const float*)d_in[20];
    const float* b_head = (const float*)d_in[21];

    float* out = (float*)d_out;
    float* out_att = out + (size_t)NB * TT * VV;

    k_order<<<1, 32>>>(caplen);
    k_cvt<<<512, 256>>>(W_gate, W_ih, W_hh, W_head, Wf);
    k_cvtf<<<NB * PP, 256>>>(feat);
    k_fe<<<dim3(98, 5), 256>>>(feat, bf);         // fe HGEMM (tensor cores) + mean
    k_initA<<<dim3(8, 8), 256>>>(W_hid, W_cell);  // init GEMM, split-K
    k_init2<<<NB, 256>>>(b_hid, b_cell);

    // entire 31-step decoder loop in ONE persistent kernel
    k_loop<<<NBLK, 256>>>(Wh, bh, We, be, b_gate, emb, tok,
                          b_ih, b_hh, b_head, out, out_att);
}

// round 14
// speedup vs baseline: 1.7650x; 1.4078x over previous
#include <cuda_runtime.h>
#include <cuda_fp16.h>
#include <cstdint>

static constexpr int NB  = 64;     // batch
static constexpr int PP  = 196;    // spatial positions
static constexpr int EE  = 2048;   // feature dim
static constexpr int DD  = 256;    // hidden
static constexpr int HH  = 256;    // attention hidden
static constexpr int EMB = 256;    // embedding
static constexpr int VV  = 10000;  // vocab
static constexpr int LL  = 32;     // caption length
static constexpr int TT  = 31;     // timesteps
static constexpr int XK  = EMB + EE + DD;  // 2560
static constexpr int G4  = 4 * DD;         // 1024
static constexpr int KC  = 10;             // split-K chunks for gates gemm
static constexpr int NBLK = 256;           // persistent grid size

__device__ int    g_order[NB];
__device__ int    g_target[NB];
__device__ int    g_nact[TT + 1];
__device__ __half g_feat16[NB * PP * EE];   // 51.4 MB fp16 feat, order-permuted
__device__ __half g_fe16[NB * PP * HH];     // 6.4 MB fp16 attention features
__device__ float  g_mean[NB * EE];
__device__ float  g_h[NB * DD];
__device__ float  g_c[NB * DD];
__device__ float  g_score[NB * PP];
__device__ float  g_x[NB * XK];
__device__ float  g_gp[KC * NB * G4];
__device__ float  g_gatep[2 * NB * EE];
__device__ __half g_Wg16[DD * EE];
__device__ __half g_Wih16[XK * G4];
__device__ __half g_Whead16[DD * VV];
__device__ __half g_Wf16[EE * HH];

__device__ int          g_bar_count;
__device__ volatile int g_bar_gen;

__device__ __forceinline__ float sigf(float x) { return 1.0f / (1.0f + expf(-x)); }

// ---------------------------------------------------------------------------
__global__ void k_order(const int* __restrict__ caplen) {
    if (threadIdx.x == 0) {
        int idx = 0;
        for (int v = LL; v >= 1; --v) {
            for (int i = 0; i < NB; ++i) {
                if (caplen[i] == v) {
                    g_order[idx]  = i;
                    g_target[idx] = v - 1;
                    ++idx;
                }
            }
        }
        for (int t = 0; t <= TT; ++t) {
            int n = 0;
            for (int i = 0; i < NB; ++i) n += (g_target[i] > t) ? 1 : 0;
            g_nact[t] = n;
        }
    }
}

// ---------------------------------------------------------------------------
__global__ void k_cvt(const float* __restrict__ Wg, const float* __restrict__ Wih,
                      const float* __restrict__ Whh, const float* __restrict__ Whead,
                      const float* __restrict__ Wf) {
    const int NQ_G  = (DD * EE) / 4;
    const int NQ_IH = (2304 * G4) / 4;
    const int NQ_HH = (DD * G4) / 4;
    const int NQ_HD = (DD * VV) / 4;
    const int NQ_WF = (EE * HH) / 4;
    const int total = NQ_G + NQ_IH + NQ_HH + NQ_HD + NQ_WF;
    for (int i = blockIdx.x * blockDim.x + threadIdx.x; i < total;
         i += gridDim.x * blockDim.x) {
        const float* src; __half* dst; int q;
        if (i < NQ_G)                          { src = Wg;    dst = g_Wg16;              q = i; }
        else if (i < NQ_G + NQ_IH)             { src = Wih;   dst = g_Wih16;             q = i - NQ_G; }
        else if (i < NQ_G + NQ_IH + NQ_HH)     { src = Whh;  dst = g_Wih16 + 2304 * G4;  q = i - NQ_G - NQ_IH; }
        else if (i < NQ_G + NQ_IH + NQ_HH + NQ_HD) { src = Whead; dst = g_Whead16;       q = i - NQ_G - NQ_IH - NQ_HH; }
        else                                   { src = Wf;    dst = g_Wf16;              q = i - NQ_G - NQ_IH - NQ_HH - NQ_HD; }
        float4 v = *(const float4*)(src + (size_t)q * 4);
        *(__half2*)(dst + (size_t)q * 4)     = __floats2half2_rn(v.x, v.y);
        *(__half2*)(dst + (size_t)q * 4 + 2) = __floats2half2_rn(v.z, v.w);
    }
}

// ---------------------------------------------------------------------------
__global__ void __launch_bounds__(256) k_cvtf(const float* __restrict__ feat) {
    int row = blockIdx.x;
    int b = row / PP, p = row % PP;
    const float* src = feat + ((size_t)g_order[b] * PP + p) * EE + threadIdx.x * 8;
    __half* dst = g_feat16 + (size_t)row * EE + threadIdx.x * 8;
    float4 v0 = *(const float4*)(src);
    float4 v1 = *(const float4*)(src + 4);
    *(__half2*)(dst + 0) = __floats2half2_rn(v0.x, v0.y);
    *(__half2*)(dst + 2) = __floats2half2_rn(v0.z, v0.w);
    *(__half2*)(dst + 4) = __floats2half2_rn(v1.x, v1.y);
    *(__half2*)(dst + 6) = __floats2half2_rn(v1.z, v1.w);
}

// ---------------------------------------------------------------------------
// K3: grid (98, 5): fe HGEMM via mma.sync + mean (y==4)
// ---------------------------------------------------------------------------
__global__ void __launch_bounds__(256) k_fe(const float* __restrict__ feat,
                                            const float* __restrict__ bf) {
    int tid = threadIdx.x;
    int mb = blockIdx.x, nb = blockIdx.y;

    if (nb == 4) {
        if (mb >= NB) return;
        int b = mb;
        const float4* base = (const float4*)(feat + (size_t)g_order[b] * PP * EE);
        float4 sA = make_float4(0.f, 0.f, 0.f, 0.f);
        float4 sB = make_float4(0.f, 0.f, 0.f, 0.f);
        #pragma unroll 2
        for (int p = 0; p < PP; ++p) {
            float4 v0 = __ldcs(base + (size_t)p * (EE / 4) + tid);
            float4 v1 = __ldcs(base + (size_t)p * (EE / 4) + tid + 256);
            sA.x += v0.x; sA.y += v0.y; sA.z += v0.z; sA.w += v0.w;
            sB.x += v1.x; sB.y += v1.y; sB.z += v1.z; sB.w += v1.w;
        }
        const float inv = 1.0f / PP;
        sA.x *= inv; sA.y *= inv; sA.z *= inv; sA.w *= inv;
        sB.x *= inv; sB.y *= inv; sB.z *= inv; sB.w *= inv;
        *(float4*)(g_mean + b * EE + tid * 4)        = sA;
        *(float4*)(g_mean + b * EE + 1024 + tid * 4) = sB;
        return;
    }

    __shared__ __half As[128][72];
    __shared__ __half Bs[64][72];

    int warp = tid >> 5, lane = tid & 31;
    int wm = warp & 3, wn = warp >> 2;

    float acc[2][4][4] = {};

    for (int k0 = 0; k0 < EE; k0 += 64) {
        #pragma unroll
        for (int i = 0; i < 4; ++i) {
            int idx = tid + i * 256;
            int r = idx >> 3, c = (idx & 7) * 8;
            *(uint4*)&As[r][c] =
                *(const uint4*)(g_feat16 + (size_t)(mb * 128 + r) * EE + k0 + c);
        }
        #pragma unroll
        for (int i = 0; i < 2; ++i) {
            int idx = tid + i * 256;
            int r = idx >> 3, c = (idx & 7) * 8;
            *(uint4*)&Bs[r][c] =
                *(const uint4*)(g_Wf16 + (size_t)(k0 + r) * HH + nb * 64 + c);
        }
        __syncthreads();

        #pragma unroll
        for (int kk = 0; kk < 64; kk += 16) {
            unsigned a[2][4], b[4][2];
            #pragma unroll
            for (int mi = 0; mi < 2; ++mi) {
                unsigned addr = (unsigned)__cvta_generic_to_shared(
                    &As[wm * 32 + mi * 16 + (lane & 15)][kk + (lane >> 4) * 8]);
                asm volatile("ldmatrix.sync.aligned.m8n8.x4.shared.b16 {%0,%1,%2,%3}, [%4];"
                    : "=r"(a[mi][0]), "=r"(a[mi][1]), "=r"(a[mi][2]), "=r"(a[mi][3])
                    : "r"(addr));
            }
            #pragma unroll
            for (int ni = 0; ni < 4; ++ni) {
                unsigned addr = (unsigned)__cvta_generic_to_shared(
                    &Bs[kk + (lane & 15)][wn * 32 + ni * 8]);
                asm volatile("ldmatrix.sync.aligned.m8n8.x2.trans.shared.b16 {%0,%1}, [%2];"
                    : "=r"(b[ni][0]), "=r"(b[ni][1]) : "r"(addr));
            }
            #pragma unroll
            for (int mi = 0; mi < 2; ++mi)
                #pragma unroll
                for (int ni = 0; ni < 4; ++ni)
                    asm volatile(
                        "mma.sync.aligned.m16n8k16.row.col.f32.f16.f16.f32 "
                        "{%0,%1,%2,%3}, {%4,%5,%6,%7}, {%8,%9}, {%0,%1,%2,%3};"
                        : "+f"(acc[mi][ni][0]), "+f"(acc[mi][ni][1]),
                          "+f"(acc[mi][ni][2]), "+f"(acc[mi][ni][3])
                        : "r"(a[mi][0]), "r"(a[mi][1]), "r"(a[mi][2]), "r"(a[mi][3]),
                          "r"(b[ni][0]), "r"(b[ni][1]));
        }
        __syncthreads();
    }

    int gr = lane >> 2;
    int gc = (lane & 3) * 2;
    #pragma unroll
    for (int mi = 0; mi < 2; ++mi)
        #pragma unroll
        for (int ni = 0; ni < 4; ++ni) {
            int gn = nb * 64 + wn * 32 + ni * 8 + gc;
            float b0 = bf[gn], b1 = bf[gn + 1];
            int m0 = mb * 128 + wm * 32 + mi * 16 + gr;
            *(__half2*)(g_fe16 + (size_t)m0 * HH + gn) =
                __floats2half2_rn(acc[mi][ni][0] + b0, acc[mi][ni][1] + b1);
            int m1 = m0 + 8;
            *(__half2*)(g_fe16 + (size_t)m1 * HH + gn) =
                __floats2half2_rn(acc[mi][ni][2] + b0, acc[mi][ni][3] + b1);
        }
}

// ---------------------------------------------------------------------------
// K2a/K2b: init GEMM + reduce (prologue, unchanged)
// ---------------------------------------------------------------------------
__global__ void __launch_bounds__(256) k_initA(const float* __restrict__ W_hid,
                                               const float* __restrict__ W_cell) {
    __shared__ float As[16][68];
    __shared__ float Bs[16][64];
    int tid = threadIdx.x;
    int nb = blockIdx.x, kc = blockIdx.y;
    const float* wsrc = (nb < 4) ? W_hid : W_cell;
    int ncol0 = (nb & 3) * 64;
    int k0g = kc * 256;
    float acc[4][4] = {};
    int rb = (tid >> 4) * 4, cb = (tid & 15) * 4;

    for (int kt = 0; kt < 256; kt += 16) {
        {
            int r = tid >> 2, kk = (tid & 3) * 4;
            float4 av = *(const float4*)(g_mean + r * EE + k0g + kt + kk);
            As[kk + 0][r] = av.x; As[kk + 1][r] = av.y;
            As[kk + 2][r] = av.z; As[kk + 3][r] = av.w;
        }
        {
            int kk = tid >> 4, n = (tid & 15) * 4;
            *(float4*)&Bs[kk][n] =
                *(const float4*)(wsrc + (size_t)(k0g + kt + kk) * DD + ncol0 + n);
        }
        __syncthreads();
        #pragma unroll
        for (int kk = 0; kk < 16; ++kk) {
            float a[4], bv[4];
            *(float4*)a  = *(float4*)&As[kk][rb];
            *(float4*)bv = *(float4*)&Bs[kk][cb];
            #pragma unroll
            for (int i = 0; i < 4; ++i)
                #pragma unroll
                for (int j = 0; j < 4; ++j) acc[i][j] += a[i] * bv[j];
        }
        __syncthreads();
    }
    #pragma unroll
    for (int i = 0; i < 4; ++i)
        #pragma unroll
        for (int j = 0; j < 4; ++j)
            g_gp[((size_t)kc * NB + rb + i) * 512 + nb * 64 + cb + j] = acc[i][j];
}

__global__ void k_init2(const float* __restrict__ b_hid, const float* __restrict__ b_cell) {
    int b = blockIdx.x, j = threadIdx.x;
    float h = b_hid[j], c = b_cell[j];
    #pragma unroll
    for (int kc = 0; kc < 8; ++kc) {
        const float* p = g_gp + ((size_t)kc * NB + b) * 512;
        h += p[j];
        c += p[256 + j];
    }
    g_h[b * DD + j] = h;
    g_c[b * DD + j] = c;
}

// ===========================================================================
// Persistent step-loop kernel
// ===========================================================================
struct SMu {
    union {
        struct { __half As[64][72]; __half Bs[64][72]; } m;   // TC tiles
        struct { float sh[256]; float she[256]; float swe[256]; } a;
        struct { float sw[256]; float red[8]; } c;
    } u;
};

__device__ __forceinline__ void gridbar() {
    __syncthreads();
    __threadfence();
    if (threadIdx.x == 0) {
        int gen = g_bar_gen;
        if (atomicAdd(&g_bar_count, 1) == NBLK - 1) {
            g_bar_count = 0;
            __threadfence();
            g_bar_gen = gen + 1;
        } else {
            while (g_bar_gen == gen) __nanosleep(64);
        }
    }
    __syncthreads();
    __threadfence();
}

// ---------------------------------------------------------------------------
// Shared tensor-core 64x64 tile GEMM: C(64x64) += A(64xK, fp32) @ B(Kx64, fp16)
// A converted fp32->fp16 on the fly into smem; fp32 accumulation.
// nvalid: number of valid B columns in this tile (<=64, for head tail tile).
// Caller epilogues from acc[ni][4] with the standard mma fragment layout.
// ---------------------------------------------------------------------------
__device__ __forceinline__ void mma64(const float* __restrict__ Ag, int lda,
        const __half* __restrict__ Bg, int ldb, int K, int nvalid,
        SMu& sm, float acc[4][4]) {
    int tid = threadIdx.x, lane = tid & 31, warp = tid >> 5;
    int wm = warp & 3, wn = warp >> 2;   // 4 m-tiles of 16, 2 n-tiles of 32

    for (int k0 = 0; k0 < K; k0 += 64) {
        // A: 64 rows x 64 cols fp32 -> fp16 smem (each thread: 16 elems of 1 row)
        {
            int r = tid >> 2, c0 = (tid & 3) * 16;
            const float* src = Ag + (size_t)r * lda + k0 + c0;
            float4 v0 = *(const float4*)(src);
            float4 v1 = *(const float4*)(src + 4);
            float4 v2 = *(const float4*)(src + 8);
            float4 v3 = *(const float4*)(src + 12);
            __half* d = &sm.u.m.As[r][c0];
            *(__half2*)(d + 0)  = __floats2half2_rn(v0.x, v0.y);
            *(__half2*)(d + 2)  = __floats2half2_rn(v0.z, v0.w);
            *(__half2*)(d + 4)  = __floats2half2_rn(v1.x, v1.y);
            *(__half2*)(d + 6)  = __floats2half2_rn(v1.z, v1.w);
            *(__half2*)(d + 8)  = __floats2half2_rn(v2.x, v2.y);
            *(__half2*)(d + 10) = __floats2half2_rn(v2.z, v2.w);
            *(__half2*)(d + 12) = __floats2half2_rn(v3.x, v3.y);
            *(__half2*)(d + 14) = __floats2half2_rn(v3.z, v3.w);
        }
        // B: 64 rows x 64 cols fp16 (2 uint4 per thread), tail-guarded
        #pragma unroll
        for (int i = 0; i < 2; ++i) {
            int idx = tid + i * 256;
            int r = idx >> 3, c = (idx & 7) * 8;
            uint4 val;
            if (c + 8 <= nvalid) {
                val = *(const uint4*)(Bg + (size_t)(k0 + r) * ldb + c);
            } else {
                __half tmp[8];
                #pragma unroll
                for (int j = 0; j < 8; ++j)
                    tmp[j] = (c + j < nvalid) ? Bg[(size_t)(k0 + r) * ldb + c + j]
                                              : __float2half(0.f);
                val = *(uint4*)tmp;
            }
            *(uint4*)&sm.u.m.Bs[r][c] = val;
        }
        __syncthreads();

        #pragma unroll
        for (int kk = 0; kk < 64; kk += 16) {
            unsigned a[4], b[4][2];
            {
                unsigned addr = (unsigned)__cvta_generic_to_shared(
                    &sm.u.m.As[wm * 16 + (lane & 15)][kk + (lane >> 4) * 8]);
                asm volatile("ldmatrix.sync.aligned.m8n8.x4.shared.b16 {%0,%1,%2,%3}, [%4];"
                    : "=r"(a[0]), "=r"(a[1]), "=r"(a[2]), "=r"(a[3]) : "r"(addr));
            }
            #pragma unroll
            for (int ni = 0; ni < 4; ++ni) {
                unsigned addr = (unsigned)__cvta_generic_to_shared(
                    &sm.u.m.Bs[kk + (lane & 15)][wn * 32 + ni * 8]);
                asm volatile("ldmatrix.sync.aligned.m8n8.x2.trans.shared.b16 {%0,%1}, [%2];"
                    : "=r"(b[ni][0]), "=r"(b[ni][1]) : "r"(addr));
            }
            #pragma unroll
            for (int ni = 0; ni < 4; ++ni)
                asm volatile(
                    "mma.sync.aligned.m16n8k16.row.col.f32.f16.f16.f32 "
                    "{%0,%1,%2,%3}, {%4,%5,%6,%7}, {%8,%9}, {%0,%1,%2,%3};"
                    : "+f"(acc[ni][0]), "+f"(acc[ni][1]),
                      "+f"(acc[ni][2]), "+f"(acc[ni][3])
                    : "r"(a[0]), "r"(a[1]), "r"(a[2]), "r"(a[3]),
                      "r"(b[ni][0]), "r"(b[ni][1]));
        }
        __syncthreads();
    }
}

__device__ __forceinline__ void dev_score(int b, int half, SMu& sm,
        const float* __restrict__ Wh, const float* __restrict__ bh,
        const float* __restrict__ We, const float* __restrict__ be) {
    int tid = threadIdx.x, lane = tid & 31, wid = tid >> 5;
    sm.u.a.sh[tid]  = g_h[b * DD + tid];
    sm.u.a.swe[tid] = We[tid];
    __syncthreads();
    float acc = bh[tid];
    #pragma unroll 8
    for (int k = 0; k < DD; ++k) acc += sm.u.a.sh[k] * Wh[k * HH + tid];
    sm.u.a.she[tid] = acc;
    __syncthreads();
    float be0 = be[0];
    int p0 = half * 98, p1 = p0 + 98;
    const __half* febase = g_fe16 + (size_t)b * PP * HH;
    for (int p = p0 + wid; p < p1; p += 8) {
        const __half* fr = febase + (size_t)p * HH;
        float s = 0.f;
        #pragma unroll
        for (int it = 0; it < 4; ++it) {
            int j = it * 64 + lane * 2;
            float2 fv = __half22float2(*(const __half2*)(fr + j));
            float v0 = fv.x + sm.u.a.she[j], v1 = fv.y + sm.u.a.she[j + 1];
            s += fmaxf(v0, 0.f) * sm.u.a.swe[j] + fmaxf(v1, 0.f) * sm.u.a.swe[j + 1];
        }
        #pragma unroll
        for (int o = 16; o; o >>= 1) s += __shfl_xor_sync(0xffffffffu, s, o);
        if (lane == 0) g_score[b * PP + p] = s + be0;
    }
}

// gpre unit: h @ W_gate16 chunk -> g_gatep partials  (TC)
__device__ __forceinline__ void dev_gpre(int bid, SMu& sm) {
    int nb = bid & 31, kc = bid >> 5;
    int kbase = kc * 128;
    float acc[4][4] = {};
    mma64(g_h + kbase, DD, g_Wg16 + (size_t)kbase * EE + nb * 64, EE, 128, 64, sm, acc);

    int lane = threadIdx.x & 31, warp = threadIdx.x >> 5;
    int wm = warp & 3, wn = warp >> 2;
    int gr = lane >> 2, gc = (lane & 3) * 2;
    #pragma unroll
    for (int ni = 0; ni < 4; ++ni) {
        int col = nb * 64 + wn * 32 + ni * 8 + gc;
        int r0 = wm * 16 + gr;
        g_gatep[((size_t)kc * NB + r0) * EE + col]         = acc[ni][0];
        g_gatep[((size_t)kc * NB + r0) * EE + col + 1]     = acc[ni][1];
        g_gatep[((size_t)kc * NB + r0 + 8) * EE + col]     = acc[ni][2];
        g_gatep[((size_t)kc * NB + r0 + 8) * EE + col + 1] = acc[ni][3];
    }
}

// head unit: h @ W_head16 tile -> out (masked, bias)  (TC)
__device__ __forceinline__ void dev_head(int nb, int tprev, SMu& sm,
        const float* __restrict__ b_head, float* __restrict__ out) {
    int n0 = nb * 64;
    int nvalid = (VV - n0 < 64) ? (VV - n0) : 64;
    float acc[4][4] = {};
    mma64(g_h, DD, g_Whead16 + n0, VV, DD, nvalid, sm, acc);

    int lane = threadIdx.x & 31, warp = threadIdx.x >> 5;
    int wm = warp & 3, wn = warp >> 2;
    int gr = lane >> 2, gc = (lane & 3) * 2;
    #pragma unroll
    for (int ni = 0; ni < 4; ++ni) {
        int gn = n0 + wn * 32 + ni * 8 + gc;
        #pragma unroll
        for (int half = 0; half < 2; ++half) {
            int b = wm * 16 + gr + half * 8;
            bool msk = (g_target[b] > tprev);
            size_t rowbase = ((size_t)b * TT + tprev) * VV;
            if (gn < VV)
                out[rowbase + gn] = msk ? (acc[ni][2 * half] + b_head[gn]) : 0.f;
            if (gn + 1 < VV)
                out[rowbase + gn + 1] = msk ? (acc[ni][2 * half + 1] + b_head[gn + 1]) : 0.f;
        }
    }
}

__device__ __forceinline__ void dev_ctx(int b, int half, int t, int nact, SMu& sm,
        const float* __restrict__ b_gate, const float* __restrict__ emb,
        const int* __restrict__ tok, float* __restrict__ out_att) {
    int tid = threadIdx.x, lane = tid & 31, wid = tid >> 5;

    if (b >= nact) {
        if (half == 0 && tid < PP)
            out_att[((size_t)b * TT + t) * PP + tid] = 0.f;
        return;
    }

    float v = (tid < PP) ? g_score[b * PP + tid] : -3.4e38f;
    float m = v;
    #pragma unroll
    for (int o = 16; o; o >>= 1) m = fmaxf(m, __shfl_xor_sync(0xffffffffu, m, o));
    if (lane == 0) sm.u.c.red[wid] = m;
    __syncthreads();
    if (tid == 0) {
        float mm = sm.u.c.red[0];
        #pragma unroll
        for (int i = 1; i < 8; ++i) mm = fmaxf(mm, sm.u.c.red[i]);
        sm.u.c.red[0] = mm;
    }
    __syncthreads();
    float mx = sm.u.c.red[0];
    __syncthreads();

    float e = (tid < PP) ? expf(v - mx) : 0.f;
    float s = e;
    #pragma unroll
    for (int o = 16; o; o >>= 1) s += __shfl_xor_sync(0xffffffffu, s, o);
    if (lane == 0) sm.u.c.red[wid] = s;
    __syncthreads();
    if (tid == 0) {
        float ss = 0.f;
        #pragma unroll
        for (int i = 0; i < 8; ++i) ss += sm.u.c.red[i];
        sm.u.c.red[0] = ss;
    }
    __syncthreads();
    float inv = 1.0f / sm.u.c.red[0];
    if (tid < PP) sm.u.c.sw[tid] = e * inv;
    __syncthreads();

    if (half == 0) {
        if (tid < PP)
            out_att[((size_t)b * TT + t) * PP + tid] = sm.u.c.sw[tid];
        int token = tok[g_order[b] * LL + t];
        g_x[b * XK + tid] = emb[(size_t)token * EMB + tid];
        g_x[b * XK + EMB + EE + tid] = g_h[b * DD + tid];
    }

    int e0i = half * 1024 + tid * 4;
    const __half* fb = g_feat16 + (size_t)b * PP * EE + e0i;

    float4 s0 = make_float4(0.f, 0.f, 0.f, 0.f);
    float4 s1 = make_float4(0.f, 0.f, 0.f, 0.f);
    float4 s2 = make_float4(0.f, 0.f, 0.f, 0.f);
    float4 s3 = make_float4(0.f, 0.f, 0.f, 0.f);
    for (int p = 0; p < PP; p += 4) {
        float w0 = sm.u.c.sw[p], w1 = sm.u.c.sw[p + 1];
        float w2 = sm.u.c.sw[p + 2], w3 = sm.u.c.sw[p + 3];
        uint2 r0 = *(const uint2*)(fb + (size_t)(p + 0) * EE);
        uint2 r1 = *(const uint2*)(fb + (size_t)(p + 1) * EE);
        uint2 r2 = *(const uint2*)(fb + (size_t)(p + 2) * EE);
        uint2 r3 = *(const uint2*)(fb + (size_t)(p + 3) * EE);
        float2 a0 = __half22float2(*reinterpret_cast<__half2*>(&r0.x));
        float2 c0 = __half22float2(*reinterpret_cast<__half2*>(&r0.y));
        float2 a1 = __half22float2(*reinterpret_cast<__half2*>(&r1.x));
        float2 c1 = __half22float2(*reinterpret_cast<__half2*>(&r1.y));
        float2 a2 = __half22float2(*reinterpret_cast<__half2*>(&r2.x));
        float2 c2 = __half22float2(*reinterpret_cast<__half2*>(&r2.y));
        float2 a3 = __half22float2(*reinterpret_cast<__half2*>(&r3.x));
        float2 c3 = __half22float2(*reinterpret_cast<__half2*>(&r3.y));
        s0.x += w0 * a0.x; s0.y += w0 * a0.y; s0.z += w0 * c0.x; s0.w += w0 * c0.y;
        s1.x += w1 * a1.x; s1.y += w1 * a1.y; s1.z += w1 * c1.x; s1.w += w1 * c1.y;
        s2.x += w2 * a2.x; s2.y += w2 * a2.y; s2.z += w2 * c2.x; s2.w += w2 * c2.y;
        s3.x += w3 * a3.x; s3.y += w3 * a3.y; s3.z += w3 * c3.x; s3.w += w3 * c3.y;
    }
    float4 sum;
    sum.x = (s0.x + s1.x) + (s2.x + s3.x);
    sum.y = (s0.y + s1.y) + (s2.y + s3.y);
    sum.z = (s0.z + s1.z) + (s2.z + s3.z);
    sum.w = (s0.w + s1.w) + (s2.w + s3.w);

    float4 gp0 = *(const float4*)(g_gatep + (size_t)b * EE + e0i);
    float4 gp1 = *(const float4*)(g_gatep + ((size_t)NB + b) * EE + e0i);
    float4 bg  = *(const float4*)(b_gate + e0i);
    float4 ctx;
    ctx.x = sum.x * sigf(bg.x + gp0.x + gp1.x);
    ctx.y = sum.y * sigf(bg.y + gp0.y + gp1.y);
    ctx.z = sum.z * sigf(bg.z + gp0.z + gp1.z);
    ctx.w = sum.w * sigf(bg.w + gp0.w + gp1.w);
    *(float4*)(g_x + (size_t)b * XK + EMB + e0i) = ctx;
}

// gates unit: x @ [W_ih;W_hh]16 chunk -> g_gp partials  (TC)
__device__ __forceinline__ void dev_gates(int nb, int kc, SMu& sm) {
    int k0g = kc * 256;
    float acc[4][4] = {};
    mma64(g_x + k0g, XK, g_Wih16 + (size_t)k0g * G4 + nb * 64, G4, 256, 64, sm, acc);

    int lane = threadIdx.x & 31, warp = threadIdx.x >> 5;
    int wm = warp & 3, wn = warp >> 2;
    int gr = lane >> 2, gc = (lane & 3) * 2;
    #pragma unroll
    for (int ni = 0; ni < 4; ++ni) {
        int col = nb * 64 + wn * 32 + ni * 8 + gc;
        int r0 = wm * 16 + gr;
        g_gp[((size_t)kc * NB + r0) * G4 + col]         = acc[ni][0];
        g_gp[((size_t)kc * NB + r0) * G4 + col + 1]     = acc[ni][1];
        g_gp[((size_t)kc * NB + r0 + 8) * G4 + col]     = acc[ni][2];
        g_gp[((size_t)kc * NB + r0 + 8) * G4 + col + 1] = acc[ni][3];
    }
}

__device__ __forceinline__ void dev_lstm(int b, int t,
        const float* __restrict__ b_ih, const float* __restrict__ b_hh) {
    int j = threadIdx.x;
    float gi = b_ih[j] + b_hh[j];
    float gf = b_ih[DD + j] + b_hh[DD + j];
    float gg = b_ih[2 * DD + j] + b_hh[2 * DD + j];
    float go = b_ih[3 * DD + j] + b_hh[3 * DD + j];
    #pragma unroll
    for (int kc = 0; kc < KC; ++kc) {
        const float* p = g_gp + ((size_t)kc * NB + b) * G4;
        gi += p[j];
        gf += p[DD + j];
        gg += p[2 * DD + j];
        go += p[3 * DD + j];
    }
    float c = g_c[b * DD + j];
    float cn = sigf(gf) * c + sigf(gi) * tanhf(gg);
    float hn = sigf(go) * tanhf(cn);
    if (g_target[b] > t) {
        g_h[b * DD + j] = hn;
        g_c[b * DD + j] = cn;
    }
}

__global__ void __launch_bounds__(256, 2) k_loop(
        const float* __restrict__ Wh, const float* __restrict__ bh,
        const float* __restrict__ We, const float* __restrict__ be,
        const float* __restrict__ b_gate, const float* __restrict__ emb,
        const int* __restrict__ tok,
        const float* __restrict__ b_ih, const float* __restrict__ b_hh,
        const float* __restrict__ b_head,
        float* __restrict__ out, float* __restrict__ out_att) {
    __shared__ SMu sm;
    for (int t = 0; t < TT; ++t) {
        int nact = g_nact[t];
        // Phase A: scores(t) 128 + gpre(t) 64 + head(t-1) nb[0,64) = 256 units
        int nA = 192 + (t >= 1 ? 64 : 0);
        for (int u = blockIdx.x; u < nA; u += NBLK) {
            __syncthreads();
            if (u < 128) {
                if ((u >> 1) < nact) dev_score(u >> 1, u & 1, sm, Wh, bh, We, be);
            }
            else if (u < 192) dev_gpre(u - 128, sm);
            else              dev_head(u - 192, t - 1, sm, b_head, out);
        }
        gridbar();
        // Phase B: ctx 128 + head(t-1) nb[64,157) = 221 units
        int nB = 128 + (t >= 1 ? 93 : 0);
        for (int u = blockIdx.x; u < nB; u += NBLK) {
            __syncthreads();
            if (u < 128) dev_ctx(u >> 1, u & 1, t, nact, sm, b_gate, emb, tok, out_att);
            else         dev_head(64 + (u - 128), t - 1, sm, b_head, out);
        }
        gridbar();
        // Phase C: gates split-K GEMM (160 units)
        for (int u = blockIdx.x; u < 160; u += NBLK) {
            __syncthreads();
            dev_gates(u & 15, u >> 4, sm);
        }
        gridbar();
        // Phase D: LSTM pointwise (64 units)
        if (blockIdx.x < NB) dev_lstm(blockIdx.x, t, b_ih, b_hh);
        gridbar();
    }
    // Tail: head for the final step (t = TT-1)
    for (int u = blockIdx.x; u < 157; u += NBLK) {
        __syncthreads();
        dev_head(u, TT - 1, sm, b_head, out);
    }
}

// ---------------------------------------------------------------------------
extern "C" void kernel_launch(void* const* d_in, const int* in_sizes, int n_in,
                              void* d_out, int out_size) {
    const float* feat   = (const float*)d_in[0];
    const int*   tok    = (const int*)d_in[1];
    const int*   caplen = (const int*)d_in[2];
    const float* Wf     = (const float*)d_in[3];
    const float* bf     = (const float*)d_in[4];
    const float* Wh     = (const float*)d_in[5];
    const float* bh     = (const float*)d_in[6];
    const float* We     = (const float*)d_in[7];
    const float* be     = (const float*)d_in[8];
    const float* emb    = (const float*)d_in[9];
    const float* W_ih   = (const float*)d_in[10];
    const float* b_ih   = (const float*)d_in[11];
    const float* W_hh   = (const float*)d_in[12];
    const float* b_hh   = (const float*)d_in[13];
    const float* W_hid  = (const float*)d_in[14];
    const float* b_hid  = (const float*)d_in[15];
    const float* W_cell = (const float*)d_in[16];
    const float* b_cell = (const float*)d_in[17];
    const float* W_gate = (const float*)d_in[18];
    const float* b_gate = (const float*)d_in[19];
    const float* W_head = (const float*)d_in[20];
    const float* b_head = (const float*)d_in[21];

    float* out = (float*)d_out;
    float* out_att = out + (size_t)NB * TT * VV;

    k_order<<<1, 32>>>(caplen);
    k_cvt<<<512, 256>>>(W_gate, W_ih, W_hh, W_head, Wf);
    k_cvtf<<<NB * PP, 256>>>(feat);
    k_fe<<<dim3(98, 5), 256>>>(feat, bf);         // fe HGEMM (tensor cores) + mean
    k_initA<<<dim3(8, 8), 256>>>(W_hid, W_cell);  // init GEMM, split-K
    k_init2<<<NB, 256>>>(b_hid, b_cell);

    // entire 31-step decoder loop in ONE persistent kernel
    k_loop<<<NBLK, 256>>>(Wh, bh, We, be, b_gate, emb, tok,
                          b_ih, b_hh, b_head, out, out_att);
}

// round 15
// speedup vs baseline: 1.8724x; 1.0608x over previous
#include <cuda_runtime.h>
#include <cuda_fp16.h>
#include <cstdint>

static constexpr int NB  = 64;     // batch
static constexpr int PP  = 196;    // spatial positions
static constexpr int EE  = 2048;   // feature dim
static constexpr int DD  = 256;    // hidden
static constexpr int HH  = 256;    // attention hidden
static constexpr int EMB = 256;    // embedding
static constexpr int VV  = 10000;  // vocab
static constexpr int LL  = 32;     // caption length
static constexpr int TT  = 31;     // timesteps
static constexpr int XK  = EMB + EE + DD;  // 2560
static constexpr int G4  = 4 * DD;         // 1024
static constexpr int KC  = 10;             // split-K chunks for gates gemm
static constexpr int NBLK = 256;           // persistent grid size

__device__ int    g_order[NB];
__device__ int    g_target[NB];
__device__ int    g_nact[TT + 1];
__device__ __half g_feat16[NB * PP * EE];   // 51.4 MB fp16 feat, order-permuted
__device__ __half g_fe16[NB * PP * HH];     // 6.4 MB fp16 attention features
__device__ float  g_mean[NB * EE];
__device__ float  g_h[NB * DD];
__device__ float  g_c[NB * DD];
__device__ float  g_score[NB * PP];
__device__ float  g_x[NB * XK];
__device__ float  g_gp[KC * NB * G4];
__device__ float  g_gatep[2 * NB * EE];
__device__ __half g_Wg16[DD * EE];
__device__ __half g_Wih16[XK * G4];
__device__ __half g_Whead16[DD * VV];
__device__ __half g_Wf16[EE * HH];
__device__ __half g_Wh16[DD * HH];          // Wh fp16 (128 KB -> L1-resident)

__device__ int          g_bar_count;
__device__ volatile int g_bar_gen;

__device__ __forceinline__ float sigf(float x) { return 1.0f / (1.0f + expf(-x)); }

// ---------------------------------------------------------------------------
__global__ void k_order(const int* __restrict__ caplen) {
    if (threadIdx.x == 0) {
        int idx = 0;
        for (int v = LL; v >= 1; --v) {
            for (int i = 0; i < NB; ++i) {
                if (caplen[i] == v) {
                    g_order[idx]  = i;
                    g_target[idx] = v - 1;
                    ++idx;
                }
            }
        }
        for (int t = 0; t <= TT; ++t) {
            int n = 0;
            for (int i = 0; i < NB; ++i) n += (g_target[i] > t) ? 1 : 0;
            g_nact[t] = n;
        }
    }
}

// ---------------------------------------------------------------------------
__global__ void k_cvt(const float* __restrict__ Wg, const float* __restrict__ Wih,
                      const float* __restrict__ Whh, const float* __restrict__ Whead,
                      const float* __restrict__ Wf, const float* __restrict__ Wh) {
    const int NQ_G  = (DD * EE) / 4;
    const int NQ_IH = (2304 * G4) / 4;
    const int NQ_HH = (DD * G4) / 4;
    const int NQ_HD = (DD * VV) / 4;
    const int NQ_WF = (EE * HH) / 4;
    const int NQ_WH = (DD * HH) / 4;
    const int total = NQ_G + NQ_IH + NQ_HH + NQ_HD + NQ_WF + NQ_WH;
    for (int i = blockIdx.x * blockDim.x + threadIdx.x; i < total;
         i += gridDim.x * blockDim.x) {
        const float* src; __half* dst; int q;
        int o0 = NQ_G, o1 = o0 + NQ_IH, o2 = o1 + NQ_HH, o3 = o2 + NQ_HD, o4 = o3 + NQ_WF;
        if (i < o0)      { src = Wg;    dst = g_Wg16;             q = i; }
        else if (i < o1) { src = Wih;   dst = g_Wih16;            q = i - o0; }
        else if (i < o2) { src = Whh;   dst = g_Wih16 + 2304 * G4; q = i - o1; }
        else if (i < o3) { src = Whead; dst = g_Whead16;          q = i - o2; }
        else if (i < o4) { src = Wf;    dst = g_Wf16;             q = i - o3; }
        else             { src = Wh;    dst = g_Wh16;             q = i - o4; }
        float4 v = *(const float4*)(src + (size_t)q * 4);
        *(__half2*)(dst + (size_t)q * 4)     = __floats2half2_rn(v.x, v.y);
        *(__half2*)(dst + (size_t)q * 4 + 2) = __floats2half2_rn(v.z, v.w);
    }
}

// ---------------------------------------------------------------------------
__global__ void __launch_bounds__(256) k_cvtf(const float* __restrict__ feat) {
    int row = blockIdx.x;
    int b = row / PP, p = row % PP;
    const float* src = feat + ((size_t)g_order[b] * PP + p) * EE + threadIdx.x * 8;
    __half* dst = g_feat16 + (size_t)row * EE + threadIdx.x * 8;
    float4 v0 = *(const float4*)(src);
    float4 v1 = *(const float4*)(src + 4);
    *(__half2*)(dst + 0) = __floats2half2_rn(v0.x, v0.y);
    *(__half2*)(dst + 2) = __floats2half2_rn(v0.z, v0.w);
    *(__half2*)(dst + 4) = __floats2half2_rn(v1.x, v1.y);
    *(__half2*)(dst + 6) = __floats2half2_rn(v1.z, v1.w);
}

// ---------------------------------------------------------------------------
// K3: grid (98, 5): fe HGEMM via mma.sync + mean (y==4)
// ---------------------------------------------------------------------------
__global__ void __launch_bounds__(256) k_fe(const float* __restrict__ feat,
                                            const float* __restrict__ bf) {
    int tid = threadIdx.x;
    int mb = blockIdx.x, nb = blockIdx.y;

    if (nb == 4) {
        if (mb >= NB) return;
        int b = mb;
        const float4* base = (const float4*)(feat + (size_t)g_order[b] * PP * EE);
        float4 sA = make_float4(0.f, 0.f, 0.f, 0.f);
        float4 sB = make_float4(0.f, 0.f, 0.f, 0.f);
        #pragma unroll 2
        for (int p = 0; p < PP; ++p) {
            float4 v0 = __ldcs(base + (size_t)p * (EE / 4) + tid);
            float4 v1 = __ldcs(base + (size_t)p * (EE / 4) + tid + 256);
            sA.x += v0.x; sA.y += v0.y; sA.z += v0.z; sA.w += v0.w;
            sB.x += v1.x; sB.y += v1.y; sB.z += v1.z; sB.w += v1.w;
        }
        const float inv = 1.0f / PP;
        sA.x *= inv; sA.y *= inv; sA.z *= inv; sA.w *= inv;
        sB.x *= inv; sB.y *= inv; sB.z *= inv; sB.w *= inv;
        *(float4*)(g_mean + b * EE + tid * 4)        = sA;
        *(float4*)(g_mean + b * EE + 1024 + tid * 4) = sB;
        return;
    }

    __shared__ __half As[128][72];
    __shared__ __half Bs[64][72];

    int warp = tid >> 5, lane = tid & 31;
    int wm = warp & 3, wn = warp >> 2;

    float acc[2][4][4] = {};

    for (int k0 = 0; k0 < EE; k0 += 64) {
        #pragma unroll
        for (int i = 0; i < 4; ++i) {
            int idx = tid + i * 256;
            int r = idx >> 3, c = (idx & 7) * 8;
            *(uint4*)&As[r][c] =
                *(const uint4*)(g_feat16 + (size_t)(mb * 128 + r) * EE + k0 + c);
        }
        #pragma unroll
        for (int i = 0; i < 2; ++i) {
            int idx = tid + i * 256;
            int r = idx >> 3, c = (idx & 7) * 8;
            *(uint4*)&Bs[r][c] =
                *(const uint4*)(g_Wf16 + (size_t)(k0 + r) * HH + nb * 64 + c);
        }
        __syncthreads();

        #pragma unroll
        for (int kk = 0; kk < 64; kk += 16) {
            unsigned a[2][4], b[4][2];
            #pragma unroll
            for (int mi = 0; mi < 2; ++mi) {
                unsigned addr = (unsigned)__cvta_generic_to_shared(
                    &As[wm * 32 + mi * 16 + (lane & 15)][kk + (lane >> 4) * 8]);
                asm volatile("ldmatrix.sync.aligned.m8n8.x4.shared.b16 {%0,%1,%2,%3}, [%4];"
                    : "=r"(a[mi][0]), "=r"(a[mi][1]), "=r"(a[mi][2]), "=r"(a[mi][3])
                    : "r"(addr));
            }
            #pragma unroll
            for (int ni = 0; ni < 4; ++ni) {
                unsigned addr = (unsigned)__cvta_generic_to_shared(
                    &Bs[kk + (lane & 15)][wn * 32 + ni * 8]);
                asm volatile("ldmatrix.sync.aligned.m8n8.x2.trans.shared.b16 {%0,%1}, [%2];"
                    : "=r"(b[ni][0]), "=r"(b[ni][1]) : "r"(addr));
            }
            #pragma unroll
            for (int mi = 0; mi < 2; ++mi)
                #pragma unroll
                for (int ni = 0; ni < 4; ++ni)
                    asm volatile(
                        "mma.sync.aligned.m16n8k16.row.col.f32.f16.f16.f32 "
                        "{%0,%1,%2,%3}, {%4,%5,%6,%7}, {%8,%9}, {%0,%1,%2,%3};"
                        : "+f"(acc[mi][ni][0]), "+f"(acc[mi][ni][1]),
                          "+f"(acc[mi][ni][2]), "+f"(acc[mi][ni][3])
                        : "r"(a[mi][0]), "r"(a[mi][1]), "r"(a[mi][2]), "r"(a[mi][3]),
                          "r"(b[ni][0]), "r"(b[ni][1]));
        }
        __syncthreads();
    }

    int gr = lane >> 2;
    int gc = (lane & 3) * 2;
    #pragma unroll
    for (int mi = 0; mi < 2; ++mi)
        #pragma unroll
        for (int ni = 0; ni < 4; ++ni) {
            int gn = nb * 64 + wn * 32 + ni * 8 + gc;
            float b0 = bf[gn], b1 = bf[gn + 1];
            int m0 = mb * 128 + wm * 32 + mi * 16 + gr;
            *(__half2*)(g_fe16 + (size_t)m0 * HH + gn) =
                __floats2half2_rn(acc[mi][ni][0] + b0, acc[mi][ni][1] + b1);
            int m1 = m0 + 8;
            *(__half2*)(g_fe16 + (size_t)m1 * HH + gn) =
                __floats2half2_rn(acc[mi][ni][2] + b0, acc[mi][ni][3] + b1);
        }
}

// ---------------------------------------------------------------------------
// K2a/K2b: init GEMM + reduce (prologue, unchanged)
// ---------------------------------------------------------------------------
__global__ void __launch_bounds__(256) k_initA(const float* __restrict__ W_hid,
                                               const float* __restrict__ W_cell) {
    __shared__ float As[16][68];
    __shared__ float Bs[16][64];
    int tid = threadIdx.x;
    int nb = blockIdx.x, kc = blockIdx.y;
    const float* wsrc = (nb < 4) ? W_hid : W_cell;
    int ncol0 = (nb & 3) * 64;
    int k0g = kc * 256;
    float acc[4][4] = {};
    int rb = (tid >> 4) * 4, cb = (tid & 15) * 4;

    for (int kt = 0; kt < 256; kt += 16) {
        {
            int r = tid >> 2, kk = (tid & 3) * 4;
            float4 av = *(const float4*)(g_mean + r * EE + k0g + kt + kk);
            As[kk + 0][r] = av.x; As[kk + 1][r] = av.y;
            As[kk + 2][r] = av.z; As[kk + 3][r] = av.w;
        }
        {
            int kk = tid >> 4, n = (tid & 15) * 4;
            *(float4*)&Bs[kk][n] =
                *(const float4*)(wsrc + (size_t)(k0g + kt + kk) * DD + ncol0 + n);
        }
        __syncthreads();
        #pragma unroll
        for (int kk = 0; kk < 16; ++kk) {
            float a[4], bv[4];
            *(float4*)a  = *(float4*)&As[kk][rb];
            *(float4*)bv = *(float4*)&Bs[kk][cb];
            #pragma unroll
            for (int i = 0; i < 4; ++i)
                #pragma unroll
                for (int j = 0; j < 4; ++j) acc[i][j] += a[i] * bv[j];
        }
        __syncthreads();
    }
    #pragma unroll
    for (int i = 0; i < 4; ++i)
        #pragma unroll
        for (int j = 0; j < 4; ++j)
            g_gp[((size_t)kc * NB + rb + i) * 512 + nb * 64 + cb + j] = acc[i][j];
}

__global__ void k_init2(const float* __restrict__ b_hid, const float* __restrict__ b_cell) {
    int b = blockIdx.x, j = threadIdx.x;
    float h = b_hid[j], c = b_cell[j];
    #pragma unroll
    for (int kc = 0; kc < 8; ++kc) {
        const float* p = g_gp + ((size_t)kc * NB + b) * 512;
        h += p[j];
        c += p[256 + j];
    }
    g_h[b * DD + j] = h;
    g_c[b * DD + j] = c;
}

// ===========================================================================
// Persistent step-loop kernel
// ===========================================================================
struct SMu {
    union {
        struct { __half As[64][72]; __half Bs[64][72]; } m;   // TC tiles
        struct { float sh[256]; float she[256]; float swe[256]; } a;
        struct { float sw[256]; float red[8]; } c;
    } u;
};

__device__ __forceinline__ void gridbar() {
    __syncthreads();
    __threadfence();
    if (threadIdx.x == 0) {
        int gen = g_bar_gen;
        if (atomicAdd(&g_bar_count, 1) == NBLK - 1) {
            g_bar_count = 0;
            __threadfence();
            g_bar_gen = gen + 1;
        } else {
            while (g_bar_gen == gen) __nanosleep(64);
        }
    }
    __syncthreads();
    __threadfence();
}

// ---------------------------------------------------------------------------
// Shared tensor-core 64x64 tile GEMM (unchanged from R14)
// ---------------------------------------------------------------------------
__device__ __forceinline__ void mma64(const float* __restrict__ Ag, int lda,
        const __half* __restrict__ Bg, int ldb, int K, int nvalid,
        SMu& sm, float acc[4][4]) {
    int tid = threadIdx.x, lane = tid & 31, warp = tid >> 5;
    int wm = warp & 3, wn = warp >> 2;

    for (int k0 = 0; k0 < K; k0 += 64) {
        {
            int r = tid >> 2, c0 = (tid & 3) * 16;
            const float* src = Ag + (size_t)r * lda + k0 + c0;
            float4 v0 = *(const float4*)(src);
            float4 v1 = *(const float4*)(src + 4);
            float4 v2 = *(const float4*)(src + 8);
            float4 v3 = *(const float4*)(src + 12);
            __half* d = &sm.u.m.As[r][c0];
            *(__half2*)(d + 0)  = __floats2half2_rn(v0.x, v0.y);
            *(__half2*)(d + 2)  = __floats2half2_rn(v0.z, v0.w);
            *(__half2*)(d + 4)  = __floats2half2_rn(v1.x, v1.y);
            *(__half2*)(d + 6)  = __floats2half2_rn(v1.z, v1.w);
            *(__half2*)(d + 8)  = __floats2half2_rn(v2.x, v2.y);
            *(__half2*)(d + 10) = __floats2half2_rn(v2.z, v2.w);
            *(__half2*)(d + 12) = __floats2half2_rn(v3.x, v3.y);
            *(__half2*)(d + 14) = __floats2half2_rn(v3.z, v3.w);
        }
        #pragma unroll
        for (int i = 0; i < 2; ++i) {
            int idx = tid + i * 256;
            int r = idx >> 3, c = (idx & 7) * 8;
            uint4 val;
            if (c + 8 <= nvalid) {
                val = *(const uint4*)(Bg + (size_t)(k0 + r) * ldb + c);
            } else {
                __half tmp[8];
                #pragma unroll
                for (int j = 0; j < 8; ++j)
                    tmp[j] = (c + j < nvalid) ? Bg[(size_t)(k0 + r) * ldb + c + j]
                                              : __float2half(0.f);
                val = *(uint4*)tmp;
            }
            *(uint4*)&sm.u.m.Bs[r][c] = val;
        }
        __syncthreads();

        #pragma unroll
        for (int kk = 0; kk < 64; kk += 16) {
            unsigned a[4], b[4][2];
            {
                unsigned addr = (unsigned)__cvta_generic_to_shared(
                    &sm.u.m.As[wm * 16 + (lane & 15)][kk + (lane >> 4) * 8]);
                asm volatile("ldmatrix.sync.aligned.m8n8.x4.shared.b16 {%0,%1,%2,%3}, [%4];"
                    : "=r"(a[0]), "=r"(a[1]), "=r"(a[2]), "=r"(a[3]) : "r"(addr));
            }
            #pragma unroll
            for (int ni = 0; ni < 4; ++ni) {
                unsigned addr = (unsigned)__cvta_generic_to_shared(
                    &sm.u.m.Bs[kk + (lane & 15)][wn * 32 + ni * 8]);
                asm volatile("ldmatrix.sync.aligned.m8n8.x2.trans.shared.b16 {%0,%1}, [%2];"
                    : "=r"(b[ni][0]), "=r"(b[ni][1]) : "r"(addr));
            }
            #pragma unroll
            for (int ni = 0; ni < 4; ++ni)
                asm volatile(
                    "mma.sync.aligned.m16n8k16.row.col.f32.f16.f16.f32 "
                    "{%0,%1,%2,%3}, {%4,%5,%6,%7}, {%8,%9}, {%0,%1,%2,%3};"
                    : "+f"(acc[ni][0]), "+f"(acc[ni][1]),
                      "+f"(acc[ni][2]), "+f"(acc[ni][3])
                    : "r"(a[0]), "r"(a[1]), "r"(a[2]), "r"(a[3]),
                      "r"(b[ni][0]), "r"(b[ni][1]));
        }
        __syncthreads();
    }
}

// score unit: he GEMV (fp16 Wh, 4-way ILP) + fe scan
__device__ __forceinline__ void dev_score(int b, int half, SMu& sm,
        const float* __restrict__ bh,
        const float* __restrict__ We, const float* __restrict__ be) {
    int tid = threadIdx.x, lane = tid & 31, wid = tid >> 5;
    sm.u.a.sh[tid]  = g_h[b * DD + tid];
    sm.u.a.swe[tid] = We[tid];
    __syncthreads();
    // he[tid] = bh[tid] + sum_k h[k] * Wh16[k][tid]  (4 independent chains)
    float a0 = 0.f, a1 = 0.f, a2 = 0.f, a3 = 0.f;
    const __half* whc = g_Wh16 + tid;
    #pragma unroll 4
    for (int k = 0; k < DD; k += 4) {
        a0 += sm.u.a.sh[k + 0] * __half2float(whc[(k + 0) * HH]);
        a1 += sm.u.a.sh[k + 1] * __half2float(whc[(k + 1) * HH]);
        a2 += sm.u.a.sh[k + 2] * __half2float(whc[(k + 2) * HH]);
        a3 += sm.u.a.sh[k + 3] * __half2float(whc[(k + 3) * HH]);
    }
    sm.u.a.she[tid] = bh[tid] + ((a0 + a1) + (a2 + a3));
    __syncthreads();
    float be0 = be[0];
    int p0 = half * 98, p1 = p0 + 98;
    const __half* febase = g_fe16 + (size_t)b * PP * HH;
    for (int p = p0 + wid; p < p1; p += 8) {
        const __half* fr = febase + (size_t)p * HH;
        float s = 0.f;
        #pragma unroll
        for (int it = 0; it < 4; ++it) {
            int j = it * 64 + lane * 2;
            float2 fv = __half22float2(*(const __half2*)(fr + j));
            float v0 = fv.x + sm.u.a.she[j], v1 = fv.y + sm.u.a.she[j + 1];
            s += fmaxf(v0, 0.f) * sm.u.a.swe[j] + fmaxf(v1, 0.f) * sm.u.a.swe[j + 1];
        }
        #pragma unroll
        for (int o = 16; o; o >>= 1) s += __shfl_xor_sync(0xffffffffu, s, o);
        if (lane == 0) g_score[b * PP + p] = s + be0;
    }
}

// gpre unit: h @ W_gate16 chunk -> g_gatep partials  (TC)
__device__ __forceinline__ void dev_gpre(int bid, SMu& sm) {
    int nb = bid & 31, kc = bid >> 5;
    int kbase = kc * 128;
    float acc[4][4] = {};
    mma64(g_h + kbase, DD, g_Wg16 + (size_t)kbase * EE + nb * 64, EE, 128, 64, sm, acc);

    int lane = threadIdx.x & 31, warp = threadIdx.x >> 5;
    int wm = warp & 3, wn = warp >> 2;
    int gr = lane >> 2, gc = (lane & 3) * 2;
    #pragma unroll
    for (int ni = 0; ni < 4; ++ni) {
        int col = nb * 64 + wn * 32 + ni * 8 + gc;
        int r0 = wm * 16 + gr;
        g_gatep[((size_t)kc * NB + r0) * EE + col]         = acc[ni][0];
        g_gatep[((size_t)kc * NB + r0) * EE + col + 1]     = acc[ni][1];
        g_gatep[((size_t)kc * NB + r0 + 8) * EE + col]     = acc[ni][2];
        g_gatep[((size_t)kc * NB + r0 + 8) * EE + col + 1] = acc[ni][3];
    }
}

// head unit: h @ W_head16 tile -> out (masked, bias)  (TC)
__device__ __forceinline__ void dev_head(int nb, int tprev, SMu& sm,
        const float* __restrict__ b_head, float* __restrict__ out) {
    int n0 = nb * 64;
    int nvalid = (VV - n0 < 64) ? (VV - n0) : 64;
    float acc[4][4] = {};
    mma64(g_h, DD, g_Whead16 + n0, VV, DD, nvalid, sm, acc);

    int lane = threadIdx.x & 31, warp = threadIdx.x >> 5;
    int wm = warp & 3, wn = warp >> 2;
    int gr = lane >> 2, gc = (lane & 3) * 2;
    #pragma unroll
    for (int ni = 0; ni < 4; ++ni) {
        int gn = n0 + wn * 32 + ni * 8 + gc;
        #pragma unroll
        for (int half = 0; half < 2; ++half) {
            int b = wm * 16 + gr + half * 8;
            bool msk = (g_target[b] > tprev);
            size_t rowbase = ((size_t)b * TT + tprev) * VV;
            if (gn < VV)
                out[rowbase + gn] = msk ? (acc[ni][2 * half] + b_head[gn]) : 0.f;
            if (gn + 1 < VV)
                out[rowbase + gn + 1] = msk ? (acc[ni][2 * half + 1] + b_head[gn + 1]) : 0.f;
        }
    }
}

__device__ __forceinline__ void dev_ctx(int b, int half, int t, int nact, SMu& sm,
        const float* __restrict__ b_gate, const float* __restrict__ emb,
        const int* __restrict__ tok, float* __restrict__ out_att) {
    int tid = threadIdx.x, lane = tid & 31, wid = tid >> 5;

    if (b >= nact) {
        if (half == 0 && tid < PP)
            out_att[((size_t)b * TT + t) * PP + tid] = 0.f;
        return;
    }

    float v = (tid < PP) ? g_score[b * PP + tid] : -3.4e38f;
    float m = v;
    #pragma unroll
    for (int o = 16; o; o >>= 1) m = fmaxf(m, __shfl_xor_sync(0xffffffffu, m, o));
    if (lane == 0) sm.u.c.red[wid] = m;
    __syncthreads();
    if (tid == 0) {
        float mm = sm.u.c.red[0];
        #pragma unroll
        for (int i = 1; i < 8; ++i) mm = fmaxf(mm, sm.u.c.red[i]);
        sm.u.c.red[0] = mm;
    }
    __syncthreads();
    float mx = sm.u.c.red[0];
    __syncthreads();

    float e = (tid < PP) ? expf(v - mx) : 0.f;
    float s = e;
    #pragma unroll
    for (int o = 16; o; o >>= 1) s += __shfl_xor_sync(0xffffffffu, s, o);
    if (lane == 0) sm.u.c.red[wid] = s;
    __syncthreads();
    if (tid == 0) {
        float ss = 0.f;
        #pragma unroll
        for (int i = 0; i < 8; ++i) ss += sm.u.c.red[i];
        sm.u.c.red[0] = ss;
    }
    __syncthreads();
    float inv = 1.0f / sm.u.c.red[0];
    if (tid < PP) sm.u.c.sw[tid] = e * inv;
    __syncthreads();

    if (half == 0) {
        if (tid < PP)
            out_att[((size_t)b * TT + t) * PP + tid] = sm.u.c.sw[tid];
        int token = tok[g_order[b] * LL + t];
        g_x[b * XK + tid] = emb[(size_t)token * EMB + tid];
        g_x[b * XK + EMB + EE + tid] = g_h[b * DD + tid];
    }

    int e0i = half * 1024 + tid * 4;
    const __half* fb = g_feat16 + (size_t)b * PP * EE + e0i;

    float4 s0 = make_float4(0.f, 0.f, 0.f, 0.f);
    float4 s1 = make_float4(0.f, 0.f, 0.f, 0.f);
    float4 s2 = make_float4(0.f, 0.f, 0.f, 0.f);
    float4 s3 = make_float4(0.f, 0.f, 0.f, 0.f);
    for (int p = 0; p < PP; p += 4) {
        float w0 = sm.u.c.sw[p], w1 = sm.u.c.sw[p + 1];
        float w2 = sm.u.c.sw[p + 2], w3 = sm.u.c.sw[p + 3];
        uint2 r0 = *(const uint2*)(fb + (size_t)(p + 0) * EE);
        uint2 r1 = *(const uint2*)(fb + (size_t)(p + 1) * EE);
        uint2 r2 = *(const uint2*)(fb + (size_t)(p + 2) * EE);
        uint2 r3 = *(const uint2*)(fb + (size_t)(p + 3) * EE);
        float2 a0 = __half22float2(*reinterpret_cast<__half2*>(&r0.x));
        float2 c0 = __half22float2(*reinterpret_cast<__half2*>(&r0.y));
        float2 a1 = __half22float2(*reinterpret_cast<__half2*>(&r1.x));
        float2 c1 = __half22float2(*reinterpret_cast<__half2*>(&r1.y));
        float2 a2 = __half22float2(*reinterpret_cast<__half2*>(&r2.x));
        float2 c2 = __half22float2(*reinterpret_cast<__half2*>(&r2.y));
        float2 a3 = __half22float2(*reinterpret_cast<__half2*>(&r3.x));
        float2 c3 = __half22float2(*reinterpret_cast<__half2*>(&r3.y));
        s0.x += w0 * a0.x; s0.y += w0 * a0.y; s0.z += w0 * c0.x; s0.w += w0 * c0.y;
        s1.x += w1 * a1.x; s1.y += w1 * a1.y; s1.z += w1 * c1.x; s1.w += w1 * c1.y;
        s2.x += w2 * a2.x; s2.y += w2 * a2.y; s2.z += w2 * c2.x; s2.w += w2 * c2.y;
        s3.x += w3 * a3.x; s3.y += w3 * a3.y; s3.z += w3 * c3.x; s3.w += w3 * c3.y;
    }
    float4 sum;
    sum.x = (s0.x + s1.x) + (s2.x + s3.x);
    sum.y = (s0.y + s1.y) + (s2.y + s3.y);
    sum.z = (s0.z + s1.z) + (s2.z + s3.z);
    sum.w = (s0.w + s1.w) + (s2.w + s3.w);

    float4 gp0 = *(const float4*)(g_gatep + (size_t)b * EE + e0i);
    float4 gp1 = *(const float4*)(g_gatep + ((size_t)NB + b) * EE + e0i);
    float4 bg  = *(const float4*)(b_gate + e0i);
    float4 ctx;
    ctx.x = sum.x * sigf(bg.x + gp0.x + gp1.x);
    ctx.y = sum.y * sigf(bg.y + gp0.y + gp1.y);
    ctx.z = sum.z * sigf(bg.z + gp0.z + gp1.z);
    ctx.w = sum.w * sigf(bg.w + gp0.w + gp1.w);
    *(float4*)(g_x + (size_t)b * XK + EMB + e0i) = ctx;
}

// gates unit: x @ [W_ih;W_hh]16 chunk -> g_gp partials  (TC)
__device__ __forceinline__ void dev_gates(int nb, int kc, SMu& sm) {
    int k0g = kc * 256;
    float acc[4][4] = {};
    mma64(g_x + k0g, XK, g_Wih16 + (size_t)k0g * G4 + nb * 64, G4, 256, 64, sm, acc);

    int lane = threadIdx.x & 31, warp = threadIdx.x >> 5;
    int wm = warp & 3, wn = warp >> 2;
    int gr = lane >> 2, gc = (lane & 3) * 2;
    #pragma unroll
    for (int ni = 0; ni < 4; ++ni) {
        int col = nb * 64 + wn * 32 + ni * 8 + gc;
        int r0 = wm * 16 + gr;
        g_gp[((size_t)kc * NB + r0) * G4 + col]         = acc[ni][0];
        g_gp[((size_t)kc * NB + r0) * G4 + col + 1]     = acc[ni][1];
        g_gp[((size_t)kc * NB + r0 + 8) * G4 + col]     = acc[ni][2];
        g_gp[((size_t)kc * NB + r0 + 8) * G4 + col + 1] = acc[ni][3];
    }
}

__device__ __forceinline__ void dev_lstm(int b, int t,
        const float* __restrict__ b_ih, const float* __restrict__ b_hh) {
    int j = threadIdx.x;
    float gi = b_ih[j] + b_hh[j];
    float gf = b_ih[DD + j] + b_hh[DD + j];
    float gg = b_ih[2 * DD + j] + b_hh[2 * DD + j];
    float go = b_ih[3 * DD + j] + b_hh[3 * DD + j];
    #pragma unroll
    for (int kc = 0; kc < KC; ++kc) {
        const float* p = g_gp + ((size_t)kc * NB + b) * G4;
        gi += p[j];
        gf += p[DD + j];
        gg += p[2 * DD + j];
        go += p[3 * DD + j];
    }
    float c = g_c[b * DD + j];
    float cn = sigf(gf) * c + sigf(gi) * tanhf(gg);
    float hn = sigf(go) * tanhf(cn);
    if (g_target[b] > t) {
        g_h[b * DD + j] = hn;
        g_c[b * DD + j] = cn;
    }
}

__global__ void __launch_bounds__(256, 2) k_loop(
        const float* __restrict__ bh,
        const float* __restrict__ We, const float* __restrict__ be,
        const float* __restrict__ b_gate, const float* __restrict__ emb,
        const int* __restrict__ tok,
        const float* __restrict__ b_ih, const float* __restrict__ b_hh,
        const float* __restrict__ b_head,
        float* __restrict__ out, float* __restrict__ out_att) {
    __shared__ SMu sm;
    for (int t = 0; t < TT; ++t) {
        int nact = g_nact[t];
        // Phase A: scores(t) 128 + gpre(t) 64 + head(t-1) nb[0,64) = 256 units
        int nA = 192 + (t >= 1 ? 64 : 0);
        for (int u = blockIdx.x; u < nA; u += NBLK) {
            __syncthreads();
            if (u < 128) {
                if ((u >> 1) < nact) dev_score(u >> 1, u & 1, sm, bh, We, be);
            }
            else if (u < 192) dev_gpre(u - 128, sm);
            else              dev_head(u - 192, t - 1, sm, b_head, out);
        }
        gridbar();
        // Phase B: ctx 128 + head(t-1) nb[64,157) = 221 units
        int nB = 128 + (t >= 1 ? 93 : 0);
        for (int u = blockIdx.x; u < nB; u += NBLK) {
            __syncthreads();
            if (u < 128) dev_ctx(u >> 1, u & 1, t, nact, sm, b_gate, emb, tok, out_att);
            else         dev_head(64 + (u - 128), t - 1, sm, b_head, out);
        }
        gridbar();
        // Phase C: gates split-K GEMM (160 units)
        for (int u = blockIdx.x; u < 160; u += NBLK) {
            __syncthreads();
            dev_gates(u & 15, u >> 4, sm);
        }
        gridbar();
        // Phase D: LSTM pointwise (64 units)
        if (blockIdx.x < NB) dev_lstm(blockIdx.x, t, b_ih, b_hh);
        gridbar();
    }
    // Tail: head for the final step (t = TT-1)
    for (int u = blockIdx.x; u < 157; u += NBLK) {
        __syncthreads();
        dev_head(u, TT - 1, sm, b_head, out);
    }
}

// ---------------------------------------------------------------------------
extern "C" void kernel_launch(void* const* d_in, const int* in_sizes, int n_in,
                              void* d_out, int out_size) {
    const float* feat   = (const float*)d_in[0];
    const int*   tok    = (const int*)d_in[1];
    const int*   caplen = (const int*)d_in[2];
    const float* Wf     = (const float*)d_in[3];
    const float* bf     = (const float*)d_in[4];
    const float* Wh     = (const float*)d_in[5];
    const float* bh     = (const float*)d_in[6];
    const float* We     = (const float*)d_in[7];
    const float* be     = (const float*)d_in[8];
    const float* emb    = (const float*)d_in[9];
    const float* W_ih   = (const float*)d_in[10];
    const float* b_ih   = (const float*)d_in[11];
    const float* W_hh   = (const float*)d_in[12];
    const float* b_hh   = (const float*)d_in[13];
    const float* W_hid  = (const float*)d_in[14];
    const float* b_hid  = (const float*)d_in[15];
    const float* W_cell = (const float*)d_in[16];
    const float* b_cell = (const float*)d_in[17];
    const float* W_gate = (const float*)d_in[18];
    const float* b_gate = (const float*)d_in[19];
    const float* W_head = (const float*)d_in[20];
    const float* b_head = (const float*)d_in[21];

    float* out = (float*)d_out;
    float* out_att = out + (size_t)NB * TT * VV;

    k_order<<<1, 32>>>(caplen);
    k_cvt<<<512, 256>>>(W_gate, W_ih, W_hh, W_head, Wf, Wh);
    k_cvtf<<<NB * PP, 256>>>(feat);
    k_fe<<<dim3(98, 5), 256>>>(feat, bf);         // fe HGEMM (tensor cores) + mean
    k_initA<<<dim3(8, 8), 256>>>(W_hid, W_cell);  // init GEMM, split-K
    k_init2<<<NB, 256>>>(b_hid, b_cell);

    // entire 31-step decoder loop in ONE persistent kernel
    k_loop<<<NBLK, 256>>>(bh, We, be, b_gate, emb, tok,
                          b_ih, b_hh, b_head, out, out_att);
}

// round 16
// speedup vs baseline: 1.8833x; 1.0058x over previous
#include <cuda_runtime.h>
#include <cuda_fp16.h>
#include <cstdint>

static constexpr int NB  = 64;     // batch
static constexpr int PP  = 196;    // spatial positions
static constexpr int EE  = 2048;   // feature dim
static constexpr int DD  = 256;    // hidden
static constexpr int HH  = 256;    // attention hidden
static constexpr int EMB = 256;    // embedding
static constexpr int VV  = 10000;  // vocab
static constexpr int LL  = 32;     // caption length
static constexpr int TT  = 31;     // timesteps
static constexpr int XK  = EMB + EE + DD;  // 2560
static constexpr int G4  = 4 * DD;         // 1024
static constexpr int KC  = 10;             // split-K chunks for gates gemm
static constexpr int NBLK = 256;           // persistent grid size

__device__ int    g_order[NB];
__device__ int    g_target[NB];
__device__ int    g_nact[TT + 1];
__device__ __half g_feat16[NB * PP * EE];   // 51.4 MB fp16 feat, order-permuted
__device__ __half g_fe16[NB * PP * HH];     // 6.4 MB fp16 attention features
__device__ float  g_mean[NB * EE];
__device__ float  g_h[NB * DD];
__device__ float  g_c[NB * DD];
__device__ float  g_score[NB * PP];
__device__ float  g_x[NB * XK];
__device__ float  g_gp[KC * NB * G4];
__device__ float  g_gatep[2 * NB * EE];
__device__ __half g_Wg16[DD * EE];
__device__ __half g_Wih16[XK * G4];
__device__ __half g_Whead16[DD * VV];
__device__ __half g_Wf16[EE * HH];
__device__ __half g_Wh16[DD * HH];          // Wh fp16 (128 KB -> L1-resident)

__device__ int          g_bar_count;
__device__ volatile int g_bar_gen;

__device__ __forceinline__ float sigf(float x) { return 1.0f / (1.0f + expf(-x)); }

// ---------------------------------------------------------------------------
__global__ void k_order(const int* __restrict__ caplen) {
    if (threadIdx.x == 0) {
        int idx = 0;
        for (int v = LL; v >= 1; --v) {
            for (int i = 0; i < NB; ++i) {
                if (caplen[i] == v) {
                    g_order[idx]  = i;
                    g_target[idx] = v - 1;
                    ++idx;
                }
            }
        }
        for (int t = 0; t <= TT; ++t) {
            int n = 0;
            for (int i = 0; i < NB; ++i) n += (g_target[i] > t) ? 1 : 0;
            g_nact[t] = n;
        }
    }
}

// ---------------------------------------------------------------------------
__global__ void k_cvt(const float* __restrict__ Wg, const float* __restrict__ Wih,
                      const float* __restrict__ Whh, const float* __restrict__ Whead,
                      const float* __restrict__ Wf, const float* __restrict__ Wh) {
    const int NQ_G  = (DD * EE) / 4;
    const int NQ_IH = (2304 * G4) / 4;
    const int NQ_HH = (DD * G4) / 4;
    const int NQ_HD = (DD * VV) / 4;
    const int NQ_WF = (EE * HH) / 4;
    const int NQ_WH = (DD * HH) / 4;
    const int total = NQ_G + NQ_IH + NQ_HH + NQ_HD + NQ_WF + NQ_WH;
    for (int i = blockIdx.x * blockDim.x + threadIdx.x; i < total;
         i += gridDim.x * blockDim.x) {
        const float* src; __half* dst; int q;
        int o0 = NQ_G, o1 = o0 + NQ_IH, o2 = o1 + NQ_HH, o3 = o2 + NQ_HD, o4 = o3 + NQ_WF;
        if (i < o0)      { src = Wg;    dst = g_Wg16;             q = i; }
        else if (i < o1) { src = Wih;   dst = g_Wih16;            q = i - o0; }
        else if (i < o2) { src = Whh;   dst = g_Wih16 + 2304 * G4; q = i - o1; }
        else if (i < o3) { src = Whead; dst = g_Whead16;          q = i - o2; }
        else if (i < o4) { src = Wf;    dst = g_Wf16;             q = i - o3; }
        else             { src = Wh;    dst = g_Wh16;             q = i - o4; }
        float4 v = *(const float4*)(src + (size_t)q * 4);
        *(__half2*)(dst + (size_t)q * 4)     = __floats2half2_rn(v.x, v.y);
        *(__half2*)(dst + (size_t)q * 4 + 2) = __floats2half2_rn(v.z, v.w);
    }
}

// ---------------------------------------------------------------------------
__global__ void __launch_bounds__(256) k_cvtf(const float* __restrict__ feat) {
    int row = blockIdx.x;
    int b = row / PP, p = row % PP;
    const float* src = feat + ((size_t)g_order[b] * PP + p) * EE + threadIdx.x * 8;
    __half* dst = g_feat16 + (size_t)row * EE + threadIdx.x * 8;
    float4 v0 = *(const float4*)(src);
    float4 v1 = *(const float4*)(src + 4);
    *(__half2*)(dst + 0) = __floats2half2_rn(v0.x, v0.y);
    *(__half2*)(dst + 2) = __floats2half2_rn(v0.z, v0.w);
    *(__half2*)(dst + 4) = __floats2half2_rn(v1.x, v1.y);
    *(__half2*)(dst + 6) = __floats2half2_rn(v1.z, v1.w);
}

// ---------------------------------------------------------------------------
// K3: grid (98, 5): fe HGEMM via mma.sync + mean (y==4)
// ---------------------------------------------------------------------------
__global__ void __launch_bounds__(256) k_fe(const float* __restrict__ feat,
                                            const float* __restrict__ bf) {
    int tid = threadIdx.x;
    int mb = blockIdx.x, nb = blockIdx.y;

    if (nb == 4) {
        if (mb >= NB) return;
        int b = mb;
        const float4* base = (const float4*)(feat + (size_t)g_order[b] * PP * EE);
        float4 sA = make_float4(0.f, 0.f, 0.f, 0.f);
        float4 sB = make_float4(0.f, 0.f, 0.f, 0.f);
        #pragma unroll 2
        for (int p = 0; p < PP; ++p) {
            float4 v0 = __ldcs(base + (size_t)p * (EE / 4) + tid);
            float4 v1 = __ldcs(base + (size_t)p * (EE / 4) + tid + 256);
            sA.x += v0.x; sA.y += v0.y; sA.z += v0.z; sA.w += v0.w;
            sB.x += v1.x; sB.y += v1.y; sB.z += v1.z; sB.w += v1.w;
        }
        const float inv = 1.0f / PP;
        sA.x *= inv; sA.y *= inv; sA.z *= inv; sA.w *= inv;
        sB.x *= inv; sB.y *= inv; sB.z *= inv; sB.w *= inv;
        *(float4*)(g_mean + b * EE + tid * 4)        = sA;
        *(float4*)(g_mean + b * EE + 1024 + tid * 4) = sB;
        return;
    }

    __shared__ __half As[128][72];
    __shared__ __half Bs[64][72];

    int warp = tid >> 5, lane = tid & 31;
    int wm = warp & 3, wn = warp >> 2;

    float acc[2][4][4] = {};

    for (int k0 = 0; k0 < EE; k0 += 64) {
        #pragma unroll
        for (int i = 0; i < 4; ++i) {
            int idx = tid + i * 256;
            int r = idx >> 3, c = (idx & 7) * 8;
            *(uint4*)&As[r][c] =
                *(const uint4*)(g_feat16 + (size_t)(mb * 128 + r) * EE + k0 + c);
        }
        #pragma unroll
        for (int i = 0; i < 2; ++i) {
            int idx = tid + i * 256;
            int r = idx >> 3, c = (idx & 7) * 8;
            *(uint4*)&Bs[r][c] =
                *(const uint4*)(g_Wf16 + (size_t)(k0 + r) * HH + nb * 64 + c);
        }
        __syncthreads();

        #pragma unroll
        for (int kk = 0; kk < 64; kk += 16) {
            unsigned a[2][4], b[4][2];
            #pragma unroll
            for (int mi = 0; mi < 2; ++mi) {
                unsigned addr = (unsigned)__cvta_generic_to_shared(
                    &As[wm * 32 + mi * 16 + (lane & 15)][kk + (lane >> 4) * 8]);
                asm volatile("ldmatrix.sync.aligned.m8n8.x4.shared.b16 {%0,%1,%2,%3}, [%4];"
                    : "=r"(a[mi][0]), "=r"(a[mi][1]), "=r"(a[mi][2]), "=r"(a[mi][3])
                    : "r"(addr));
            }
            #pragma unroll
            for (int ni = 0; ni < 4; ++ni) {
                unsigned addr = (unsigned)__cvta_generic_to_shared(
                    &Bs[kk + (lane & 15)][wn * 32 + ni * 8]);
                asm volatile("ldmatrix.sync.aligned.m8n8.x2.trans.shared.b16 {%0,%1}, [%2];"
                    : "=r"(b[ni][0]), "=r"(b[ni][1]) : "r"(addr));
            }
            #pragma unroll
            for (int mi = 0; mi < 2; ++mi)
                #pragma unroll
                for (int ni = 0; ni < 4; ++ni)
                    asm volatile(
                        "mma.sync.aligned.m16n8k16.row.col.f32.f16.f16.f32 "
                        "{%0,%1,%2,%3}, {%4,%5,%6,%7}, {%8,%9}, {%0,%1,%2,%3};"
                        : "+f"(acc[mi][ni][0]), "+f"(acc[mi][ni][1]),
                          "+f"(acc[mi][ni][2]), "+f"(acc[mi][ni][3])
                        : "r"(a[mi][0]), "r"(a[mi][1]), "r"(a[mi][2]), "r"(a[mi][3]),
                          "r"(b[ni][0]), "r"(b[ni][1]));
        }
        __syncthreads();
    }

    int gr = lane >> 2;
    int gc = (lane & 3) * 2;
    #pragma unroll
    for (int mi = 0; mi < 2; ++mi)
        #pragma unroll
        for (int ni = 0; ni < 4; ++ni) {
            int gn = nb * 64 + wn * 32 + ni * 8 + gc;
            float b0 = bf[gn], b1 = bf[gn + 1];
            int m0 = mb * 128 + wm * 32 + mi * 16 + gr;
            *(__half2*)(g_fe16 + (size_t)m0 * HH + gn) =
                __floats2half2_rn(acc[mi][ni][0] + b0, acc[mi][ni][1] + b1);
            int m1 = m0 + 8;
            *(__half2*)(g_fe16 + (size_t)m1 * HH + gn) =
                __floats2half2_rn(acc[mi][ni][2] + b0, acc[mi][ni][3] + b1);
        }
}

// ---------------------------------------------------------------------------
// K2a/K2b: init GEMM + reduce (prologue, unchanged)
// ---------------------------------------------------------------------------
__global__ void __launch_bounds__(256) k_initA(const float* __restrict__ W_hid,
                                               const float* __restrict__ W_cell) {
    __shared__ float As[16][68];
    __shared__ float Bs[16][64];
    int tid = threadIdx.x;
    int nb = blockIdx.x, kc = blockIdx.y;
    const float* wsrc = (nb < 4) ? W_hid : W_cell;
    int ncol0 = (nb & 3) * 64;
    int k0g = kc * 256;
    float acc[4][4] = {};
    int rb = (tid >> 4) * 4, cb = (tid & 15) * 4;

    for (int kt = 0; kt < 256; kt += 16) {
        {
            int r = tid >> 2, kk = (tid & 3) * 4;
            float4 av = *(const float4*)(g_mean + r * EE + k0g + kt + kk);
            As[kk + 0][r] = av.x; As[kk + 1][r] = av.y;
            As[kk + 2][r] = av.z; As[kk + 3][r] = av.w;
        }
        {
            int kk = tid >> 4, n = (tid & 15) * 4;
            *(float4*)&Bs[kk][n] =
                *(const float4*)(wsrc + (size_t)(k0g + kt + kk) * DD + ncol0 + n);
        }
        __syncthreads();
        #pragma unroll
        for (int kk = 0; kk < 16; ++kk) {
            float a[4], bv[4];
            *(float4*)a  = *(float4*)&As[kk][rb];
            *(float4*)bv = *(float4*)&Bs[kk][cb];
            #pragma unroll
            for (int i = 0; i < 4; ++i)
                #pragma unroll
                for (int j = 0; j < 4; ++j) acc[i][j] += a[i] * bv[j];
        }
        __syncthreads();
    }
    #pragma unroll
    for (int i = 0; i < 4; ++i)
        #pragma unroll
        for (int j = 0; j < 4; ++j)
            g_gp[((size_t)kc * NB + rb + i) * 512 + nb * 64 + cb + j] = acc[i][j];
}

__global__ void k_init2(const float* __restrict__ b_hid, const float* __restrict__ b_cell) {
    int b = blockIdx.x, j = threadIdx.x;
    float h = b_hid[j], c = b_cell[j];
    #pragma unroll
    for (int kc = 0; kc < 8; ++kc) {
        const float* p = g_gp + ((size_t)kc * NB + b) * 512;
        h += p[j];
        c += p[256 + j];
    }
    g_h[b * DD + j] = h;
    g_c[b * DD + j] = c;
}

// ===========================================================================
// Persistent step-loop kernel
// ===========================================================================
struct SMu {
    union {
        struct { __half As[64][72]; __half Bs[64][72]; } m;   // TC tiles
        struct { float sh[256]; float she[256]; float swe[256]; } a;
        struct { float sw[256]; float red[8]; } c;
    } u;
};

__device__ __forceinline__ void gridbar() {
    __syncthreads();
    __threadfence();
    if (threadIdx.x == 0) {
        int gen = g_bar_gen;
        if (atomicAdd(&g_bar_count, 1) == NBLK - 1) {
            g_bar_count = 0;
            __threadfence();
            g_bar_gen = gen + 1;
        } else {
            while (g_bar_gen == gen) __nanosleep(64);
        }
    }
    __syncthreads();
    __threadfence();
}

// ---------------------------------------------------------------------------
// Shared tensor-core 64x64 tile GEMM (unchanged from R14)
// ---------------------------------------------------------------------------
__device__ __forceinline__ void mma64(const float* __restrict__ Ag, int lda,
        const __half* __restrict__ Bg, int ldb, int K, int nvalid,
        SMu& sm, float acc[4][4]) {
    int tid = threadIdx.x, lane = tid & 31, warp = tid >> 5;
    int wm = warp & 3, wn = warp >> 2;

    for (int k0 = 0; k0 < K; k0 += 64) {
        {
            int r = tid >> 2, c0 = (tid & 3) * 16;
            const float* src = Ag + (size_t)r * lda + k0 + c0;
            float4 v0 = *(const float4*)(src);
            float4 v1 = *(const float4*)(src + 4);
            float4 v2 = *(const float4*)(src + 8);
            float4 v3 = *(const float4*)(src + 12);
            __half* d = &sm.u.m.As[r][c0];
            *(__half2*)(d + 0)  = __floats2half2_rn(v0.x, v0.y);
            *(__half2*)(d + 2)  = __floats2half2_rn(v0.z, v0.w);
            *(__half2*)(d + 4)  = __floats2half2_rn(v1.x, v1.y);
            *(__half2*)(d + 6)  = __floats2half2_rn(v1.z, v1.w);
            *(__half2*)(d + 8)  = __floats2half2_rn(v2.x, v2.y);
            *(__half2*)(d + 10) = __floats2half2_rn(v2.z, v2.w);
            *(__half2*)(d + 12) = __floats2half2_rn(v3.x, v3.y);
            *(__half2*)(d + 14) = __floats2half2_rn(v3.z, v3.w);
        }
        #pragma unroll
        for (int i = 0; i < 2; ++i) {
            int idx = tid + i * 256;
            int r = idx >> 3, c = (idx & 7) * 8;
            uint4 val;
            if (c + 8 <= nvalid) {
                val = *(const uint4*)(Bg + (size_t)(k0 + r) * ldb + c);
            } else {
                __half tmp[8];
                #pragma unroll
                for (int j = 0; j < 8; ++j)
                    tmp[j] = (c + j < nvalid) ? Bg[(size_t)(k0 + r) * ldb + c + j]
                                              : __float2half(0.f);
                val = *(uint4*)tmp;
            }
            *(uint4*)&sm.u.m.Bs[r][c] = val;
        }
        __syncthreads();

        #pragma unroll
        for (int kk = 0; kk < 64; kk += 16) {
            unsigned a[4], b[4][2];
            {
                unsigned addr = (unsigned)__cvta_generic_to_shared(
                    &sm.u.m.As[wm * 16 + (lane & 15)][kk + (lane >> 4) * 8]);
                asm volatile("ldmatrix.sync.aligned.m8n8.x4.shared.b16 {%0,%1,%2,%3}, [%4];"
                    : "=r"(a[0]), "=r"(a[1]), "=r"(a[2]), "=r"(a[3]) : "r"(addr));
            }
            #pragma unroll
            for (int ni = 0; ni < 4; ++ni) {
                unsigned addr = (unsigned)__cvta_generic_to_shared(
                    &sm.u.m.Bs[kk + (lane & 15)][wn * 32 + ni * 8]);
                asm volatile("ldmatrix.sync.aligned.m8n8.x2.trans.shared.b16 {%0,%1}, [%2];"
                    : "=r"(b[ni][0]), "=r"(b[ni][1]) : "r"(addr));
            }
            #pragma unroll
            for (int ni = 0; ni < 4; ++ni)
                asm volatile(
                    "mma.sync.aligned.m16n8k16.row.col.f32.f16.f16.f32 "
                    "{%0,%1,%2,%3}, {%4,%5,%6,%7}, {%8,%9}, {%0,%1,%2,%3};"
                    : "+f"(acc[ni][0]), "+f"(acc[ni][1]),
                      "+f"(acc[ni][2]), "+f"(acc[ni][3])
                    : "r"(a[0]), "r"(a[1]), "r"(a[2]), "r"(a[3]),
                      "r"(b[ni][0]), "r"(b[ni][1]));
        }
        __syncthreads();
    }
}

// score unit: he GEMV (fp16 Wh, 4-way ILP) + fe scan
__device__ __forceinline__ void dev_score(int b, int half, SMu& sm,
        const float* __restrict__ bh,
        const float* __restrict__ We, const float* __restrict__ be) {
    int tid = threadIdx.x, lane = tid & 31, wid = tid >> 5;
    sm.u.a.sh[tid]  = g_h[b * DD + tid];
    sm.u.a.swe[tid] = We[tid];
    __syncthreads();
    // he[tid] = bh[tid] + sum_k h[k] * Wh16[k][tid]  (4 independent chains)
    float a0 = 0.f, a1 = 0.f, a2 = 0.f, a3 = 0.f;
    const __half* whc = g_Wh16 + tid;
    #pragma unroll 4
    for (int k = 0; k < DD; k += 4) {
        a0 += sm.u.a.sh[k + 0] * __half2float(whc[(k + 0) * HH]);
        a1 += sm.u.a.sh[k + 1] * __half2float(whc[(k + 1) * HH]);
        a2 += sm.u.a.sh[k + 2] * __half2float(whc[(k + 2) * HH]);
        a3 += sm.u.a.sh[k + 3] * __half2float(whc[(k + 3) * HH]);
    }
    sm.u.a.she[tid] = bh[tid] + ((a0 + a1) + (a2 + a3));
    __syncthreads();
    float be0 = be[0];
    int p0 = half * 98, p1 = p0 + 98;
    const __half* febase = g_fe16 + (size_t)b * PP * HH;
    for (int p = p0 + wid; p < p1; p += 8) {
        const __half* fr = febase + (size_t)p * HH;
        float s = 0.f;
        #pragma unroll
        for (int it = 0; it < 4; ++it) {
            int j = it * 64 + lane * 2;
            float2 fv = __half22float2(*(const __half2*)(fr + j));
            float v0 = fv.x + sm.u.a.she[j], v1 = fv.y + sm.u.a.she[j + 1];
            s += fmaxf(v0, 0.f) * sm.u.a.swe[j] + fmaxf(v1, 0.f) * sm.u.a.swe[j + 1];
        }
        #pragma unroll
        for (int o = 16; o; o >>= 1) s += __shfl_xor_sync(0xffffffffu, s, o);
        if (lane == 0) g_score[b * PP + p] = s + be0;
    }
}

// gpre unit: h @ W_gate16 chunk -> g_gatep partials  (TC)
__device__ __forceinline__ void dev_gpre(int bid, SMu& sm) {
    int nb = bid & 31, kc = bid >> 5;
    int kbase = kc * 128;
    float acc[4][4] = {};
    mma64(g_h + kbase, DD, g_Wg16 + (size_t)kbase * EE + nb * 64, EE, 128, 64, sm, acc);

    int lane = threadIdx.x & 31, warp = threadIdx.x >> 5;
    int wm = warp & 3, wn = warp >> 2;
    int gr = lane >> 2, gc = (lane & 3) * 2;
    #pragma unroll
    for (int ni = 0; ni < 4; ++ni) {
        int col = nb * 64 + wn * 32 + ni * 8 + gc;
        int r0 = wm * 16 + gr;
        g_gatep[((size_t)kc * NB + r0) * EE + col]         = acc[ni][0];
        g_gatep[((size_t)kc * NB + r0) * EE + col + 1]     = acc[ni][1];
        g_gatep[((size_t)kc * NB + r0 + 8) * EE + col]     = acc[ni][2];
        g_gatep[((size_t)kc * NB + r0 + 8) * EE + col + 1] = acc[ni][3];
    }
}

// head unit: h @ W_head16 tile -> out (masked, bias)  (TC)
__device__ __forceinline__ void dev_head(int nb, int tprev, SMu& sm,
        const float* __restrict__ b_head, float* __restrict__ out) {
    int n0 = nb * 64;
    int nvalid = (VV - n0 < 64) ? (VV - n0) : 64;
    float acc[4][4] = {};
    mma64(g_h, DD, g_Whead16 + n0, VV, DD, nvalid, sm, acc);

    int lane = threadIdx.x & 31, warp = threadIdx.x >> 5;
    int wm = warp & 3, wn = warp >> 2;
    int gr = lane >> 2, gc = (lane & 3) * 2;
    #pragma unroll
    for (int ni = 0; ni < 4; ++ni) {
        int gn = n0 + wn * 32 + ni * 8 + gc;
        #pragma unroll
        for (int half = 0; half < 2; ++half) {
            int b = wm * 16 + gr + half * 8;
            bool msk = (g_target[b] > tprev);
            size_t rowbase = ((size_t)b * TT + tprev) * VV;
            if (gn < VV)
                out[rowbase + gn] = msk ? (acc[ni][2 * half] + b_head[gn]) : 0.f;
            if (gn + 1 < VV)
                out[rowbase + gn + 1] = msk ? (acc[ni][2 * half + 1] + b_head[gn + 1]) : 0.f;
        }
    }
}

__device__ __forceinline__ void dev_ctx(int b, int half, int t, int nact, SMu& sm,
        const float* __restrict__ b_gate, const float* __restrict__ emb,
        const int* __restrict__ tok, float* __restrict__ out_att) {
    int tid = threadIdx.x, lane = tid & 31, wid = tid >> 5;

    if (b >= nact) {
        if (half == 0 && tid < PP)
            out_att[((size_t)b * TT + t) * PP + tid] = 0.f;
        return;
    }

    float v = (tid < PP) ? g_score[b * PP + tid] : -3.4e38f;
    float m = v;
    #pragma unroll
    for (int o = 16; o; o >>= 1) m = fmaxf(m, __shfl_xor_sync(0xffffffffu, m, o));
    if (lane == 0) sm.u.c.red[wid] = m;
    __syncthreads();
    if (tid == 0) {
        float mm = sm.u.c.red[0];
        #pragma unroll
        for (int i = 1; i < 8; ++i) mm = fmaxf(mm, sm.u.c.red[i]);
        sm.u.c.red[0] = mm;
    }
    __syncthreads();
    float mx = sm.u.c.red[0];
    __syncthreads();

    float e = (tid < PP) ? expf(v - mx) : 0.f;
    float s = e;
    #pragma unroll
    for (int o = 16; o; o >>= 1) s += __shfl_xor_sync(0xffffffffu, s, o);
    if (lane == 0) sm.u.c.red[wid] = s;
    __syncthreads();
    if (tid == 0) {
        float ss = 0.f;
        #pragma unroll
        for (int i = 0; i < 8; ++i) ss += sm.u.c.red[i];
        sm.u.c.red[0] = ss;
    }
    __syncthreads();
    float inv = 1.0f / sm.u.c.red[0];
    if (tid < PP) sm.u.c.sw[tid] = e * inv;
    __syncthreads();

    if (half == 0) {
        if (tid < PP)
            out_att[((size_t)b * TT + t) * PP + tid] = sm.u.c.sw[tid];
        int token = tok[g_order[b] * LL + t];
        g_x[b * XK + tid] = emb[(size_t)token * EMB + tid];
        g_x[b * XK + EMB + EE + tid] = g_h[b * DD + tid];
    }

    int e0i = half * 1024 + tid * 4;
    const __half* fb = g_feat16 + (size_t)b * PP * EE + e0i;

    float4 s0 = make_float4(0.f, 0.f, 0.f, 0.f);
    float4 s1 = make_float4(0.f, 0.f, 0.f, 0.f);
    float4 s2 = make_float4(0.f, 0.f, 0.f, 0.f);
    float4 s3 = make_float4(0.f, 0.f, 0.f, 0.f);
    for (int p = 0; p < PP; p += 4) {
        float w0 = sm.u.c.sw[p], w1 = sm.u.c.sw[p + 1];
        float w2 = sm.u.c.sw[p + 2], w3 = sm.u.c.sw[p + 3];
        uint2 r0 = *(const uint2*)(fb + (size_t)(p + 0) * EE);
        uint2 r1 = *(const uint2*)(fb + (size_t)(p + 1) * EE);
        uint2 r2 = *(const uint2*)(fb + (size_t)(p + 2) * EE);
        uint2 r3 = *(const uint2*)(fb + (size_t)(p + 3) * EE);
        float2 a0 = __half22float2(*reinterpret_cast<__half2*>(&r0.x));
        float2 c0 = __half22float2(*reinterpret_cast<__half2*>(&r0.y));
        float2 a1 = __half22float2(*reinterpret_cast<__half2*>(&r1.x));
        float2 c1 = __half22float2(*reinterpret_cast<__half2*>(&r1.y));
        float2 a2 = __half22float2(*reinterpret_cast<__half2*>(&r2.x));
        float2 c2 = __half22float2(*reinterpret_cast<__half2*>(&r2.y));
        float2 a3 = __half22float2(*reinterpret_cast<__half2*>(&r3.x));
        float2 c3 = __half22float2(*reinterpret_cast<__half2*>(&r3.y));
        s0.x += w0 * a0.x; s0.y += w0 * a0.y; s0.z += w0 * c0.x; s0.w += w0 * c0.y;
        s1.x += w1 * a1.x; s1.y += w1 * a1.y; s1.z += w1 * c1.x; s1.w += w1 * c1.y;
        s2.x += w2 * a2.x; s2.y += w2 * a2.y; s2.z += w2 * c2.x; s2.w += w2 * c2.y;
        s3.x += w3 * a3.x; s3.y += w3 * a3.y; s3.z += w3 * c3.x; s3.w += w3 * c3.y;
    }
    float4 sum;
    sum.x = (s0.x + s1.x) + (s2.x + s3.x);
    sum.y = (s0.y + s1.y) + (s2.y + s3.y);
    sum.z = (s0.z + s1.z) + (s2.z + s3.z);
    sum.w = (s0.w + s1.w) + (s2.w + s3.w);

    float4 gp0 = *(const float4*)(g_gatep + (size_t)b * EE + e0i);
    float4 gp1 = *(const float4*)(g_gatep + ((size_t)NB + b) * EE + e0i);
    float4 bg  = *(const float4*)(b_gate + e0i);
    float4 ctx;
    ctx.x = sum.x * sigf(bg.x + gp0.x + gp1.x);
    ctx.y = sum.y * sigf(bg.y + gp0.y + gp1.y);
    ctx.z = sum.z * sigf(bg.z + gp0.z + gp1.z);
    ctx.w = sum.w * sigf(bg.w + gp0.w + gp1.w);
    *(float4*)(g_x + (size_t)b * XK + EMB + e0i) = ctx;
}

// gates unit: x @ [W_ih;W_hh]16 chunk -> g_gp partials  (TC)
__device__ __forceinline__ void dev_gates(int nb, int kc, SMu& sm) {
    int k0g = kc * 256;
    float acc[4][4] = {};
    mma64(g_x + k0g, XK, g_Wih16 + (size_t)k0g * G4 + nb * 64, G4, 256, 64, sm, acc);

    int lane = threadIdx.x & 31, warp = threadIdx.x >> 5;
    int wm = warp & 3, wn = warp >> 2;
    int gr = lane >> 2, gc = (lane & 3) * 2;
    #pragma unroll
    for (int ni = 0; ni < 4; ++ni) {
        int col = nb * 64 + wn * 32 + ni * 8 + gc;
        int r0 = wm * 16 + gr;
        g_gp[((size_t)kc * NB + r0) * G4 + col]         = acc[ni][0];
        g_gp[((size_t)kc * NB + r0) * G4 + col + 1]     = acc[ni][1];
        g_gp[((size_t)kc * NB + r0 + 8) * G4 + col]     = acc[ni][2];
        g_gp[((size_t)kc * NB + r0 + 8) * G4 + col + 1] = acc[ni][3];
    }
}

__device__ __forceinline__ void dev_lstm(int b, int t,
        const float* __restrict__ b_ih, const float* __restrict__ b_hh) {
    int j = threadIdx.x;
    float gi = b_ih[j] + b_hh[j];
    float gf = b_ih[DD + j] + b_hh[DD + j];
    float gg = b_ih[2 * DD + j] + b_hh[2 * DD + j];
    float go = b_ih[3 * DD + j] + b_hh[3 * DD + j];
    #pragma unroll
    for (int kc = 0; kc < KC; ++kc) {
        const float* p = g_gp + ((size_t)kc * NB + b) * G4;
        gi += p[j];
        gf += p[DD + j];
        gg += p[2 * DD + j];
        go += p[3 * DD + j];
    }
    float c = g_c[b * DD + j];
    float cn = sigf(gf) * c + sigf(gi) * tanhf(gg);
    float hn = sigf(go) * tanhf(cn);
    if (g_target[b] > t) {
        g_h[b * DD + j] = hn;
        g_c[b * DD + j] = cn;
    }
}

__global__ void __launch_bounds__(256, 2) k_loop(
        const float* __restrict__ bh,
        const float* __restrict__ We, const float* __restrict__ be,
        const float* __restrict__ b_gate, const float* __restrict__ emb,
        const int* __restrict__ tok,
        const float* __restrict__ b_ih, const float* __restrict__ b_hh,
        const float* __restrict__ b_head,
        float* __restrict__ out, float* __restrict__ out_att) {
    __shared__ SMu sm;
    for (int t = 0; t < TT; ++t) {
        int nact = g_nact[t];
        // Phase A: scores(t) 128 + gpre(t) 64 + head(t-1) nb[0,64) = 256 units
        int nA = 192 + (t >= 1 ? 64 : 0);
        for (int u = blockIdx.x; u < nA; u += NBLK) {
            __syncthreads();
            if (u < 128) {
                if ((u >> 1) < nact) dev_score(u >> 1, u & 1, sm, bh, We, be);
            }
            else if (u < 192) dev_gpre(u - 128, sm);
            else              dev_head(u - 192, t - 1, sm, b_head, out);
        }
        gridbar();
        // Phase B: ctx 128 + head(t-1) nb[64,157) = 221 units
        int nB = 128 + (t >= 1 ? 93 : 0);
        for (int u = blockIdx.x; u < nB; u += NBLK) {
            __syncthreads();
            if (u < 128) dev_ctx(u >> 1, u & 1, t, nact, sm, b_gate, emb, tok, out_att);
            else         dev_head(64 + (u - 128), t - 1, sm, b_head, out);
        }
        gridbar();
        // Phase C: gates split-K GEMM (160 units)
        for (int u = blockIdx.x; u < 160; u += NBLK) {
            __syncthreads();
            dev_gates(u & 15, u >> 4, sm);
        }
        gridbar();
        // Phase D: LSTM pointwise (64 units)
        if (blockIdx.x < NB) dev_lstm(blockIdx.x, t, b_ih, b_hh);
        gridbar();
    }
    // Tail: head for the final step (t = TT-1)
    for (int u = blockIdx.x; u < 157; u += NBLK) {
        __syncthreads();
        dev_head(u, TT - 1, sm, b_head, out);
    }
}

// ---------------------------------------------------------------------------
extern "C" void kernel_launch(void* const* d_in, const int* in_sizes, int n_in,
                              void* d_out, int out_size) {
    const float* feat   = (const float*)d_in[0];
    const int*   tok    = (const int*)d_in[1];
    const int*   caplen = (const int*)d_in[2];
    const float* Wf     = (const float*)d_in[3];
    const float* bf     = (const float*)d_in[4];
    const float* Wh     = (const float*)d_in[5];
    const float* bh     = (const float*)d_in[6];
    const float* We     = (const float*)d_in[7];
    const float* be     = (const float*)d_in[8];
    const float* emb    = (const float*)d_in[9];
    const float* W_ih   = (const float*)d_in[10];
    const float* b_ih   = (const float*)d_in[11];
    const float* W_hh   = (const float*)d_in[12];
    const float* b_hh   = (const float*)d_in[13];
    const float* W_hid  = (const float*)d_in[14];
    const float* b_hid  = (const float*)d_in[15];
    const float* W_cell = (const float*)d_in[16];
    const float* b_cell = (const float*)d_in[17];
    const float* W_gate = (const float*)d_in[18];
    const float* b_gate = (const float*)d_in[19];
    const float* W_head = (const float*)d_in[20];
    const float* b_head = (const float*)d_in[21];

    float* out = (float*)d_out;
    float* out_att = out + (size_t)NB * TT * VV;

    k_order<<<1, 32>>>(caplen);
    k_cvt<<<512, 256>>>(W_gate, W_ih, W_hh, W_head, Wf, Wh);
    k_cvtf<<<NB * PP, 256>>>(feat);
    k_fe<<<dim3(98, 5), 256>>>(feat, bf);         // fe HGEMM (tensor cores) + mean
    k_initA<<<dim3(8, 8), 256>>>(W_hid, W_cell);  // init GEMM, split-K
    k_init2<<<NB, 256>>>(b_hid, b_cell);

    // entire 31-step decoder loop in ONE persistent kernel
    k_loop<<<NBLK, 256>>>(bh, We, be, b_gate, emb, tok,
                          b_ih, b_hh, b_head, out, out_att);
}